// round 5
// baseline (speedup 1.0000x reference)
#include <cuda_runtime.h>

// ---------------------------------------------------------------------------
// MoE transformer block, fp32 baseline.
// B=4 S=2048 D=1024 H=16 KV=4 HD=64 E=8 K(top)=2 F=1024
// Output layout assumed: [out (B,S,D)][k_roped (B,S,KV,HD)][v (B,S,KV,HD)]
// ---------------------------------------------------------------------------

namespace {
constexpr int Bb  = 4;
constexpr int Ss  = 2048;
constexpr int Dd  = 1024;
constexpr int Hh  = 16;
constexpr int KVh = 4;
constexpr int HDd = 64;
constexpr int Ee  = 8;
constexpr int TKk = 2;
constexpr int Ff  = 1024;
constexpr int NT  = Bb * Ss;        // 8192 tokens
constexpr int QD  = Hh * HDd;       // 1024
constexpr int KD  = KVh * HDd;      // 256
}

// Scratch (static device globals; no allocation at runtime)
__device__ float g_x[(size_t)NT * Dd];
__device__ float g_q[(size_t)NT * QD];
__device__ float g_k[(size_t)NT * KD];
__device__ float g_vscr[(size_t)NT * KD];
__device__ float g_kscr[(size_t)NT * KD];
__device__ float g_attn[(size_t)NT * QD];
__device__ float g_h[(size_t)NT * Dd];
__device__ float g_y[(size_t)NT * Dd];
__device__ float g_ga[(size_t)Ee * NT * Ff];   // gate act -> he (in place)
__device__ float g_ua[(size_t)Ee * NT * Ff];   // up act
__device__ float g_dn[(size_t)Ee * NT * Dd];   // down-proj per slot
__device__ int   g_cnt[Ee];
__device__ int   g_list[Ee * NT];
__device__ int   g_slot[NT * TKk];
__device__ float g_gw[NT * TKk];

// ---------------------------------------------------------------------------
// RMSNorm: one block per token
// ---------------------------------------------------------------------------
__global__ void rmsnorm_kernel(const float* __restrict__ in,
                               const float* __restrict__ w,
                               float* __restrict__ out) {
    int t = blockIdx.x;
    const float* row = in + (size_t)t * Dd;
    float ss = 0.f;
#pragma unroll
    for (int i = 0; i < 4; i++) {
        float v = row[threadIdx.x + i * 256];
        ss += v * v;
    }
#pragma unroll
    for (int o = 16; o > 0; o >>= 1) ss += __shfl_xor_sync(0xffffffffu, ss, o);
    __shared__ float sred[8];
    if ((threadIdx.x & 31) == 0) sred[threadIdx.x >> 5] = ss;
    __syncthreads();
    if (threadIdx.x < 32) {
        float v = (threadIdx.x < 8) ? sred[threadIdx.x] : 0.f;
#pragma unroll
        for (int o = 4; o > 0; o >>= 1) v += __shfl_xor_sync(0xffffffffu, v, o);
        if (threadIdx.x == 0) sred[0] = v;
    }
    __syncthreads();
    float inv = rsqrtf(sred[0] * (1.f / Dd) + 1e-6f);
    float* orow = out + (size_t)t * Dd;
#pragma unroll
    for (int i = 0; i < 4; i++) {
        int d = threadIdx.x + i * 256;
        orow[d] = row[d] * inv * w[d];
    }
}

// ---------------------------------------------------------------------------
// Generic tiled GEMM: C[M,N] = A[M,K] @ B[K,N] (+ addsrc)
// mode 0: plain (M fixed, multiple of 64)
// mode 1: MoE gather rows of A via g_list[z], M_eff = g_cnt[z]
// mode 2: MoE contiguous A with M_eff = g_cnt[z]
// Tile 64x64x16, 256 threads, 4x4 microtile.
// ---------------------------------------------------------------------------
__global__ void __launch_bounds__(256)
gemm_kernel(const float* __restrict__ Abase, size_t astride_z,
            const float* __restrict__ Wbase, size_t wstride_z,
            float* __restrict__ Cbase, size_t cstride_z,
            const float* __restrict__ addsrc,
            int mode, int M, int N, int K) {
    int z = blockIdx.z;
    const float* A = Abase + astride_z * z;
    const float* Bw = Wbase + wstride_z * z;
    float* C = Cbase + cstride_z * z;

    int Meff = M;
    const int* rowlist = nullptr;
    if (mode == 1) { Meff = g_cnt[z]; rowlist = &g_list[z * NT]; }
    else if (mode == 2) { Meff = g_cnt[z]; }

    int m0 = blockIdx.y * 64, n0 = blockIdx.x * 64;
    if (m0 >= Meff) return;

    __shared__ float As[16][68];
    __shared__ float Bs[16][64];

    int tid = threadIdx.x;
    int ty = tid >> 4, tx = tid & 15;
    int arow = tid >> 2, ac4 = (tid & 3) << 2;

    int agrow = m0 + arow;
    size_t aoff;
    if (rowlist) {
        int rr = (agrow < Meff) ? rowlist[agrow] : rowlist[0];
        aoff = (size_t)rr * K;
    } else {
        int rr = (agrow < Meff) ? agrow : (Meff - 1);
        aoff = (size_t)rr * K;
    }
    aoff += ac4;
    size_t boff = (size_t)ty * N + n0 + (tx << 2);

    float acc[4][4] = {};
    for (int kk = 0; kk < K; kk += 16) {
        float4 av = *(const float4*)(A + aoff + kk);
        As[ac4 + 0][arow] = av.x;
        As[ac4 + 1][arow] = av.y;
        As[ac4 + 2][arow] = av.z;
        As[ac4 + 3][arow] = av.w;
        *(float4*)&Bs[ty][tx << 2] = *(const float4*)(Bw + boff + (size_t)kk * N);
        __syncthreads();
#pragma unroll
        for (int k = 0; k < 16; k++) {
            float4 a = *(const float4*)&As[k][ty << 2];
            float4 b = *(const float4*)&Bs[k][tx << 2];
            float ar[4] = {a.x, a.y, a.z, a.w};
            float br[4] = {b.x, b.y, b.z, b.w};
#pragma unroll
            for (int i = 0; i < 4; i++)
#pragma unroll
                for (int j = 0; j < 4; j++)
                    acc[i][j] += ar[i] * br[j];
        }
        __syncthreads();
    }

#pragma unroll
    for (int i = 0; i < 4; i++) {
        int r = m0 + (ty << 2) + i;
        if (mode != 0 && r >= Meff) continue;
        size_t co = (size_t)r * N + n0 + (tx << 2);
#pragma unroll
        for (int j = 0; j < 4; j++) {
            float v = acc[i][j];
            if (addsrc) v += addsrc[co + j];
            C[co + j] = v;
        }
    }
}

// ---------------------------------------------------------------------------
// RoPE in place on q (16 heads) and k (4 heads); also writes rotated k to outk.
// cos/sin: [S][64], concatenated halves.
// ---------------------------------------------------------------------------
__global__ void rope_kernel(const float* __restrict__ cosb,
                            const float* __restrict__ sinb,
                            float* __restrict__ q,
                            float* __restrict__ k,
                            float* __restrict__ outk) {
    int t = blockIdx.x;
    int s = t % Ss;
    const float* cs = cosb + (size_t)s * HDd;
    const float* sn = sinb + (size_t)s * HDd;

    float* qrow = q + (size_t)t * QD;
    for (int idx = threadIdx.x; idx < Hh * 32; idx += blockDim.x) {
        int hh = idx >> 5, d = idx & 31;
        float* p = qrow + hh * HDd;
        float a = p[d], b2 = p[d + 32];
        p[d]      = a * cs[d]       - b2 * sn[d];
        p[d + 32] = b2 * cs[d + 32] + a * sn[d + 32];
    }
    float* krow = k + (size_t)t * KD;
    float* okr = outk + (size_t)t * KD;
    for (int idx = threadIdx.x; idx < KVh * 32; idx += blockDim.x) {
        int hh = idx >> 5, d = idx & 31;
        float* p = krow + hh * HDd;
        float a = p[d], b2 = p[d + 32];
        float o1 = a * cs[d]       - b2 * sn[d];
        float o2 = b2 * cs[d + 32] + a * sn[d + 32];
        p[d] = o1; p[d + 32] = o2;
        okr[hh * HDd + d] = o1;
        okr[hh * HDd + d + 32] = o2;
    }
}

// ---------------------------------------------------------------------------
// Causal GQA attention, flash style. One thread = one query row.
// Block: 128 threads = 128 query rows for one (b, h). 64-key tiles in smem.
// ---------------------------------------------------------------------------
__global__ void __launch_bounds__(128)
attn_kernel(const float* __restrict__ q,
            const float* __restrict__ k,
            const float* __restrict__ v,
            float* __restrict__ out) {
    int b = blockIdx.z, h = blockIdx.y, qt = blockIdx.x;
    int kvh = h >> 2;
    int qi = qt * 128 + threadIdx.x;

    size_t qoff = ((size_t)(b * Ss + qi)) * QD + h * HDd;
    float qreg[64];
#pragma unroll
    for (int d = 0; d < 64; d++) qreg[d] = q[qoff + d] * 0.125f;  // 1/sqrt(64)
    float acc[64];
#pragma unroll
    for (int d = 0; d < 64; d++) acc[d] = 0.f;
    float m = -1e30f, l = 0.f;

    __shared__ float Ks[64][68];
    __shared__ float Vs[64][68];

    int ntiles = (qt + 1) * 2;
    int lr = threadIdx.x >> 1, lc = (threadIdx.x & 1) * 32;
    for (int ktile = 0; ktile < ntiles; ktile++) {
        int k0 = ktile * 64;
        __syncthreads();
        size_t ksrc = ((size_t)(b * Ss + k0 + lr)) * KD + kvh * HDd + lc;
#pragma unroll
        for (int i = 0; i < 8; i++) {
            *(float4*)&Ks[lr][lc + i * 4] = *(const float4*)&k[ksrc + i * 4];
            *(float4*)&Vs[lr][lc + i * 4] = *(const float4*)&v[ksrc + i * 4];
        }
        __syncthreads();
        int jmax = qi - k0;
        int jend = (jmax >= 63) ? 64 : (jmax + 1);
        for (int j = 0; j < jend; j++) {
            float s0 = 0.f, s1 = 0.f, s2 = 0.f, s3 = 0.f;
#pragma unroll
            for (int d4 = 0; d4 < 16; d4++) {
                float4 kv = *(const float4*)&Ks[j][d4 * 4];
                s0 += qreg[d4 * 4 + 0] * kv.x;
                s1 += qreg[d4 * 4 + 1] * kv.y;
                s2 += qreg[d4 * 4 + 2] * kv.z;
                s3 += qreg[d4 * 4 + 3] * kv.w;
            }
            float s = (s0 + s1) + (s2 + s3);
            if (s > m) {
                float corr = __expf(m - s);
                l *= corr;
#pragma unroll
                for (int d = 0; d < 64; d++) acc[d] *= corr;
                m = s;
            }
            float p = __expf(s - m);
            l += p;
#pragma unroll
            for (int d4 = 0; d4 < 16; d4++) {
                float4 vv = *(const float4*)&Vs[j][d4 * 4];
                acc[d4 * 4 + 0] += p * vv.x;
                acc[d4 * 4 + 1] += p * vv.y;
                acc[d4 * 4 + 2] += p * vv.z;
                acc[d4 * 4 + 3] += p * vv.w;
            }
        }
    }
    float inv = 1.f / l;
    size_t ooff = ((size_t)(b * Ss + qi)) * QD + h * HDd;
#pragma unroll
    for (int d = 0; d < 64; d++) out[ooff + d] = acc[d] * inv;
}

// ---------------------------------------------------------------------------
// Router: one warp per token. logits = y @ router_w (D x 8); top-2 + softmax.
// ---------------------------------------------------------------------------
__global__ void zero_cnt_kernel() {
    if (threadIdx.x < Ee) g_cnt[threadIdx.x] = 0;
}

__global__ void router_kernel(const float* __restrict__ y,
                              const float* __restrict__ rw) {
    int t = (blockIdx.x * blockDim.x + threadIdx.x) >> 5;
    int lane = threadIdx.x & 31;
    if (t >= NT) return;
    const float* yrow = y + (size_t)t * Dd;
    float logits[8] = {};
    for (int i = 0; i < 32; i++) {
        int d = i * 32 + lane;
        float yv = yrow[d];
#pragma unroll
        for (int e = 0; e < 8; e++) logits[e] += yv * rw[d * 8 + e];
    }
#pragma unroll
    for (int e = 0; e < 8; e++) {
#pragma unroll
        for (int o = 16; o > 0; o >>= 1)
            logits[e] += __shfl_xor_sync(0xffffffffu, logits[e], o);
    }
    if (lane == 0) {
        int i0 = 0; float v0 = logits[0];
#pragma unroll
        for (int e = 1; e < 8; e++) if (logits[e] > v0) { v0 = logits[e]; i0 = e; }
        int i1 = -1; float v1 = -1e30f;
#pragma unroll
        for (int e = 0; e < 8; e++)
            if (e != i0 && logits[e] > v1) { v1 = logits[e]; i1 = e; }
        float e1 = __expf(v1 - v0);
        float w0 = 1.f / (1.f + e1);
        float w1 = e1 / (1.f + e1);
        int p0 = atomicAdd(&g_cnt[i0], 1);
        g_list[i0 * NT + p0] = t;
        g_slot[t * 2 + 0] = i0 * NT + p0;
        g_gw[t * 2 + 0] = w0;
        int p1 = atomicAdd(&g_cnt[i1], 1);
        g_list[i1 * NT + p1] = t;
        g_slot[t * 2 + 1] = i1 * NT + p1;
        g_gw[t * 2 + 1] = w1;
    }
}

// ---------------------------------------------------------------------------
// he = silu(gate) * up, in place into g_ga. One block per assignment slot-row.
// ---------------------------------------------------------------------------
__global__ void silu_kernel() {
    int a = blockIdx.x;                  // assignment 0 .. NT*TK-1
    int slot = g_slot[a];
    size_t off = (size_t)slot * Ff + blockIdx.y * 256 + threadIdx.x;
    float g = g_ga[off], u = g_ua[off];
    float sg = g / (1.f + __expf(-g));
    g_ga[off] = sg * u;
}

// ---------------------------------------------------------------------------
// out = h + w0 * down[slot0] + w1 * down[slot1]
// ---------------------------------------------------------------------------
__global__ void combine_kernel(float* __restrict__ out) {
    int t = blockIdx.x;
    int d = blockIdx.y * 256 + threadIdx.x;
    int s0 = g_slot[t * 2], s1 = g_slot[t * 2 + 1];
    float w0 = g_gw[t * 2], w1 = g_gw[t * 2 + 1];
    size_t o = (size_t)t * Dd + d;
    out[o] = g_h[o] + w0 * g_dn[(size_t)s0 * Dd + d]
                    + w1 * g_dn[(size_t)s1 * Dd + d];
}

// ---------------------------------------------------------------------------
// Launch
// ---------------------------------------------------------------------------
extern "C" void kernel_launch(void* const* d_in, const int* in_sizes, int n_in,
                              void* d_out, int out_size) {
    const float* input  = (const float*)d_in[0];
    const float* cosb   = (const float*)d_in[1];
    const float* sinb   = (const float*)d_in[2];
    // d_in[3] = mask (causal, unused)
    const float* w_attn = (const float*)d_in[4];
    const float* w_moe  = (const float*)d_in[5];
    const float* Wq     = (const float*)d_in[6];
    const float* Wk     = (const float*)d_in[7];
    const float* Wv     = (const float*)d_in[8];
    const float* Wo     = (const float*)d_in[9];
    const float* rw     = (const float*)d_in[10];
    const float* Wg     = (const float*)d_in[11];
    const float* Wu     = (const float*)d_in[12];
    const float* Wd     = (const float*)d_in[13];

    float *px, *pq, *pk, *pvs, *pks, *pattn, *ph, *py, *pga, *pua, *pdn;
    cudaGetSymbolAddress((void**)&px,   g_x);
    cudaGetSymbolAddress((void**)&pq,   g_q);
    cudaGetSymbolAddress((void**)&pk,   g_k);
    cudaGetSymbolAddress((void**)&pvs,  g_vscr);
    cudaGetSymbolAddress((void**)&pks,  g_kscr);
    cudaGetSymbolAddress((void**)&pattn, g_attn);
    cudaGetSymbolAddress((void**)&ph,   g_h);
    cudaGetSymbolAddress((void**)&py,   g_y);
    cudaGetSymbolAddress((void**)&pga,  g_ga);
    cudaGetSymbolAddress((void**)&pua,  g_ua);
    cudaGetSymbolAddress((void**)&pdn,  g_dn);

    float* out = (float*)d_out;
    size_t need = (size_t)NT * Dd + 2 * (size_t)NT * KD;
    bool full = ((size_t)out_size >= need);
    float* outk = full ? (out + (size_t)NT * Dd) : pks;
    float* outv = full ? (out + (size_t)NT * Dd + (size_t)NT * KD) : pvs;

    // 1. x = rmsnorm(input, w_attn)
    rmsnorm_kernel<<<NT, 256>>>(input, w_attn, px);
    // 2. q/k/v projections
    gemm_kernel<<<dim3(QD / 64, NT / 64, 1), 256>>>(px, 0, Wq, 0, pq, 0, nullptr, 0, NT, QD, Dd);
    gemm_kernel<<<dim3(KD / 64, NT / 64, 1), 256>>>(px, 0, Wk, 0, pk, 0, nullptr, 0, NT, KD, Dd);
    gemm_kernel<<<dim3(KD / 64, NT / 64, 1), 256>>>(px, 0, Wv, 0, outv, 0, nullptr, 0, NT, KD, Dd);
    // 3. RoPE (in place; rotated k also copied to output)
    rope_kernel<<<NT, 256>>>(cosb, sinb, pq, pk, outk);
    // 4. attention
    attn_kernel<<<dim3(Ss / 128, Hh, Bb), 128>>>(pq, pk, outv, pattn);
    // 5. h = input + attn @ Wo
    gemm_kernel<<<dim3(Dd / 64, NT / 64, 1), 256>>>(pattn, 0, Wo, 0, ph, 0, input, 0, NT, Dd, QD);
    // 6. y = rmsnorm(h, w_moe)
    rmsnorm_kernel<<<NT, 256>>>(ph, w_moe, py);
    // 7. router top-2
    zero_cnt_kernel<<<1, 32>>>();
    router_kernel<<<NT / 8, 256>>>(py, rw);
    // 8. expert gate / up GEMMs (gathered rows)
    gemm_kernel<<<dim3(Ff / 64, NT / 64, Ee), 256>>>(py, 0, Wg, (size_t)Dd * Ff,
                                                     pga, (size_t)NT * Ff, nullptr, 1, NT, Ff, Dd);
    gemm_kernel<<<dim3(Ff / 64, NT / 64, Ee), 256>>>(py, 0, Wu, (size_t)Dd * Ff,
                                                     pua, (size_t)NT * Ff, nullptr, 1, NT, Ff, Dd);
    // 9. he = silu(gate) * up
    silu_kernel<<<dim3(NT * TKk, Ff / 256), 256>>>();
    // 10. down projection
    gemm_kernel<<<dim3(Dd / 64, NT / 64, Ee), 256>>>(pga, (size_t)NT * Ff, Wd, (size_t)Ff * Dd,
                                                     pdn, (size_t)NT * Dd, nullptr, 2, NT, Dd, Ff);
    // 11. out = h + gated expert outputs
    combine_kernel<<<dim3(NT, Dd / 256), 256>>>(out);
}

// round 7
// speedup vs baseline: 1.5791x; 1.5791x over previous
#include <cuda_runtime.h>
#include <cuda_bf16.h>
#include <cstdint>

// ---------------------------------------------------------------------------
// MoE transformer block. Split-bf16 (3-term) warp-MMA GEMMs + fp32 flash attn.
// B=4 S=2048 D=1024 H=16 KV=4 HD=64 E=8 K(top)=2 F=1024
// Uses only base sm_103 PTX: mma.sync / ldmatrix / cp.async (no tcgen05).
// ---------------------------------------------------------------------------

namespace {
constexpr int Bb  = 4;
constexpr int Ss  = 2048;
constexpr int Dd  = 1024;
constexpr int Hh  = 16;
constexpr int KVh = 4;
constexpr int HDd = 64;
constexpr int Ee  = 8;
constexpr int TKk = 2;
constexpr int Ff  = 1024;
constexpr int NT  = Bb * Ss;        // 8192 tokens
constexpr int QD  = Hh * HDd;       // 1024
constexpr int KD  = KVh * HDd;      // 256
constexpr int NSLOT = NT * TKk;     // 16384 expert slots

// GEMM tiling
constexpr int ROWB  = 80;                 // smem row stride bytes (32 bf16 + pad)
constexpr int TILEB = 128 * ROWB;         // one 128x32 bf16 tile = 10240 B
constexpr int STAGE = 4 * TILEB;          // AH, AL, BH, BL
constexpr int GSMEM = 2 * STAGE;          // 81920 B double-buffered
}

__device__ __forceinline__ uint32_t smem_u32(const void* p) {
    uint32_t a;
    asm("{ .reg .u64 t; cvta.to.shared.u64 t, %1; cvt.u32.u64 %0, t; }" : "=r"(a) : "l"(p));
    return a;
}
#define CP16(dst, src) asm volatile( \
    "cp.async.cg.shared.global [%0], [%1], 16;" :: "r"(dst), "l"(src))
#define CP_COMMIT() asm volatile("cp.async.commit_group;" ::: "memory")
#define CP_WAIT(n)  asm volatile("cp.async.wait_group %0;" :: "n"(n) : "memory")

__device__ __forceinline__ void ldsm_x4(uint32_t* r, uint32_t addr) {
    asm volatile("ldmatrix.sync.aligned.m8n8.x4.shared.b16 {%0,%1,%2,%3}, [%4];"
                 : "=r"(r[0]), "=r"(r[1]), "=r"(r[2]), "=r"(r[3]) : "r"(addr));
}
__device__ __forceinline__ void mma_bf16(float* c, const uint32_t* a, const uint32_t* b) {
    asm volatile(
        "mma.sync.aligned.m16n8k16.row.col.f32.bf16.bf16.f32 "
        "{%0,%1,%2,%3}, {%4,%5,%6,%7}, {%8,%9}, {%0,%1,%2,%3};"
        : "+f"(c[0]), "+f"(c[1]), "+f"(c[2]), "+f"(c[3])
        : "r"(a[0]), "r"(a[1]), "r"(a[2]), "r"(a[3]), "r"(b[0]), "r"(b[1]));
}

// ---------------------------------------------------------------------------
// Scratch (device globals; no runtime allocation)
// ---------------------------------------------------------------------------
__device__ __align__(128) float g_q[(size_t)NT * QD];
__device__ __align__(128) float g_k[(size_t)NT * KD];
__device__ __align__(128) float g_vscr[(size_t)NT * KD];
__device__ __align__(128) float g_kscr[(size_t)NT * KD];
__device__ __align__(128) float g_h[(size_t)NT * Dd];
__device__ __align__(128) float g_y[(size_t)NT * Dd];
__device__ __align__(128) float g_ga[(size_t)NSLOT * Ff];
__device__ __align__(128) float g_ua[(size_t)NSLOT * Ff];
__device__ __align__(128) float g_dn[(size_t)NSLOT * Dd];

__device__ __align__(128) __nv_bfloat16 g_xhi[(size_t)NT * Dd], g_xlo[(size_t)NT * Dd];
__device__ __align__(128) __nv_bfloat16 g_ahi[(size_t)NT * QD], g_alo[(size_t)NT * QD];
__device__ __align__(128) __nv_bfloat16 g_yhi[(size_t)NT * Dd], g_ylo[(size_t)NT * Dd];
__device__ __align__(128) __nv_bfloat16 g_hehi[(size_t)NSLOT * Ff], g_helo[(size_t)NSLOT * Ff];

// transposed split weights [N, K]
__device__ __align__(128) __nv_bfloat16 g_wq_hi[(size_t)QD * Dd], g_wq_lo[(size_t)QD * Dd];
__device__ __align__(128) __nv_bfloat16 g_wk_hi[(size_t)KD * Dd], g_wk_lo[(size_t)KD * Dd];
__device__ __align__(128) __nv_bfloat16 g_wv_hi[(size_t)KD * Dd], g_wv_lo[(size_t)KD * Dd];
__device__ __align__(128) __nv_bfloat16 g_wo_hi[(size_t)Dd * QD], g_wo_lo[(size_t)Dd * QD];
__device__ __align__(128) __nv_bfloat16 g_wg_hi[(size_t)Ee * Ff * Dd], g_wg_lo[(size_t)Ee * Ff * Dd];
__device__ __align__(128) __nv_bfloat16 g_wu_hi[(size_t)Ee * Ff * Dd], g_wu_lo[(size_t)Ee * Ff * Dd];
__device__ __align__(128) __nv_bfloat16 g_wd_hi[(size_t)Ee * Dd * Ff], g_wd_lo[(size_t)Ee * Dd * Ff];

__device__ int   g_cnt[Ee];
__device__ int   g_off[Ee];
__device__ int   g_fill[Ee];
__device__ int   g_list[NSLOT];
__device__ int   g_slot[NSLOT];
__device__ int   g_texp[NSLOT];
__device__ float g_gw[NSLOT];

// ---------------------------------------------------------------------------
// RMSNorm with bf16 hi/lo split output (+ optional f32 output)
// ---------------------------------------------------------------------------
__global__ void rmsnorm_split_kernel(const float* __restrict__ in,
                                     const float* __restrict__ w,
                                     __nv_bfloat16* __restrict__ ohi,
                                     __nv_bfloat16* __restrict__ olo,
                                     float* __restrict__ of32) {
    int t = blockIdx.x;
    const float* row = in + (size_t)t * Dd;
    float ss = 0.f;
#pragma unroll
    for (int i = 0; i < 4; i++) { float v = row[threadIdx.x + i * 256]; ss += v * v; }
#pragma unroll
    for (int o = 16; o > 0; o >>= 1) ss += __shfl_xor_sync(0xffffffffu, ss, o);
    __shared__ float sred[8];
    if ((threadIdx.x & 31) == 0) sred[threadIdx.x >> 5] = ss;
    __syncthreads();
    if (threadIdx.x < 32) {
        float v = (threadIdx.x < 8) ? sred[threadIdx.x] : 0.f;
#pragma unroll
        for (int o = 4; o > 0; o >>= 1) v += __shfl_xor_sync(0xffffffffu, v, o);
        if (threadIdx.x == 0) sred[0] = v;
    }
    __syncthreads();
    float inv = rsqrtf(sred[0] * (1.f / Dd) + 1e-6f);
    size_t base = (size_t)t * Dd;
#pragma unroll
    for (int i = 0; i < 4; i++) {
        int d = threadIdx.x + i * 256;
        float r = row[d] * inv * w[d];
        __nv_bfloat16 hi = __float2bfloat16(r);
        float lo = r - __bfloat162float(hi);
        ohi[base + d] = hi;
        olo[base + d] = __float2bfloat16(lo);
        if (of32) of32[base + d] = r;
    }
}

// ---------------------------------------------------------------------------
// Transpose + split: W[K,N] fp32 -> Thi/Tlo[N,K] bf16. Block (32,8).
// ---------------------------------------------------------------------------
__global__ void transpose_split_kernel(const float* __restrict__ W,
                                       __nv_bfloat16* __restrict__ Thi,
                                       __nv_bfloat16* __restrict__ Tlo,
                                       int K, int N) {
    __shared__ float tile[32][33];
    size_t zb = (size_t)blockIdx.z * K * N;
    int k0 = blockIdx.y * 32, n0 = blockIdx.x * 32;
    int tx = threadIdx.x, ty = threadIdx.y;
#pragma unroll
    for (int j = 0; j < 4; j++)
        tile[ty + 8 * j][tx] = W[zb + (size_t)(k0 + ty + 8 * j) * N + n0 + tx];
    __syncthreads();
#pragma unroll
    for (int j = 0; j < 4; j++) {
        float v = tile[tx][ty + 8 * j];
        __nv_bfloat16 hi = __float2bfloat16(v);
        float lo = v - __bfloat162float(hi);
        size_t o = zb + (size_t)(n0 + ty + 8 * j) * K + k0 + tx;
        Thi[o] = hi;
        Tlo[o] = __float2bfloat16(lo);
    }
}

// ---------------------------------------------------------------------------
// Warp-MMA GEMM: C[M,N] = Ahi@Bhi + Alo@Bhi + Ahi@Blo (fp32 accum)
// A: [M,K] bf16 K-major (hi/lo). B: [N,K] bf16 K-major (hi/lo). K % 32 == 0.
// CTA tile 128x128, BK=32, double-buffered cp.async smem, 256 threads.
// 8 warps: warp_m = wid&1 (64 rows), warp_n = wid>>1 (32 cols).
// mode 0: plain. mode 1: A rows via g_list[g_off[z]+r], C rows g_off[z]+r,
//         Meff=g_cnt[z]. mode 2: A/C rows at g_off[z]+r.
// ---------------------------------------------------------------------------
__global__ void __launch_bounds__(256, 1)
mma_gemm(const __nv_bfloat16* __restrict__ Ahi, const __nv_bfloat16* __restrict__ Alo,
         const __nv_bfloat16* __restrict__ Bhi, const __nv_bfloat16* __restrict__ Blo,
         size_t bz,
         float* __restrict__ C,
         const float* __restrict__ addsrc,
         int mode, int M, int N, int K) {
    extern __shared__ char smem[];
    int z = blockIdx.z;
    int Meff = M, off = 0;
    if (mode) { Meff = g_cnt[z]; off = g_off[z]; }
    int m0 = blockIdx.y * 128;
    if (m0 >= Meff) return;
    int n0 = blockIdx.x * 128;
    const __nv_bfloat16* bhi = Bhi + bz * z;
    const __nv_bfloat16* blo = Blo + bz * z;

    int tid = threadIdx.x, lane = tid & 31, wid = tid >> 5;
    uint32_t sb = smem_u32(smem);

    // ---- global->smem load mapping: thread loads one row (32B half) per tile
    int lrow = tid >> 1;
    int lcolh = (tid & 1) * 16;           // offset in halves
    int ar = m0 + lrow;
    long grow;
    if (mode == 1) { int rr = (ar < Meff) ? ar : (Meff - 1); grow = g_list[off + rr]; }
    else if (mode == 2) { int rr = (ar < Meff) ? ar : (Meff - 1); grow = off + rr; }
    else grow = ar;
    const __nv_bfloat16* pAH = Ahi + (size_t)grow * K + lcolh;
    const __nv_bfloat16* pAL = Alo + (size_t)grow * K + lcolh;
    const __nv_bfloat16* pBH = bhi + (size_t)(n0 + lrow) * K + lcolh;
    const __nv_bfloat16* pBL = blo + (size_t)(n0 + lrow) * K + lcolh;
    uint32_t dstrel = (uint32_t)(lrow * ROWB + lcolh * 2);

    float acc[4][4][4];
#pragma unroll
    for (int i = 0; i < 4; i++)
#pragma unroll
        for (int j = 0; j < 4; j++)
#pragma unroll
            for (int q = 0; q < 4; q++) acc[i][j][q] = 0.f;

    const int NS = K / 32;
    // prologue: stage 0
    {
        uint32_t d = sb + dstrel;
        CP16(d + 0 * TILEB,      pAH); CP16(d + 0 * TILEB + 16, pAH + 8);
        CP16(d + 1 * TILEB,      pAL); CP16(d + 1 * TILEB + 16, pAL + 8);
        CP16(d + 2 * TILEB,      pBH); CP16(d + 2 * TILEB + 16, pBH + 8);
        CP16(d + 3 * TILEB,      pBL); CP16(d + 3 * TILEB + 16, pBL + 8);
        CP_COMMIT();
    }

    // ldmatrix base offsets (within a stage)
    uint32_t a_rel = (uint32_t)(((wid & 1) * 64 + (lane & 15)) * ROWB + (lane >> 4) * 16);
    uint32_t b_rel = (uint32_t)(2 * TILEB +
        ((wid >> 1) * 32 + (lane & 7) + ((lane >> 4) & 1) * 8) * ROWB +
        ((lane >> 3) & 1) * 16);

    for (int s = 0; s < NS; s++) {
        if (s + 1 < NS) {
            size_t ko = (size_t)(s + 1) * 32;
            uint32_t d = sb + ((s + 1) & 1) * STAGE + dstrel;
            CP16(d + 0 * TILEB,      pAH + ko); CP16(d + 0 * TILEB + 16, pAH + ko + 8);
            CP16(d + 1 * TILEB,      pAL + ko); CP16(d + 1 * TILEB + 16, pAL + ko + 8);
            CP16(d + 2 * TILEB,      pBH + ko); CP16(d + 2 * TILEB + 16, pBH + ko + 8);
            CP16(d + 3 * TILEB,      pBL + ko); CP16(d + 3 * TILEB + 16, pBL + ko + 8);
            CP_COMMIT();
            CP_WAIT(1);
        } else {
            CP_WAIT(0);
        }
        __syncthreads();
        uint32_t base = sb + (s & 1) * STAGE;
#pragma unroll
        for (int kh = 0; kh < 2; kh++) {
            uint32_t koffb = kh * 32;
            uint32_t ah[4][4], al[4][4];
            uint32_t aaddr = base + a_rel + koffb;
#pragma unroll
            for (int mi = 0; mi < 4; mi++) {
                ldsm_x4(ah[mi], aaddr + mi * 16 * ROWB);
                ldsm_x4(al[mi], aaddr + mi * 16 * ROWB + TILEB);
            }
            uint32_t bh[4][2], bl[4][2];
            uint32_t baddr = base + b_rel + koffb;
#pragma unroll
            for (int hf = 0; hf < 2; hf++) {
                uint32_t t4[4];
                ldsm_x4(t4, baddr + hf * 16 * ROWB);
                bh[2 * hf][0] = t4[0]; bh[2 * hf][1] = t4[1];
                bh[2 * hf + 1][0] = t4[2]; bh[2 * hf + 1][1] = t4[3];
                ldsm_x4(t4, baddr + hf * 16 * ROWB + TILEB);
                bl[2 * hf][0] = t4[0]; bl[2 * hf][1] = t4[1];
                bl[2 * hf + 1][0] = t4[2]; bl[2 * hf + 1][1] = t4[3];
            }
#pragma unroll
            for (int mi = 0; mi < 4; mi++)
#pragma unroll
                for (int ni = 0; ni < 4; ni++) {
                    mma_bf16(acc[mi][ni], ah[mi], bh[ni]);
                    mma_bf16(acc[mi][ni], al[mi], bh[ni]);
                    mma_bf16(acc[mi][ni], ah[mi], bl[ni]);
                }
        }
        __syncthreads();
    }

    // ---- epilogue
    int mW = m0 + (wid & 1) * 64;
    int nW = n0 + (wid >> 1) * 32;
#pragma unroll
    for (int mi = 0; mi < 4; mi++) {
#pragma unroll
        for (int hf = 0; hf < 2; hf++) {
            int r = mW + mi * 16 + hf * 8 + (lane >> 2);
            if (r >= Meff) continue;
            int crow = mode ? (off + r) : r;
#pragma unroll
            for (int ni = 0; ni < 4; ni++) {
                int c = nW + ni * 8 + (lane & 3) * 2;
                size_t co = (size_t)crow * N + c;
                float v0 = acc[mi][ni][2 * hf + 0];
                float v1 = acc[mi][ni][2 * hf + 1];
                if (addsrc) {
                    v0 += addsrc[co];
                    v1 += addsrc[co + 1];
                }
                float2 v = {v0, v1};
                *(float2*)(C + co) = v;
            }
        }
    }
}

// ---------------------------------------------------------------------------
// RoPE in place on q (16 heads) and k (4 heads); rotated k also to outk.
// ---------------------------------------------------------------------------
__global__ void rope_kernel(const float* __restrict__ cosb,
                            const float* __restrict__ sinb,
                            float* __restrict__ q,
                            float* __restrict__ k,
                            float* __restrict__ outk) {
    int t = blockIdx.x;
    int s = t % Ss;
    const float* cs = cosb + (size_t)s * HDd;
    const float* sn = sinb + (size_t)s * HDd;

    float* qrow = q + (size_t)t * QD;
    for (int idx = threadIdx.x; idx < Hh * 32; idx += blockDim.x) {
        int hh = idx >> 5, d = idx & 31;
        float* p = qrow + hh * HDd;
        float a = p[d], b2 = p[d + 32];
        p[d]      = a * cs[d]       - b2 * sn[d];
        p[d + 32] = b2 * cs[d + 32] + a * sn[d + 32];
    }
    float* krow = k + (size_t)t * KD;
    float* okr = outk + (size_t)t * KD;
    for (int idx = threadIdx.x; idx < KVh * 32; idx += blockDim.x) {
        int hh = idx >> 5, d = idx & 31;
        float* p = krow + hh * HDd;
        float a = p[d], b2 = p[d + 32];
        float o1 = a * cs[d]       - b2 * sn[d];
        float o2 = b2 * cs[d + 32] + a * sn[d + 32];
        p[d] = o1; p[d + 32] = o2;
        okr[hh * HDd + d] = o1;
        okr[hh * HDd + d + 32] = o2;
    }
}

// ---------------------------------------------------------------------------
// Causal GQA flash attention; epilogue writes bf16 hi/lo split.
// ---------------------------------------------------------------------------
__global__ void __launch_bounds__(128)
attn_kernel(const float* __restrict__ q,
            const float* __restrict__ k,
            const float* __restrict__ v,
            __nv_bfloat16* __restrict__ ohi,
            __nv_bfloat16* __restrict__ olo) {
    int b = blockIdx.z, h = blockIdx.y, qt = blockIdx.x;
    int kvh = h >> 2;
    int qi = qt * 128 + threadIdx.x;

    size_t qoff = ((size_t)(b * Ss + qi)) * QD + h * HDd;
    float qreg[64];
#pragma unroll
    for (int d = 0; d < 64; d++) qreg[d] = q[qoff + d] * 0.125f;
    float acc[64];
#pragma unroll
    for (int d = 0; d < 64; d++) acc[d] = 0.f;
    float m = -1e30f, l = 0.f;

    __shared__ float Ks[64][68];
    __shared__ float Vs[64][68];

    int ntiles = (qt + 1) * 2;
    int lr = threadIdx.x >> 1, lc = (threadIdx.x & 1) * 32;
    for (int ktile = 0; ktile < ntiles; ktile++) {
        int k0 = ktile * 64;
        __syncthreads();
        size_t ksrc = ((size_t)(b * Ss + k0 + lr)) * KD + kvh * HDd + lc;
#pragma unroll
        for (int i = 0; i < 8; i++) {
            *(float4*)&Ks[lr][lc + i * 4] = *(const float4*)&k[ksrc + i * 4];
            *(float4*)&Vs[lr][lc + i * 4] = *(const float4*)&v[ksrc + i * 4];
        }
        __syncthreads();
        int jmax = qi - k0;
        int jend = (jmax >= 63) ? 64 : (jmax + 1);
        for (int j = 0; j < jend; j++) {
            float s0 = 0.f, s1 = 0.f, s2 = 0.f, s3 = 0.f;
#pragma unroll
            for (int d4 = 0; d4 < 16; d4++) {
                float4 kv = *(const float4*)&Ks[j][d4 * 4];
                s0 += qreg[d4 * 4 + 0] * kv.x;
                s1 += qreg[d4 * 4 + 1] * kv.y;
                s2 += qreg[d4 * 4 + 2] * kv.z;
                s3 += qreg[d4 * 4 + 3] * kv.w;
            }
            float s = (s0 + s1) + (s2 + s3);
            if (s > m) {
                float corr = __expf(m - s);
                l *= corr;
#pragma unroll
                for (int d = 0; d < 64; d++) acc[d] *= corr;
                m = s;
            }
            float p = __expf(s - m);
            l += p;
#pragma unroll
            for (int d4 = 0; d4 < 16; d4++) {
                float4 vv = *(const float4*)&Vs[j][d4 * 4];
                acc[d4 * 4 + 0] += p * vv.x;
                acc[d4 * 4 + 1] += p * vv.y;
                acc[d4 * 4 + 2] += p * vv.z;
                acc[d4 * 4 + 3] += p * vv.w;
            }
        }
    }
    float inv = 1.f / l;
    size_t ooff = ((size_t)(b * Ss + qi)) * QD + h * HDd;
#pragma unroll
    for (int d = 0; d < 64; d++) {
        float val = acc[d] * inv;
        __nv_bfloat16 hi = __float2bfloat16(val);
        float lo = val - __bfloat162float(hi);
        ohi[ooff + d] = hi;
        olo[ooff + d] = __float2bfloat16(lo);
    }
}

// ---------------------------------------------------------------------------
// Router + compacted slot assignment
// ---------------------------------------------------------------------------
__global__ void zero_cnt_kernel() {
    if (threadIdx.x < Ee) g_cnt[threadIdx.x] = 0;
}

__global__ void router_kernel(const float* __restrict__ y,
                              const float* __restrict__ rw) {
    int t = (blockIdx.x * blockDim.x + threadIdx.x) >> 5;
    int lane = threadIdx.x & 31;
    if (t >= NT) return;
    const float* yrow = y + (size_t)t * Dd;
    float logits[8] = {};
    for (int i = 0; i < 32; i++) {
        int d = i * 32 + lane;
        float yv = yrow[d];
#pragma unroll
        for (int e = 0; e < 8; e++) logits[e] += yv * rw[d * 8 + e];
    }
#pragma unroll
    for (int e = 0; e < 8; e++) {
#pragma unroll
        for (int o = 16; o > 0; o >>= 1)
            logits[e] += __shfl_xor_sync(0xffffffffu, logits[e], o);
    }
    if (lane == 0) {
        int i0 = 0; float v0 = logits[0];
#pragma unroll
        for (int e = 1; e < 8; e++) if (logits[e] > v0) { v0 = logits[e]; i0 = e; }
        int i1 = -1; float v1 = -1e30f;
#pragma unroll
        for (int e = 0; e < 8; e++)
            if (e != i0 && logits[e] > v1) { v1 = logits[e]; i1 = e; }
        float e1 = __expf(v1 - v0);
        g_texp[t * 2 + 0] = i0;
        g_texp[t * 2 + 1] = i1;
        g_gw[t * 2 + 0] = 1.f / (1.f + e1);
        g_gw[t * 2 + 1] = e1 / (1.f + e1);
        atomicAdd(&g_cnt[i0], 1);
        atomicAdd(&g_cnt[i1], 1);
    }
}

__global__ void offsets_kernel() {
    if (threadIdx.x == 0) {
        int a = 0;
        for (int e = 0; e < Ee; e++) { g_off[e] = a; a += g_cnt[e]; g_fill[e] = 0; }
    }
}

__global__ void scatter_kernel() {
    int t = blockIdx.x * blockDim.x + threadIdx.x;
    if (t >= NT) return;
#pragma unroll
    for (int j = 0; j < 2; j++) {
        int e = g_texp[t * 2 + j];
        int p = atomicAdd(&g_fill[e], 1);
        int slot = g_off[e] + p;
        g_list[slot] = t;
        g_slot[t * 2 + j] = slot;
    }
}

// ---------------------------------------------------------------------------
// he = silu(gate) * up, split to bf16 hi/lo. Slots are compact [0, NSLOT).
// ---------------------------------------------------------------------------
__global__ void silu_split_kernel() {
    size_t off = (size_t)blockIdx.x * Ff + blockIdx.y * 256 + threadIdx.x;
    float g = g_ga[off], u = g_ua[off];
    float v = (g / (1.f + __expf(-g))) * u;
    __nv_bfloat16 hi = __float2bfloat16(v);
    float lo = v - __bfloat162float(hi);
    g_hehi[off] = hi;
    g_helo[off] = __float2bfloat16(lo);
}

// ---------------------------------------------------------------------------
// out = h + w0 * down[slot0] + w1 * down[slot1]
// ---------------------------------------------------------------------------
__global__ void combine_kernel(float* __restrict__ out) {
    int t = blockIdx.x;
    int d = blockIdx.y * 256 + threadIdx.x;
    int s0 = g_slot[t * 2], s1 = g_slot[t * 2 + 1];
    float w0 = g_gw[t * 2], w1 = g_gw[t * 2 + 1];
    size_t o = (size_t)t * Dd + d;
    out[o] = g_h[o] + w0 * g_dn[(size_t)s0 * Dd + d]
                    + w1 * g_dn[(size_t)s1 * Dd + d];
}

// ---------------------------------------------------------------------------
// Launch
// ---------------------------------------------------------------------------
extern "C" void kernel_launch(void* const* d_in, const int* in_sizes, int n_in,
                              void* d_out, int out_size) {
    const float* input  = (const float*)d_in[0];
    const float* cosb   = (const float*)d_in[1];
    const float* sinb   = (const float*)d_in[2];
    // d_in[3] = mask (causal, unused)
    const float* w_attn = (const float*)d_in[4];
    const float* w_moe  = (const float*)d_in[5];
    const float* Wq     = (const float*)d_in[6];
    const float* Wk     = (const float*)d_in[7];
    const float* Wv     = (const float*)d_in[8];
    const float* Wo     = (const float*)d_in[9];
    const float* rw     = (const float*)d_in[10];
    const float* Wg     = (const float*)d_in[11];
    const float* Wu     = (const float*)d_in[12];
    const float* Wd     = (const float*)d_in[13];

    cudaFuncSetAttribute(mma_gemm, cudaFuncAttributeMaxDynamicSharedMemorySize, GSMEM);

    float *pq, *pk, *pvs, *pks, *ph, *py, *pga, *pua, *pdn;
    cudaGetSymbolAddress((void**)&pq,  g_q);
    cudaGetSymbolAddress((void**)&pk,  g_k);
    cudaGetSymbolAddress((void**)&pvs, g_vscr);
    cudaGetSymbolAddress((void**)&pks, g_kscr);
    cudaGetSymbolAddress((void**)&ph,  g_h);
    cudaGetSymbolAddress((void**)&py,  g_y);
    cudaGetSymbolAddress((void**)&pga, g_ga);
    cudaGetSymbolAddress((void**)&pua, g_ua);
    cudaGetSymbolAddress((void**)&pdn, g_dn);

    __nv_bfloat16 *xhi, *xlo, *ahi, *alo, *yhi, *ylo, *hehi, *helo;
    __nv_bfloat16 *wqh, *wql, *wkh, *wkl, *wvh, *wvl, *woh, *wol;
    __nv_bfloat16 *wgh, *wgl, *wuh, *wul, *wdh, *wdl;
    cudaGetSymbolAddress((void**)&xhi, g_xhi);  cudaGetSymbolAddress((void**)&xlo, g_xlo);
    cudaGetSymbolAddress((void**)&ahi, g_ahi);  cudaGetSymbolAddress((void**)&alo, g_alo);
    cudaGetSymbolAddress((void**)&yhi, g_yhi);  cudaGetSymbolAddress((void**)&ylo, g_ylo);
    cudaGetSymbolAddress((void**)&hehi, g_hehi); cudaGetSymbolAddress((void**)&helo, g_helo);
    cudaGetSymbolAddress((void**)&wqh, g_wq_hi); cudaGetSymbolAddress((void**)&wql, g_wq_lo);
    cudaGetSymbolAddress((void**)&wkh, g_wk_hi); cudaGetSymbolAddress((void**)&wkl, g_wk_lo);
    cudaGetSymbolAddress((void**)&wvh, g_wv_hi); cudaGetSymbolAddress((void**)&wvl, g_wv_lo);
    cudaGetSymbolAddress((void**)&woh, g_wo_hi); cudaGetSymbolAddress((void**)&wol, g_wo_lo);
    cudaGetSymbolAddress((void**)&wgh, g_wg_hi); cudaGetSymbolAddress((void**)&wgl, g_wg_lo);
    cudaGetSymbolAddress((void**)&wuh, g_wu_hi); cudaGetSymbolAddress((void**)&wul, g_wu_lo);
    cudaGetSymbolAddress((void**)&wdh, g_wd_hi); cudaGetSymbolAddress((void**)&wdl, g_wd_lo);

    float* out = (float*)d_out;
    size_t need = (size_t)NT * Dd + 2 * (size_t)NT * KD;
    bool full = ((size_t)out_size >= need);
    float* outk = full ? (out + (size_t)NT * Dd) : pks;
    float* outv = full ? (out + (size_t)NT * Dd + (size_t)NT * KD) : pvs;

    dim3 tb(32, 8);
    // weight split-transposes
    transpose_split_kernel<<<dim3(QD / 32, Dd / 32, 1),  tb>>>(Wq, wqh, wql, Dd, QD);
    transpose_split_kernel<<<dim3(KD / 32, Dd / 32, 1),  tb>>>(Wk, wkh, wkl, Dd, KD);
    transpose_split_kernel<<<dim3(KD / 32, Dd / 32, 1),  tb>>>(Wv, wvh, wvl, Dd, KD);
    transpose_split_kernel<<<dim3(Dd / 32, QD / 32, 1),  tb>>>(Wo, woh, wol, QD, Dd);
    transpose_split_kernel<<<dim3(Ff / 32, Dd / 32, Ee), tb>>>(Wg, wgh, wgl, Dd, Ff);
    transpose_split_kernel<<<dim3(Ff / 32, Dd / 32, Ee), tb>>>(Wu, wuh, wul, Dd, Ff);
    transpose_split_kernel<<<dim3(Dd / 32, Ff / 32, Ee), tb>>>(Wd, wdh, wdl, Ff, Dd);

    // 1. x = rmsnorm(input) -> split
    rmsnorm_split_kernel<<<NT, 256>>>(input, w_attn, xhi, xlo, nullptr);
    // 2. q/k/v projections
    mma_gemm<<<dim3(QD / 128, NT / 128, 1), 256, GSMEM>>>(
        xhi, xlo, wqh, wql, 0, pq, nullptr, 0, NT, QD, Dd);
    mma_gemm<<<dim3(KD / 128, NT / 128, 1), 256, GSMEM>>>(
        xhi, xlo, wkh, wkl, 0, pk, nullptr, 0, NT, KD, Dd);
    mma_gemm<<<dim3(KD / 128, NT / 128, 1), 256, GSMEM>>>(
        xhi, xlo, wvh, wvl, 0, outv, nullptr, 0, NT, KD, Dd);
    // 3. RoPE
    rope_kernel<<<NT, 256>>>(cosb, sinb, pq, pk, outk);
    // 4. attention -> split output
    attn_kernel<<<dim3(Ss / 128, Hh, Bb), 128>>>(pq, pk, outv, ahi, alo);
    // 5. h = input + attn @ Wo
    mma_gemm<<<dim3(Dd / 128, NT / 128, 1), 256, GSMEM>>>(
        ahi, alo, woh, wol, 0, ph, input, 0, NT, Dd, QD);
    // 6. y = rmsnorm(h) -> split + f32
    rmsnorm_split_kernel<<<NT, 256>>>(ph, w_moe, yhi, ylo, py);
    // 7. router + compact slots
    zero_cnt_kernel<<<1, 32>>>();
    router_kernel<<<NT / 8, 256>>>(py, rw);
    offsets_kernel<<<1, 32>>>();
    scatter_kernel<<<NT / 256, 256>>>();
    // 8. expert gate / up GEMMs (gathered A rows)
    mma_gemm<<<dim3(Ff / 128, NT / 128, Ee), 256, GSMEM>>>(
        yhi, ylo, wgh, wgl, (size_t)Ff * Dd, pga, nullptr, 1, NT, Ff, Dd);
    mma_gemm<<<dim3(Ff / 128, NT / 128, Ee), 256, GSMEM>>>(
        yhi, ylo, wuh, wul, (size_t)Ff * Dd, pua, nullptr, 1, NT, Ff, Dd);
    // 9. he = silu(gate) * up -> split
    silu_split_kernel<<<dim3(NSLOT, Ff / 256), 256>>>();
    // 10. down projection (contiguous slot rows)
    mma_gemm<<<dim3(Dd / 128, NT / 128, Ee), 256, GSMEM>>>(
        hehi, helo, wdh, wdl, (size_t)Dd * Ff, pdn, nullptr, 2, NT, Dd, Ff);
    // 11. combine
    combine_kernel<<<dim3(NT, Dd / 256), 256>>>(out);
}

// round 9
// speedup vs baseline: 1.7362x; 1.0995x over previous
#include <cuda_runtime.h>
#include <cuda_fp16.h>
#include <cstdint>

// ---------------------------------------------------------------------------
// MoE transformer block. Split-fp16 (2-term) warp-MMA GEMMs + f32x2 flash attn.
// B=4 S=2048 D=1024 H=16 KV=4 HD=64 E=8 K(top)=2 F=1024
// Base sm_103 PTX only: mma.sync / ldmatrix / cp.async / fma.rn.f32x2.
// ---------------------------------------------------------------------------

namespace {
constexpr int Bb  = 4;
constexpr int Ss  = 2048;
constexpr int Dd  = 1024;
constexpr int Hh  = 16;
constexpr int KVh = 4;
constexpr int HDd = 64;
constexpr int Ee  = 8;
constexpr int TKk = 2;
constexpr int Ff  = 1024;
constexpr int NT  = Bb * Ss;        // 8192 tokens
constexpr int QD  = Hh * HDd;       // 1024
constexpr int KD  = KVh * HDd;      // 256
constexpr int NSLOT = NT * TKk;     // 16384 expert slots

// GEMM tiling
constexpr int ROWB  = 80;                 // smem row stride bytes (32 fp16 + pad)
constexpr int TILEB = 128 * ROWB;         // one 128x32 fp16 tile = 10240 B
constexpr int STAGE = 3 * TILEB;          // AH, AL, BH
constexpr int GSMEM = 2 * STAGE;          // 61440 B double-buffered
}

__device__ __forceinline__ uint32_t smem_u32(const void* p) {
    uint32_t a;
    asm("{ .reg .u64 t; cvta.to.shared.u64 t, %1; cvt.u32.u64 %0, t; }" : "=r"(a) : "l"(p));
    return a;
}
#define CP16(dst, src) asm volatile( \
    "cp.async.cg.shared.global [%0], [%1], 16;" :: "r"(dst), "l"(src))
#define CP_COMMIT() asm volatile("cp.async.commit_group;" ::: "memory")
#define CP_WAIT(n)  asm volatile("cp.async.wait_group %0;" :: "n"(n) : "memory")

__device__ __forceinline__ void ldsm_x4(uint32_t* r, uint32_t addr) {
    asm volatile("ldmatrix.sync.aligned.m8n8.x4.shared.b16 {%0,%1,%2,%3}, [%4];"
                 : "=r"(r[0]), "=r"(r[1]), "=r"(r[2]), "=r"(r[3]) : "r"(addr));
}
__device__ __forceinline__ void mma_fp16(float* c, const uint32_t* a, const uint32_t* b) {
    asm volatile(
        "mma.sync.aligned.m16n8k16.row.col.f32.f16.f16.f32 "
        "{%0,%1,%2,%3}, {%4,%5,%6,%7}, {%8,%9}, {%0,%1,%2,%3};"
        : "+f"(c[0]), "+f"(c[1]), "+f"(c[2]), "+f"(c[3])
        : "r"(a[0]), "r"(a[1]), "r"(a[2]), "r"(a[3]), "r"(b[0]), "r"(b[1]));
}

// ---- packed f32x2 (Blackwell base ISA)
typedef unsigned long long u64;
__device__ __forceinline__ u64 pack2(float lo, float hi) {
    u64 r; asm("mov.b64 %0, {%1, %2};" : "=l"(r) : "f"(lo), "f"(hi)); return r;
}
__device__ __forceinline__ void unpack2(u64 v, float& lo, float& hi) {
    asm("mov.b64 {%0, %1}, %2;" : "=f"(lo), "=f"(hi) : "l"(v));
}
__device__ __forceinline__ u64 fma2(u64 a, u64 b, u64 c) {
    u64 d; asm("fma.rn.f32x2 %0, %1, %2, %3;" : "=l"(d) : "l"(a), "l"(b), "l"(c)); return d;
}
__device__ __forceinline__ u64 mul2(u64 a, u64 b) {
    u64 d; asm("mul.rn.f32x2 %0, %1, %2;" : "=l"(d) : "l"(a), "l"(b)); return d;
}

// ---------------------------------------------------------------------------
// Scratch (device globals; no runtime allocation)
// ---------------------------------------------------------------------------
__device__ __align__(128) float g_q[(size_t)NT * QD];
__device__ __align__(128) float g_k[(size_t)NT * KD];
__device__ __align__(128) float g_vscr[(size_t)NT * KD];
__device__ __align__(128) float g_kscr[(size_t)NT * KD];
__device__ __align__(128) float g_h[(size_t)NT * Dd];
__device__ __align__(128) float g_y[(size_t)NT * Dd];
__device__ __align__(128) float g_ga[(size_t)NSLOT * Ff];
__device__ __align__(128) float g_ua[(size_t)NSLOT * Ff];
__device__ __align__(128) float g_dn[(size_t)NSLOT * Dd];

__device__ __align__(128) __half g_xhi[(size_t)NT * Dd], g_xlo[(size_t)NT * Dd];
__device__ __align__(128) __half g_ahi[(size_t)NT * QD], g_alo[(size_t)NT * QD];
__device__ __align__(128) __half g_yhi[(size_t)NT * Dd], g_ylo[(size_t)NT * Dd];
__device__ __align__(128) __half g_hehi[(size_t)NSLOT * Ff], g_helo[(size_t)NSLOT * Ff];

// transposed fp16 weights [N, K]
__device__ __align__(128) __half g_wq[(size_t)QD * Dd];
__device__ __align__(128) __half g_wk[(size_t)KD * Dd];
__device__ __align__(128) __half g_wv[(size_t)KD * Dd];
__device__ __align__(128) __half g_wo[(size_t)Dd * QD];
__device__ __align__(128) __half g_wg[(size_t)Ee * Ff * Dd];
__device__ __align__(128) __half g_wu[(size_t)Ee * Ff * Dd];
__device__ __align__(128) __half g_wd[(size_t)Ee * Dd * Ff];

__device__ int   g_cnt[Ee];
__device__ int   g_off[Ee];
__device__ int   g_fill[Ee];
__device__ int   g_list[NSLOT];
__device__ int   g_slot[NSLOT];
__device__ int   g_texp[NSLOT];
__device__ float g_gw[NSLOT];

// ---------------------------------------------------------------------------
// RMSNorm with fp16 hi/lo split output (+ optional f32 output)
// ---------------------------------------------------------------------------
__global__ void rmsnorm_split_kernel(const float* __restrict__ in,
                                     const float* __restrict__ w,
                                     __half* __restrict__ ohi,
                                     __half* __restrict__ olo,
                                     float* __restrict__ of32) {
    int t = blockIdx.x;
    const float* row = in + (size_t)t * Dd;
    float ss = 0.f;
#pragma unroll
    for (int i = 0; i < 4; i++) { float v = row[threadIdx.x + i * 256]; ss += v * v; }
#pragma unroll
    for (int o = 16; o > 0; o >>= 1) ss += __shfl_xor_sync(0xffffffffu, ss, o);
    __shared__ float sred[8];
    if ((threadIdx.x & 31) == 0) sred[threadIdx.x >> 5] = ss;
    __syncthreads();
    if (threadIdx.x < 32) {
        float v = (threadIdx.x < 8) ? sred[threadIdx.x] : 0.f;
#pragma unroll
        for (int o = 4; o > 0; o >>= 1) v += __shfl_xor_sync(0xffffffffu, v, o);
        if (threadIdx.x == 0) sred[0] = v;
    }
    __syncthreads();
    float inv = rsqrtf(sred[0] * (1.f / Dd) + 1e-6f);
    size_t base = (size_t)t * Dd;
#pragma unroll
    for (int i = 0; i < 4; i++) {
        int d = threadIdx.x + i * 256;
        float r = row[d] * inv * w[d];
        __half hi = __float2half_rn(r);
        float lo = r - __half2float(hi);
        ohi[base + d] = hi;
        olo[base + d] = __float2half_rn(lo);
        if (of32) of32[base + d] = r;
    }
}

// ---------------------------------------------------------------------------
// Transpose: W[K,N] fp32 -> T[N,K] fp16. Block (32,8).
// ---------------------------------------------------------------------------
__global__ void transpose_half_kernel(const float* __restrict__ W,
                                      __half* __restrict__ T,
                                      int K, int N) {
    __shared__ float tile[32][33];
    size_t zb = (size_t)blockIdx.z * K * N;
    int k0 = blockIdx.y * 32, n0 = blockIdx.x * 32;
    int tx = threadIdx.x, ty = threadIdx.y;
#pragma unroll
    for (int j = 0; j < 4; j++)
        tile[ty + 8 * j][tx] = W[zb + (size_t)(k0 + ty + 8 * j) * N + n0 + tx];
    __syncthreads();
#pragma unroll
    for (int j = 0; j < 4; j++) {
        float v = tile[tx][ty + 8 * j];
        T[zb + (size_t)(n0 + ty + 8 * j) * K + k0 + tx] = __float2half_rn(v);
    }
}

// ---------------------------------------------------------------------------
// Warp-MMA GEMM: C[M,N] = Ahi@B + Alo@B (fp32 accum)
// A: [M,K] fp16 K-major (hi/lo). B: [N,K] fp16 K-major. K % 32 == 0.
// CTA tile 128x128, BK=32, double-buffered cp.async smem, 256 threads.
// 8 warps: warp_m = wid&1 (64 rows), warp_n = wid>>1 (32 cols).
// mode 0: plain. mode 1: A rows via g_list[g_off[z]+r], C rows g_off[z]+r,
//         Meff=g_cnt[z]. mode 2: A/C rows at g_off[z]+r.
// ---------------------------------------------------------------------------
__global__ void __launch_bounds__(256, 1)
mma_gemm(const __half* __restrict__ Ahi, const __half* __restrict__ Alo,
         const __half* __restrict__ Bw,
         size_t bz,
         float* __restrict__ C,
         const float* __restrict__ addsrc,
         int mode, int M, int N, int K) {
    extern __shared__ char smem[];
    int z = blockIdx.z;
    int Meff = M, off = 0;
    if (mode) { Meff = g_cnt[z]; off = g_off[z]; }
    int m0 = blockIdx.y * 128;
    if (m0 >= Meff) return;
    int n0 = blockIdx.x * 128;
    const __half* bw = Bw + bz * z;

    int tid = threadIdx.x, lane = tid & 31, wid = tid >> 5;
    uint32_t sb = smem_u32(smem);

    // ---- global->smem load mapping: thread loads one row (32B half) per tile
    int lrow = tid >> 1;
    int lcolh = (tid & 1) * 16;           // offset in halves
    int ar = m0 + lrow;
    long grow;
    if (mode == 1) { int rr = (ar < Meff) ? ar : (Meff - 1); grow = g_list[off + rr]; }
    else if (mode == 2) { int rr = (ar < Meff) ? ar : (Meff - 1); grow = off + rr; }
    else grow = ar;
    const __half* pAH = Ahi + (size_t)grow * K + lcolh;
    const __half* pAL = Alo + (size_t)grow * K + lcolh;
    const __half* pBH = bw + (size_t)(n0 + lrow) * K + lcolh;
    uint32_t dstrel = (uint32_t)(lrow * ROWB + lcolh * 2);

    float acc[4][4][4];
#pragma unroll
    for (int i = 0; i < 4; i++)
#pragma unroll
        for (int j = 0; j < 4; j++)
#pragma unroll
            for (int q = 0; q < 4; q++) acc[i][j][q] = 0.f;

    const int NS = K / 32;
    // prologue: stage 0
    {
        uint32_t d = sb + dstrel;
        CP16(d + 0 * TILEB,      pAH); CP16(d + 0 * TILEB + 16, pAH + 8);
        CP16(d + 1 * TILEB,      pAL); CP16(d + 1 * TILEB + 16, pAL + 8);
        CP16(d + 2 * TILEB,      pBH); CP16(d + 2 * TILEB + 16, pBH + 8);
        CP_COMMIT();
    }

    // ldmatrix base offsets (within a stage)
    uint32_t a_rel = (uint32_t)(((wid & 1) * 64 + (lane & 15)) * ROWB + (lane >> 4) * 16);
    uint32_t b_rel = (uint32_t)(2 * TILEB +
        ((wid >> 1) * 32 + (lane & 7) + ((lane >> 4) & 1) * 8) * ROWB +
        ((lane >> 3) & 1) * 16);

    for (int s = 0; s < NS; s++) {
        if (s + 1 < NS) {
            size_t ko = (size_t)(s + 1) * 32;
            uint32_t d = sb + ((s + 1) & 1) * STAGE + dstrel;
            CP16(d + 0 * TILEB,      pAH + ko); CP16(d + 0 * TILEB + 16, pAH + ko + 8);
            CP16(d + 1 * TILEB,      pAL + ko); CP16(d + 1 * TILEB + 16, pAL + ko + 8);
            CP16(d + 2 * TILEB,      pBH + ko); CP16(d + 2 * TILEB + 16, pBH + ko + 8);
            CP_COMMIT();
            CP_WAIT(1);
        } else {
            CP_WAIT(0);
        }
        __syncthreads();
        uint32_t base = sb + (s & 1) * STAGE;
#pragma unroll
        for (int kh = 0; kh < 2; kh++) {
            uint32_t koffb = kh * 32;
            uint32_t ah[4][4], al[4][4];
            uint32_t aaddr = base + a_rel + koffb;
#pragma unroll
            for (int mi = 0; mi < 4; mi++) {
                ldsm_x4(ah[mi], aaddr + mi * 16 * ROWB);
                ldsm_x4(al[mi], aaddr + mi * 16 * ROWB + TILEB);
            }
            uint32_t bh[4][2];
            uint32_t baddr = base + b_rel + koffb;
#pragma unroll
            for (int hf = 0; hf < 2; hf++) {
                uint32_t t4[4];
                ldsm_x4(t4, baddr + hf * 16 * ROWB);
                bh[2 * hf][0] = t4[0]; bh[2 * hf][1] = t4[1];
                bh[2 * hf + 1][0] = t4[2]; bh[2 * hf + 1][1] = t4[3];
            }
#pragma unroll
            for (int mi = 0; mi < 4; mi++)
#pragma unroll
                for (int ni = 0; ni < 4; ni++) {
                    mma_fp16(acc[mi][ni], ah[mi], bh[ni]);
                    mma_fp16(acc[mi][ni], al[mi], bh[ni]);
                }
        }
        __syncthreads();
    }

    // ---- epilogue
    int mW = m0 + (wid & 1) * 64;
    int nW = n0 + (wid >> 1) * 32;
#pragma unroll
    for (int mi = 0; mi < 4; mi++) {
#pragma unroll
        for (int hf = 0; hf < 2; hf++) {
            int r = mW + mi * 16 + hf * 8 + (lane >> 2);
            if (r >= Meff) continue;
            int crow = mode ? (off + r) : r;
#pragma unroll
            for (int ni = 0; ni < 4; ni++) {
                int c = nW + ni * 8 + (lane & 3) * 2;
                size_t co = (size_t)crow * N + c;
                float v0 = acc[mi][ni][2 * hf + 0];
                float v1 = acc[mi][ni][2 * hf + 1];
                if (addsrc) {
                    v0 += addsrc[co];
                    v1 += addsrc[co + 1];
                }
                float2 v = {v0, v1};
                *(float2*)(C + co) = v;
            }
        }
    }
}

// ---------------------------------------------------------------------------
// RoPE in place on q (16 heads) and k (4 heads); rotated k also to outk.
// ---------------------------------------------------------------------------
__global__ void rope_kernel(const float* __restrict__ cosb,
                            const float* __restrict__ sinb,
                            float* __restrict__ q,
                            float* __restrict__ k,
                            float* __restrict__ outk) {
    int t = blockIdx.x;
    int s = t % Ss;
    const float* cs = cosb + (size_t)s * HDd;
    const float* sn = sinb + (size_t)s * HDd;

    float* qrow = q + (size_t)t * QD;
    for (int idx = threadIdx.x; idx < Hh * 32; idx += blockDim.x) {
        int hh = idx >> 5, d = idx & 31;
        float* p = qrow + hh * HDd;
        float a = p[d], b2 = p[d + 32];
        p[d]      = a * cs[d]       - b2 * sn[d];
        p[d + 32] = b2 * cs[d + 32] + a * sn[d + 32];
    }
    float* krow = k + (size_t)t * KD;
    float* okr = outk + (size_t)t * KD;
    for (int idx = threadIdx.x; idx < KVh * 32; idx += blockDim.x) {
        int hh = idx >> 5, d = idx & 31;
        float* p = krow + hh * HDd;
        float a = p[d], b2 = p[d + 32];
        float o1 = a * cs[d]       - b2 * sn[d];
        float o2 = b2 * cs[d + 32] + a * sn[d + 32];
        p[d] = o1; p[d + 32] = o2;
        okr[hh * HDd + d] = o1;
        okr[hh * HDd + d + 32] = o2;
    }
}

// ---------------------------------------------------------------------------
// Causal GQA flash attention with packed f32x2 math; fp16 hi/lo epilogue.
// One thread = one query row; 64-key tiles staged in smem.
// ---------------------------------------------------------------------------
__global__ void __launch_bounds__(128)
attn_kernel(const float* __restrict__ q,
            const float* __restrict__ k,
            const float* __restrict__ v,
            __half* __restrict__ ohi,
            __half* __restrict__ olo) {
    int b = blockIdx.z, h = blockIdx.y, qt = blockIdx.x;
    int kvh = h >> 2;
    int qi = qt * 128 + threadIdx.x;

    size_t qoff = ((size_t)(b * Ss + qi)) * QD + h * HDd;
    u64 qp[32];
#pragma unroll
    for (int i = 0; i < 32; i++)
        qp[i] = pack2(q[qoff + 2 * i] * 0.125f, q[qoff + 2 * i + 1] * 0.125f);
    u64 accp[32];
#pragma unroll
    for (int i = 0; i < 32; i++) accp[i] = 0ull;
    float m = -1e30f, l = 0.f;

    __shared__ float Ks[64][68];
    __shared__ float Vs[64][68];

    int ntiles = (qt + 1) * 2;
    int lr = threadIdx.x >> 1, lc = (threadIdx.x & 1) * 32;
    for (int ktile = 0; ktile < ntiles; ktile++) {
        int k0 = ktile * 64;
        __syncthreads();
        size_t ksrc = ((size_t)(b * Ss + k0 + lr)) * KD + kvh * HDd + lc;
#pragma unroll
        for (int i = 0; i < 8; i++) {
            *(float4*)&Ks[lr][lc + i * 4] = *(const float4*)&k[ksrc + i * 4];
            *(float4*)&Vs[lr][lc + i * 4] = *(const float4*)&v[ksrc + i * 4];
        }
        __syncthreads();
        int jmax = qi - k0;
        int jend = (jmax >= 63) ? 64 : (jmax + 1);
        for (int j = 0; j < jend; j++) {
            const ulonglong2* kp = (const ulonglong2*)&Ks[j][0];
            u64 s0 = 0ull, s1 = 0ull, s2 = 0ull, s3 = 0ull;
#pragma unroll
            for (int i = 0; i < 8; i++) {
                ulonglong2 k0v = kp[2 * i];
                ulonglong2 k1v = kp[2 * i + 1];
                s0 = fma2(qp[4 * i + 0], k0v.x, s0);
                s1 = fma2(qp[4 * i + 1], k0v.y, s1);
                s2 = fma2(qp[4 * i + 2], k1v.x, s2);
                s3 = fma2(qp[4 * i + 3], k1v.y, s3);
            }
            float a0, a1, b0, b1, c0, c1, d0, d1;
            unpack2(s0, a0, a1); unpack2(s1, b0, b1);
            unpack2(s2, c0, c1); unpack2(s3, d0, d1);
            float s = ((a0 + a1) + (b0 + b1)) + ((c0 + c1) + (d0 + d1));
            if (s > m) {
                float corr = __expf(m - s);
                l *= corr;
                u64 cc = pack2(corr, corr);
#pragma unroll
                for (int i = 0; i < 32; i++) accp[i] = mul2(accp[i], cc);
                m = s;
            }
            float p = __expf(s - m);
            l += p;
            u64 pp = pack2(p, p);
            const ulonglong2* vp = (const ulonglong2*)&Vs[j][0];
#pragma unroll
            for (int i = 0; i < 16; i++) {
                ulonglong2 vv = vp[i];
                accp[2 * i + 0] = fma2(pp, vv.x, accp[2 * i + 0]);
                accp[2 * i + 1] = fma2(pp, vv.y, accp[2 * i + 1]);
            }
        }
    }
    float inv = 1.f / l;
    size_t ooff = ((size_t)(b * Ss + qi)) * QD + h * HDd;
#pragma unroll
    for (int i = 0; i < 32; i++) {
        float v0, v1;
        unpack2(accp[i], v0, v1);
        v0 *= inv; v1 *= inv;
        __half h0 = __float2half_rn(v0);
        __half h1 = __float2half_rn(v1);
        ohi[ooff + 2 * i]     = h0;
        ohi[ooff + 2 * i + 1] = h1;
        olo[ooff + 2 * i]     = __float2half_rn(v0 - __half2float(h0));
        olo[ooff + 2 * i + 1] = __float2half_rn(v1 - __half2float(h1));
    }
}

// ---------------------------------------------------------------------------
// Router + compacted slot assignment
// ---------------------------------------------------------------------------
__global__ void zero_cnt_kernel() {
    if (threadIdx.x < Ee) g_cnt[threadIdx.x] = 0;
}

__global__ void router_kernel(const float* __restrict__ y,
                              const float* __restrict__ rw) {
    int t = (blockIdx.x * blockDim.x + threadIdx.x) >> 5;
    int lane = threadIdx.x & 31;
    if (t >= NT) return;
    const float* yrow = y + (size_t)t * Dd;
    float logits[8] = {};
    for (int i = 0; i < 32; i++) {
        int d = i * 32 + lane;
        float yv = yrow[d];
#pragma unroll
        for (int e = 0; e < 8; e++) logits[e] += yv * rw[d * 8 + e];
    }
#pragma unroll
    for (int e = 0; e < 8; e++) {
#pragma unroll
        for (int o = 16; o > 0; o >>= 1)
            logits[e] += __shfl_xor_sync(0xffffffffu, logits[e], o);
    }
    if (lane == 0) {
        int i0 = 0; float v0 = logits[0];
#pragma unroll
        for (int e = 1; e < 8; e++) if (logits[e] > v0) { v0 = logits[e]; i0 = e; }
        int i1 = -1; float v1 = -1e30f;
#pragma unroll
        for (int e = 0; e < 8; e++)
            if (e != i0 && logits[e] > v1) { v1 = logits[e]; i1 = e; }
        float e1 = __expf(v1 - v0);
        g_texp[t * 2 + 0] = i0;
        g_texp[t * 2 + 1] = i1;
        g_gw[t * 2 + 0] = 1.f / (1.f + e1);
        g_gw[t * 2 + 1] = e1 / (1.f + e1);
        atomicAdd(&g_cnt[i0], 1);
        atomicAdd(&g_cnt[i1], 1);
    }
}

__global__ void offsets_kernel() {
    if (threadIdx.x == 0) {
        int a = 0;
        for (int e = 0; e < Ee; e++) { g_off[e] = a; a += g_cnt[e]; g_fill[e] = 0; }
    }
}

__global__ void scatter_kernel() {
    int t = blockIdx.x * blockDim.x + threadIdx.x;
    if (t >= NT) return;
#pragma unroll
    for (int j = 0; j < 2; j++) {
        int e = g_texp[t * 2 + j];
        int p = atomicAdd(&g_fill[e], 1);
        int slot = g_off[e] + p;
        g_list[slot] = t;
        g_slot[t * 2 + j] = slot;
    }
}

// ---------------------------------------------------------------------------
// he = silu(gate) * up, split to fp16 hi/lo. Slots are compact [0, NSLOT).
// ---------------------------------------------------------------------------
__global__ void silu_split_kernel() {
    size_t off = (size_t)blockIdx.x * Ff + blockIdx.y * 256 + threadIdx.x;
    float g = g_ga[off], u = g_ua[off];
    float v = (g / (1.f + __expf(-g))) * u;
    __half hi = __float2half_rn(v);
    g_hehi[off] = hi;
    g_helo[off] = __float2half_rn(v - __half2float(hi));
}

// ---------------------------------------------------------------------------
// out = h + w0 * down[slot0] + w1 * down[slot1]
// ---------------------------------------------------------------------------
__global__ void combine_kernel(float* __restrict__ out) {
    int t = blockIdx.x;
    int d = blockIdx.y * 256 + threadIdx.x;
    int s0 = g_slot[t * 2], s1 = g_slot[t * 2 + 1];
    float w0 = g_gw[t * 2], w1 = g_gw[t * 2 + 1];
    size_t o = (size_t)t * Dd + d;
    out[o] = g_h[o] + w0 * g_dn[(size_t)s0 * Dd + d]
                    + w1 * g_dn[(size_t)s1 * Dd + d];
}

// ---------------------------------------------------------------------------
// Launch
// ---------------------------------------------------------------------------
extern "C" void kernel_launch(void* const* d_in, const int* in_sizes, int n_in,
                              void* d_out, int out_size) {
    const float* input  = (const float*)d_in[0];
    const float* cosb   = (const float*)d_in[1];
    const float* sinb   = (const float*)d_in[2];
    // d_in[3] = mask (causal, unused)
    const float* w_attn = (const float*)d_in[4];
    const float* w_moe  = (const float*)d_in[5];
    const float* Wq     = (const float*)d_in[6];
    const float* Wk     = (const float*)d_in[7];
    const float* Wv     = (const float*)d_in[8];
    const float* Wo     = (const float*)d_in[9];
    const float* rw     = (const float*)d_in[10];
    const float* Wg     = (const float*)d_in[11];
    const float* Wu     = (const float*)d_in[12];
    const float* Wd     = (const float*)d_in[13];

    cudaFuncSetAttribute(mma_gemm, cudaFuncAttributeMaxDynamicSharedMemorySize, GSMEM);

    float *pq, *pk, *pvs, *pks, *ph, *py, *pga, *pua, *pdn;
    cudaGetSymbolAddress((void**)&pq,  g_q);
    cudaGetSymbolAddress((void**)&pk,  g_k);
    cudaGetSymbolAddress((void**)&pvs, g_vscr);
    cudaGetSymbolAddress((void**)&pks, g_kscr);
    cudaGetSymbolAddress((void**)&ph,  g_h);
    cudaGetSymbolAddress((void**)&py,  g_y);
    cudaGetSymbolAddress((void**)&pga, g_ga);
    cudaGetSymbolAddress((void**)&pua, g_ua);
    cudaGetSymbolAddress((void**)&pdn, g_dn);

    __half *xhi, *xlo, *ahi, *alo, *yhi, *ylo, *hehi, *helo;
    __half *wq, *wk, *wv, *wo, *wg, *wu, *wd;
    cudaGetSymbolAddress((void**)&xhi, g_xhi);  cudaGetSymbolAddress((void**)&xlo, g_xlo);
    cudaGetSymbolAddress((void**)&ahi, g_ahi);  cudaGetSymbolAddress((void**)&alo, g_alo);
    cudaGetSymbolAddress((void**)&yhi, g_yhi);  cudaGetSymbolAddress((void**)&ylo, g_ylo);
    cudaGetSymbolAddress((void**)&hehi, g_hehi); cudaGetSymbolAddress((void**)&helo, g_helo);
    cudaGetSymbolAddress((void**)&wq, g_wq);
    cudaGetSymbolAddress((void**)&wk, g_wk);
    cudaGetSymbolAddress((void**)&wv, g_wv);
    cudaGetSymbolAddress((void**)&wo, g_wo);
    cudaGetSymbolAddress((void**)&wg, g_wg);
    cudaGetSymbolAddress((void**)&wu, g_wu);
    cudaGetSymbolAddress((void**)&wd, g_wd);

    float* out = (float*)d_out;
    size_t need = (size_t)NT * Dd + 2 * (size_t)NT * KD;
    bool full = ((size_t)out_size >= need);
    float* outk = full ? (out + (size_t)NT * Dd) : pks;
    float* outv = full ? (out + (size_t)NT * Dd + (size_t)NT * KD) : pvs;

    dim3 tb(32, 8);
    // weight transposes (fp16, [N,K])
    transpose_half_kernel<<<dim3(QD / 32, Dd / 32, 1),  tb>>>(Wq, wq, Dd, QD);
    transpose_half_kernel<<<dim3(KD / 32, Dd / 32, 1),  tb>>>(Wk, wk, Dd, KD);
    transpose_half_kernel<<<dim3(KD / 32, Dd / 32, 1),  tb>>>(Wv, wv, Dd, KD);
    transpose_half_kernel<<<dim3(Dd / 32, QD / 32, 1),  tb>>>(Wo, wo, QD, Dd);
    transpose_half_kernel<<<dim3(Ff / 32, Dd / 32, Ee), tb>>>(Wg, wg, Dd, Ff);
    transpose_half_kernel<<<dim3(Ff / 32, Dd / 32, Ee), tb>>>(Wu, wu, Dd, Ff);
    transpose_half_kernel<<<dim3(Dd / 32, Ff / 32, Ee), tb>>>(Wd, wd, Ff, Dd);

    // 1. x = rmsnorm(input) -> split
    rmsnorm_split_kernel<<<NT, 256>>>(input, w_attn, xhi, xlo, nullptr);
    // 2. q/k/v projections
    mma_gemm<<<dim3(QD / 128, NT / 128, 1), 256, GSMEM>>>(
        xhi, xlo, wq, 0, pq, nullptr, 0, NT, QD, Dd);
    mma_gemm<<<dim3(KD / 128, NT / 128, 1), 256, GSMEM>>>(
        xhi, xlo, wk, 0, pk, nullptr, 0, NT, KD, Dd);
    mma_gemm<<<dim3(KD / 128, NT / 128, 1), 256, GSMEM>>>(
        xhi, xlo, wv, 0, outv, nullptr, 0, NT, KD, Dd);
    // 3. RoPE
    rope_kernel<<<NT, 256>>>(cosb, sinb, pq, pk, outk);
    // 4. attention -> split output
    attn_kernel<<<dim3(Ss / 128, Hh, Bb), 128>>>(pq, pk, outv, ahi, alo);
    // 5. h = input + attn @ Wo
    mma_gemm<<<dim3(Dd / 128, NT / 128, 1), 256, GSMEM>>>(
        ahi, alo, wo, 0, ph, input, 0, NT, Dd, QD);
    // 6. y = rmsnorm(h) -> split + f32
    rmsnorm_split_kernel<<<NT, 256>>>(ph, w_moe, yhi, ylo, py);
    // 7. router + compact slots
    zero_cnt_kernel<<<1, 32>>>();
    router_kernel<<<NT / 8, 256>>>(py, rw);
    offsets_kernel<<<1, 32>>>();
    scatter_kernel<<<NT / 256, 256>>>();
    // 8. expert gate / up GEMMs (gathered A rows)
    mma_gemm<<<dim3(Ff / 128, NT / 128, Ee), 256, GSMEM>>>(
        yhi, ylo, wg, (size_t)Ff * Dd, pga, nullptr, 1, NT, Ff, Dd);
    mma_gemm<<<dim3(Ff / 128, NT / 128, Ee), 256, GSMEM>>>(
        yhi, ylo, wu, (size_t)Ff * Dd, pua, nullptr, 1, NT, Ff, Dd);
    // 9. he = silu(gate) * up -> split
    silu_split_kernel<<<dim3(NSLOT, Ff / 256), 256>>>();
    // 10. down projection (contiguous slot rows)
    mma_gemm<<<dim3(Dd / 128, NT / 128, Ee), 256, GSMEM>>>(
        hehi, helo, wd, (size_t)Dd * Ff, pdn, nullptr, 2, NT, Dd, Ff);
    // 11. combine
    combine_kernel<<<dim3(NT, Dd / 256), 256>>>(out);
}

// round 10
// speedup vs baseline: 3.8129x; 2.1961x over previous
#include <cuda_runtime.h>
#include <cuda_fp16.h>
#include <cstdint>

// ---------------------------------------------------------------------------
// MoE transformer block. Split-fp16 warp-MMA GEMMs + FA2-style MMA attention.
// B=4 S=2048 D=1024 H=16 KV=4 HD=64 E=8 K(top)=2 F=1024
// Base sm_103 PTX only: mma.sync / ldmatrix / cp.async.
// ---------------------------------------------------------------------------

namespace {
constexpr int Bb  = 4;
constexpr int Ss  = 2048;
constexpr int Dd  = 1024;
constexpr int Hh  = 16;
constexpr int KVh = 4;
constexpr int HDd = 64;
constexpr int Ee  = 8;
constexpr int TKk = 2;
constexpr int Ff  = 1024;
constexpr int NT  = Bb * Ss;        // 8192 tokens
constexpr int QD  = Hh * HDd;       // 1024
constexpr int KD  = KVh * HDd;      // 256
constexpr int NSLOT = NT * TKk;     // 16384 expert slots

// GEMM tiling
constexpr int ROWB  = 80;                 // smem row stride bytes (32 fp16 + pad)
constexpr int TILEB = 128 * ROWB;         // one 128x32 fp16 tile = 10240 B
constexpr int STAGE = 3 * TILEB;          // AH, AL, BH
constexpr int GSMEM = 2 * STAGE;          // 61440 B double-buffered

// Attention smem: K/V tiles 64 rows x 64 halves, 144B row stride
constexpr int AROW   = 144;
constexpr int ATILE  = 64 * AROW;         // 9216 B
constexpr int ASTAGE = 2 * ATILE;         // K + V = 18432 B
constexpr int ASMEM  = 2 * ASTAGE;        // 36864 B (also fits Q hi/lo staging)
}

__device__ __forceinline__ uint32_t smem_u32(const void* p) {
    uint32_t a;
    asm("{ .reg .u64 t; cvta.to.shared.u64 t, %1; cvt.u32.u64 %0, t; }" : "=r"(a) : "l"(p));
    return a;
}
#define CP16(dst, src) asm volatile( \
    "cp.async.cg.shared.global [%0], [%1], 16;" :: "r"(dst), "l"(src))
#define CP_COMMIT() asm volatile("cp.async.commit_group;" ::: "memory")
#define CP_WAIT(n)  asm volatile("cp.async.wait_group %0;" :: "n"(n) : "memory")

__device__ __forceinline__ void ldsm_x4(uint32_t* r, uint32_t addr) {
    asm volatile("ldmatrix.sync.aligned.m8n8.x4.shared.b16 {%0,%1,%2,%3}, [%4];"
                 : "=r"(r[0]), "=r"(r[1]), "=r"(r[2]), "=r"(r[3]) : "r"(addr));
}
__device__ __forceinline__ void ldsm_x4_t(uint32_t* r, uint32_t addr) {
    asm volatile("ldmatrix.sync.aligned.m8n8.x4.trans.shared.b16 {%0,%1,%2,%3}, [%4];"
                 : "=r"(r[0]), "=r"(r[1]), "=r"(r[2]), "=r"(r[3]) : "r"(addr));
}
__device__ __forceinline__ void mma_fp16(float* c, const uint32_t* a, const uint32_t* b) {
    asm volatile(
        "mma.sync.aligned.m16n8k16.row.col.f32.f16.f16.f32 "
        "{%0,%1,%2,%3}, {%4,%5,%6,%7}, {%8,%9}, {%0,%1,%2,%3};"
        : "+f"(c[0]), "+f"(c[1]), "+f"(c[2]), "+f"(c[3])
        : "r"(a[0]), "r"(a[1]), "r"(a[2]), "r"(a[3]), "r"(b[0]), "r"(b[1]));
}
__device__ __forceinline__ uint32_t packh2(float a, float b) {
    __half2 h = __floats2half2_rn(a, b);
    return *reinterpret_cast<uint32_t*>(&h);
}

// ---------------------------------------------------------------------------
// Scratch (device globals; no runtime allocation)
// ---------------------------------------------------------------------------
__device__ __align__(128) float g_q[(size_t)NT * QD];
__device__ __align__(128) float g_k[(size_t)NT * KD];
__device__ __align__(128) float g_vscr[(size_t)NT * KD];
__device__ __align__(128) float g_kscr[(size_t)NT * KD];
__device__ __align__(128) float g_h[(size_t)NT * Dd];
__device__ __align__(128) float g_y[(size_t)NT * Dd];
__device__ __align__(128) float g_ga[(size_t)NSLOT * Ff];
__device__ __align__(128) float g_ua[(size_t)NSLOT * Ff];
__device__ __align__(128) float g_dn[(size_t)NSLOT * Dd];

__device__ __align__(128) __half g_xhi[(size_t)NT * Dd], g_xlo[(size_t)NT * Dd];
__device__ __align__(128) __half g_ahi[(size_t)NT * QD], g_alo[(size_t)NT * QD];
__device__ __align__(128) __half g_yhi[(size_t)NT * Dd], g_ylo[(size_t)NT * Dd];
__device__ __align__(128) __half g_hehi[(size_t)NSLOT * Ff], g_helo[(size_t)NSLOT * Ff];

// fp16 q (hi/lo, pre-scaled 1/8) and k/v for attention
__device__ __align__(128) __half g_qh2[(size_t)NT * QD], g_ql2[(size_t)NT * QD];
__device__ __align__(128) __half g_kh2[(size_t)NT * KD];
__device__ __align__(128) __half g_vh2[(size_t)NT * KD];

// transposed fp16 weights [N, K]
__device__ __align__(128) __half g_wq[(size_t)QD * Dd];
__device__ __align__(128) __half g_wk[(size_t)KD * Dd];
__device__ __align__(128) __half g_wv[(size_t)KD * Dd];
__device__ __align__(128) __half g_wo[(size_t)Dd * QD];
__device__ __align__(128) __half g_wg[(size_t)Ee * Ff * Dd];
__device__ __align__(128) __half g_wu[(size_t)Ee * Ff * Dd];
__device__ __align__(128) __half g_wd[(size_t)Ee * Dd * Ff];

__device__ int   g_cnt[Ee];
__device__ int   g_off[Ee];
__device__ int   g_fill[Ee];
__device__ int   g_list[NSLOT];
__device__ int   g_slot[NSLOT];
__device__ int   g_texp[NSLOT];
__device__ float g_gw[NSLOT];

// ---------------------------------------------------------------------------
// RMSNorm with fp16 hi/lo split output (+ optional f32 output)
// ---------------------------------------------------------------------------
__global__ void rmsnorm_split_kernel(const float* __restrict__ in,
                                     const float* __restrict__ w,
                                     __half* __restrict__ ohi,
                                     __half* __restrict__ olo,
                                     float* __restrict__ of32) {
    int t = blockIdx.x;
    const float* row = in + (size_t)t * Dd;
    float ss = 0.f;
#pragma unroll
    for (int i = 0; i < 4; i++) { float v = row[threadIdx.x + i * 256]; ss += v * v; }
#pragma unroll
    for (int o = 16; o > 0; o >>= 1) ss += __shfl_xor_sync(0xffffffffu, ss, o);
    __shared__ float sred[8];
    if ((threadIdx.x & 31) == 0) sred[threadIdx.x >> 5] = ss;
    __syncthreads();
    if (threadIdx.x < 32) {
        float v = (threadIdx.x < 8) ? sred[threadIdx.x] : 0.f;
#pragma unroll
        for (int o = 4; o > 0; o >>= 1) v += __shfl_xor_sync(0xffffffffu, v, o);
        if (threadIdx.x == 0) sred[0] = v;
    }
    __syncthreads();
    float inv = rsqrtf(sred[0] * (1.f / Dd) + 1e-6f);
    size_t base = (size_t)t * Dd;
#pragma unroll
    for (int i = 0; i < 4; i++) {
        int d = threadIdx.x + i * 256;
        float r = row[d] * inv * w[d];
        __half hi = __float2half_rn(r);
        float lo = r - __half2float(hi);
        ohi[base + d] = hi;
        olo[base + d] = __float2half_rn(lo);
        if (of32) of32[base + d] = r;
    }
}

// ---------------------------------------------------------------------------
// Transpose: W[K,N] fp32 -> T[N,K] fp16. Block (32,8).
// ---------------------------------------------------------------------------
__global__ void transpose_half_kernel(const float* __restrict__ W,
                                      __half* __restrict__ T,
                                      int K, int N) {
    __shared__ float tile[32][33];
    size_t zb = (size_t)blockIdx.z * K * N;
    int k0 = blockIdx.y * 32, n0 = blockIdx.x * 32;
    int tx = threadIdx.x, ty = threadIdx.y;
#pragma unroll
    for (int j = 0; j < 4; j++)
        tile[ty + 8 * j][tx] = W[zb + (size_t)(k0 + ty + 8 * j) * N + n0 + tx];
    __syncthreads();
#pragma unroll
    for (int j = 0; j < 4; j++) {
        float v = tile[tx][ty + 8 * j];
        T[zb + (size_t)(n0 + ty + 8 * j) * K + k0 + tx] = __float2half_rn(v);
    }
}

// ---------------------------------------------------------------------------
// Warp-MMA GEMM: C[M,N] = Ahi@B + Alo@B (fp32 accum)  [unchanged from R9]
// ---------------------------------------------------------------------------
__global__ void __launch_bounds__(256, 1)
mma_gemm(const __half* __restrict__ Ahi, const __half* __restrict__ Alo,
         const __half* __restrict__ Bw,
         size_t bz,
         float* __restrict__ C,
         const float* __restrict__ addsrc,
         int mode, int M, int N, int K) {
    extern __shared__ char smem[];
    int z = blockIdx.z;
    int Meff = M, off = 0;
    if (mode) { Meff = g_cnt[z]; off = g_off[z]; }
    int m0 = blockIdx.y * 128;
    if (m0 >= Meff) return;
    int n0 = blockIdx.x * 128;
    const __half* bw = Bw + bz * z;

    int tid = threadIdx.x, lane = tid & 31, wid = tid >> 5;
    uint32_t sb = smem_u32(smem);

    int lrow = tid >> 1;
    int lcolh = (tid & 1) * 16;
    int ar = m0 + lrow;
    long grow;
    if (mode == 1) { int rr = (ar < Meff) ? ar : (Meff - 1); grow = g_list[off + rr]; }
    else if (mode == 2) { int rr = (ar < Meff) ? ar : (Meff - 1); grow = off + rr; }
    else grow = ar;
    const __half* pAH = Ahi + (size_t)grow * K + lcolh;
    const __half* pAL = Alo + (size_t)grow * K + lcolh;
    const __half* pBH = bw + (size_t)(n0 + lrow) * K + lcolh;
    uint32_t dstrel = (uint32_t)(lrow * ROWB + lcolh * 2);

    float acc[4][4][4];
#pragma unroll
    for (int i = 0; i < 4; i++)
#pragma unroll
        for (int j = 0; j < 4; j++)
#pragma unroll
            for (int q = 0; q < 4; q++) acc[i][j][q] = 0.f;

    const int NS = K / 32;
    {
        uint32_t d = sb + dstrel;
        CP16(d + 0 * TILEB,      pAH); CP16(d + 0 * TILEB + 16, pAH + 8);
        CP16(d + 1 * TILEB,      pAL); CP16(d + 1 * TILEB + 16, pAL + 8);
        CP16(d + 2 * TILEB,      pBH); CP16(d + 2 * TILEB + 16, pBH + 8);
        CP_COMMIT();
    }

    uint32_t a_rel = (uint32_t)(((wid & 1) * 64 + (lane & 15)) * ROWB + (lane >> 4) * 16);
    uint32_t b_rel = (uint32_t)(2 * TILEB +
        ((wid >> 1) * 32 + (lane & 7) + ((lane >> 4) & 1) * 8) * ROWB +
        ((lane >> 3) & 1) * 16);

    for (int s = 0; s < NS; s++) {
        if (s + 1 < NS) {
            size_t ko = (size_t)(s + 1) * 32;
            uint32_t d = sb + ((s + 1) & 1) * STAGE + dstrel;
            CP16(d + 0 * TILEB,      pAH + ko); CP16(d + 0 * TILEB + 16, pAH + ko + 8);
            CP16(d + 1 * TILEB,      pAL + ko); CP16(d + 1 * TILEB + 16, pAL + ko + 8);
            CP16(d + 2 * TILEB,      pBH + ko); CP16(d + 2 * TILEB + 16, pBH + ko + 8);
            CP_COMMIT();
            CP_WAIT(1);
        } else {
            CP_WAIT(0);
        }
        __syncthreads();
        uint32_t base = sb + (s & 1) * STAGE;
#pragma unroll
        for (int kh = 0; kh < 2; kh++) {
            uint32_t koffb = kh * 32;
            uint32_t ah[4][4], al[4][4];
            uint32_t aaddr = base + a_rel + koffb;
#pragma unroll
            for (int mi = 0; mi < 4; mi++) {
                ldsm_x4(ah[mi], aaddr + mi * 16 * ROWB);
                ldsm_x4(al[mi], aaddr + mi * 16 * ROWB + TILEB);
            }
            uint32_t bh[4][2];
            uint32_t baddr = base + b_rel + koffb;
#pragma unroll
            for (int hf = 0; hf < 2; hf++) {
                uint32_t t4[4];
                ldsm_x4(t4, baddr + hf * 16 * ROWB);
                bh[2 * hf][0] = t4[0]; bh[2 * hf][1] = t4[1];
                bh[2 * hf + 1][0] = t4[2]; bh[2 * hf + 1][1] = t4[3];
            }
#pragma unroll
            for (int mi = 0; mi < 4; mi++)
#pragma unroll
                for (int ni = 0; ni < 4; ni++) {
                    mma_fp16(acc[mi][ni], ah[mi], bh[ni]);
                    mma_fp16(acc[mi][ni], al[mi], bh[ni]);
                }
        }
        __syncthreads();
    }

    int mW = m0 + (wid & 1) * 64;
    int nW = n0 + (wid >> 1) * 32;
#pragma unroll
    for (int mi = 0; mi < 4; mi++) {
#pragma unroll
        for (int hf = 0; hf < 2; hf++) {
            int r = mW + mi * 16 + hf * 8 + (lane >> 2);
            if (r >= Meff) continue;
            int crow = mode ? (off + r) : r;
#pragma unroll
            for (int ni = 0; ni < 4; ni++) {
                int c = nW + ni * 8 + (lane & 3) * 2;
                size_t co = (size_t)crow * N + c;
                float v0 = acc[mi][ni][2 * hf + 0];
                float v1 = acc[mi][ni][2 * hf + 1];
                if (addsrc) {
                    v0 += addsrc[co];
                    v1 += addsrc[co + 1];
                }
                float2 v = {v0, v1};
                *(float2*)(C + co) = v;
            }
        }
    }
}

// ---------------------------------------------------------------------------
// RoPE: rotate q/k; emit q as fp16 hi/lo (pre-scaled 1/8), k as fp32 output +
// fp16, v converted to fp16.
// ---------------------------------------------------------------------------
__global__ void rope_kernel(const float* __restrict__ cosb,
                            const float* __restrict__ sinb,
                            const float* __restrict__ q,
                            const float* __restrict__ k,
                            float* __restrict__ outk,
                            const float* __restrict__ vin,
                            __half* __restrict__ qh, __half* __restrict__ ql,
                            __half* __restrict__ kh, __half* __restrict__ vh) {
    int t = blockIdx.x;
    int s = t % Ss;
    const float* cs = cosb + (size_t)s * HDd;
    const float* sn = sinb + (size_t)s * HDd;

    const float* qrow = q + (size_t)t * QD;
    for (int idx = threadIdx.x; idx < Hh * 32; idx += blockDim.x) {
        int hh = idx >> 5, d = idx & 31;
        float a = qrow[hh * HDd + d], b2 = qrow[hh * HDd + d + 32];
        float o1 = (a * cs[d] - b2 * sn[d]) * 0.125f;
        float o2 = (b2 * cs[d + 32] + a * sn[d + 32]) * 0.125f;
        size_t base = (size_t)t * QD + hh * HDd;
        __half h1 = __float2half_rn(o1);
        __half h2 = __float2half_rn(o2);
        qh[base + d] = h1;      ql[base + d] = __float2half_rn(o1 - __half2float(h1));
        qh[base + d + 32] = h2; ql[base + d + 32] = __float2half_rn(o2 - __half2float(h2));
    }
    const float* krow = k + (size_t)t * KD;
    for (int idx = threadIdx.x; idx < KVh * 32; idx += blockDim.x) {
        int hh = idx >> 5, d = idx & 31;
        float a = krow[hh * HDd + d], b2 = krow[hh * HDd + d + 32];
        float o1 = a * cs[d] - b2 * sn[d];
        float o2 = b2 * cs[d + 32] + a * sn[d + 32];
        size_t base = (size_t)t * KD + hh * HDd;
        outk[base + d] = o1;      outk[base + d + 32] = o2;
        kh[base + d] = __float2half_rn(o1);
        kh[base + d + 32] = __float2half_rn(o2);
    }
    for (int idx = threadIdx.x; idx < KD; idx += blockDim.x) {
        vh[(size_t)t * KD + idx] = __float2half_rn(vin[(size_t)t * KD + idx]);
    }
}

// ---------------------------------------------------------------------------
// FA2-style causal GQA attention on mma.sync.
// Block = 128 q rows of one (b,h); 8 warps x 16 rows. 64-key tiles.
// Q fp16 2-term (hi/lo, pre-scaled); K/V/P fp16 single; fp32 softmax state.
// ---------------------------------------------------------------------------
__global__ void __launch_bounds__(256, 1)
attn_mma_kernel(const __half* __restrict__ qh, const __half* __restrict__ ql,
                const __half* __restrict__ kh, const __half* __restrict__ vh,
                __half* __restrict__ ohi, __half* __restrict__ olo) {
    extern __shared__ char smem[];
    int b = blockIdx.z, h = blockIdx.y, qt = blockIdx.x;
    int kvh = h >> 2;
    int tid = threadIdx.x, lane = tid & 31, wid = tid >> 5;
    int qrow0 = qt * 128;
    uint32_t sb = smem_u32(smem);

    // ---- stage Q hi/lo (128 rows x 64 halves, stride AROW)
    {
        const __half* qsh = qh + ((size_t)(b * Ss + qrow0)) * QD + h * HDd;
        const __half* qsl = ql + ((size_t)(b * Ss + qrow0)) * QD + h * HDd;
#pragma unroll
        for (int i = 0; i < 4; i++) {
            int c = tid + 256 * i;       // 1024 chunks over 128 rows
            int row = c >> 3, u = c & 7;
            CP16(sb + row * AROW + u * 16, qsh + (size_t)row * QD + u * 8);
            CP16(sb + ASTAGE + row * AROW + u * 16, qsl + (size_t)row * QD + u * 8);
        }
        CP_COMMIT(); CP_WAIT(0);
    }
    __syncthreads();

    int wr = wid * 16;
    uint32_t qfh[4][4], qfl[4][4];
    {
        uint32_t qa = sb + (wr + (lane & 15)) * AROW + (lane >> 4) * 16;
#pragma unroll
        for (int kc = 0; kc < 4; kc++) {
            ldsm_x4(qfh[kc], qa + kc * 32);
            ldsm_x4(qfl[kc], qa + kc * 32 + ASTAGE);
        }
    }
    __syncthreads();

    float o[8][4];
#pragma unroll
    for (int i = 0; i < 8; i++)
#pragma unroll
        for (int j = 0; j < 4; j++) o[i][j] = 0.f;
    float m0 = -1e30f, m1 = -1e30f, l0 = 0.f, l1 = 0.f;

    const __half* kbase = kh + ((size_t)(b * Ss)) * KD + kvh * HDd;
    const __half* vbase = vh + ((size_t)(b * Ss)) * KD + kvh * HDd;

    int ntiles = (qt + 1) * 2;
    // stage tile 0 into buf 0
    {
#pragma unroll
        for (int i = 0; i < 2; i++) {
            int c = tid + 256 * i;       // 512 chunks over 64 rows
            int row = c >> 3, u = c & 7;
            CP16(sb + row * AROW + u * 16, kbase + (size_t)row * KD + u * 8);
            CP16(sb + ATILE + row * AROW + u * 16, vbase + (size_t)row * KD + u * 8);
        }
        CP_COMMIT();
    }

    for (int t = 0; t < ntiles; t++) {
        int k0 = t * 64;
        if (t + 1 < ntiles) {
            uint32_t dbuf = sb + ((t + 1) & 1) * ASTAGE;
            const __half* kb = kbase + (size_t)(k0 + 64) * KD;
            const __half* vb = vbase + (size_t)(k0 + 64) * KD;
#pragma unroll
            for (int i = 0; i < 2; i++) {
                int c = tid + 256 * i;
                int row = c >> 3, u = c & 7;
                CP16(dbuf + row * AROW + u * 16, kb + (size_t)row * KD + u * 8);
                CP16(dbuf + ATILE + row * AROW + u * 16, vb + (size_t)row * KD + u * 8);
            }
            CP_COMMIT(); CP_WAIT(1);
        } else {
            CP_WAIT(0);
        }
        __syncthreads();
        uint32_t kb0 = sb + (t & 1) * ASTAGE;
        uint32_t vb0 = kb0 + ATILE;

        // ---- S = Q @ K^T
        float s[8][4];
#pragma unroll
        for (int nc16 = 0; nc16 < 4; nc16++) {
            uint32_t bk[4][4];
            uint32_t baddr = kb0 + (nc16 * 16 + (lane & 7) + ((lane >> 4) & 1) * 8) * AROW
                           + ((lane >> 3) & 1) * 16;
#pragma unroll
            for (int kc = 0; kc < 4; kc++) ldsm_x4(bk[kc], baddr + kc * 32);
#pragma unroll
            for (int j = 0; j < 2; j++) {
                int nc = nc16 * 2 + j;
                s[nc][0] = s[nc][1] = s[nc][2] = s[nc][3] = 0.f;
#pragma unroll
                for (int kc = 0; kc < 4; kc++) {
                    mma_fp16(s[nc], qfh[kc], &bk[kc][2 * j]);
                    mma_fp16(s[nc], qfl[kc], &bk[kc][2 * j]);
                }
            }
        }
        // ---- causal mask
        if (k0 + 63 > qrow0 + wr) {
            int row0 = qrow0 + wr + (lane >> 2);
            int colb = k0 + (lane & 3) * 2;
#pragma unroll
            for (int nc = 0; nc < 8; nc++) {
                int c0 = colb + nc * 8, c1 = c0 + 1;
                if (c0 > row0)     s[nc][0] = -1e9f;
                if (c1 > row0)     s[nc][1] = -1e9f;
                if (c0 > row0 + 8) s[nc][2] = -1e9f;
                if (c1 > row0 + 8) s[nc][3] = -1e9f;
            }
        }
        // ---- online softmax (per 2 rows held by this thread's quad)
        float mx0 = -1e30f, mx1 = -1e30f;
#pragma unroll
        for (int nc = 0; nc < 8; nc++) {
            mx0 = fmaxf(mx0, fmaxf(s[nc][0], s[nc][1]));
            mx1 = fmaxf(mx1, fmaxf(s[nc][2], s[nc][3]));
        }
        mx0 = fmaxf(mx0, __shfl_xor_sync(0xffffffffu, mx0, 1));
        mx0 = fmaxf(mx0, __shfl_xor_sync(0xffffffffu, mx0, 2));
        mx1 = fmaxf(mx1, __shfl_xor_sync(0xffffffffu, mx1, 1));
        mx1 = fmaxf(mx1, __shfl_xor_sync(0xffffffffu, mx1, 2));
        float mn0 = fmaxf(m0, mx0), mn1 = fmaxf(m1, mx1);
        float cr0 = __expf(m0 - mn0), cr1 = __expf(m1 - mn1);
        m0 = mn0; m1 = mn1;
        float sum0 = 0.f, sum1 = 0.f;
#pragma unroll
        for (int nc = 0; nc < 8; nc++) {
            s[nc][0] = __expf(s[nc][0] - m0);
            s[nc][1] = __expf(s[nc][1] - m0);
            s[nc][2] = __expf(s[nc][2] - m1);
            s[nc][3] = __expf(s[nc][3] - m1);
            sum0 += s[nc][0] + s[nc][1];
            sum1 += s[nc][2] + s[nc][3];
        }
        sum0 += __shfl_xor_sync(0xffffffffu, sum0, 1);
        sum0 += __shfl_xor_sync(0xffffffffu, sum0, 2);
        sum1 += __shfl_xor_sync(0xffffffffu, sum1, 1);
        sum1 += __shfl_xor_sync(0xffffffffu, sum1, 2);
        l0 = l0 * cr0 + sum0;
        l1 = l1 * cr1 + sum1;
#pragma unroll
        for (int nc = 0; nc < 8; nc++) {
            o[nc][0] *= cr0; o[nc][1] *= cr0;
            o[nc][2] *= cr1; o[nc][3] *= cr1;
        }
        // ---- pack P into A fragments
        uint32_t pa[4][4];
#pragma unroll
        for (int kc = 0; kc < 4; kc++) {
            pa[kc][0] = packh2(s[2 * kc][0],     s[2 * kc][1]);
            pa[kc][1] = packh2(s[2 * kc][2],     s[2 * kc][3]);
            pa[kc][2] = packh2(s[2 * kc + 1][0], s[2 * kc + 1][1]);
            pa[kc][3] = packh2(s[2 * kc + 1][2], s[2 * kc + 1][3]);
        }
        // ---- O += P @ V  (V via ldmatrix.trans)
#pragma unroll
        for (int kc = 0; kc < 4; kc++) {
            uint32_t baddr = vb0 + (kc * 16 + (lane & 7) + ((lane >> 3) & 1) * 8) * AROW
                           + ((lane >> 4) & 1) * 16;
#pragma unroll
            for (int n16 = 0; n16 < 4; n16++) {
                uint32_t t4[4];
                ldsm_x4_t(t4, baddr + n16 * 32);
                mma_fp16(o[n16 * 2],     pa[kc], &t4[0]);
                mma_fp16(o[n16 * 2 + 1], pa[kc], &t4[2]);
            }
        }
        __syncthreads();
    }

    // ---- epilogue
    float inv0 = 1.f / l0, inv1 = 1.f / l1;
    int row0 = qrow0 + wr + (lane >> 2);
#pragma unroll
    for (int nc = 0; nc < 8; nc++) {
        int col = h * HDd + nc * 8 + (lane & 3) * 2;
        float v0 = o[nc][0] * inv0, v1 = o[nc][1] * inv0;
        float v2 = o[nc][2] * inv1, v3 = o[nc][3] * inv1;
        size_t o0 = (size_t)(b * Ss + row0) * QD + col;
        size_t o1 = (size_t)(b * Ss + row0 + 8) * QD + col;
        __half h0 = __float2half_rn(v0), h1 = __float2half_rn(v1);
        __half h2 = __float2half_rn(v2), h3 = __float2half_rn(v3);
        *(__half2*)(ohi + o0) = __halves2half2(h0, h1);
        *(__half2*)(ohi + o1) = __halves2half2(h2, h3);
        *(__half2*)(olo + o0) = __halves2half2(
            __float2half_rn(v0 - __half2float(h0)), __float2half_rn(v1 - __half2float(h1)));
        *(__half2*)(olo + o1) = __halves2half2(
            __float2half_rn(v2 - __half2float(h2)), __float2half_rn(v3 - __half2float(h3)));
    }
}

// ---------------------------------------------------------------------------
// Router + compacted slot assignment
// ---------------------------------------------------------------------------
__global__ void zero_cnt_kernel() {
    if (threadIdx.x < Ee) g_cnt[threadIdx.x] = 0;
}

__global__ void router_kernel(const float* __restrict__ y,
                              const float* __restrict__ rw) {
    int t = (blockIdx.x * blockDim.x + threadIdx.x) >> 5;
    int lane = threadIdx.x & 31;
    if (t >= NT) return;
    const float* yrow = y + (size_t)t * Dd;
    float logits[8] = {};
    for (int i = 0; i < 32; i++) {
        int d = i * 32 + lane;
        float yv = yrow[d];
#pragma unroll
        for (int e = 0; e < 8; e++) logits[e] += yv * rw[d * 8 + e];
    }
#pragma unroll
    for (int e = 0; e < 8; e++) {
#pragma unroll
        for (int o = 16; o > 0; o >>= 1)
            logits[e] += __shfl_xor_sync(0xffffffffu, logits[e], o);
    }
    if (lane == 0) {
        int i0 = 0; float v0 = logits[0];
#pragma unroll
        for (int e = 1; e < 8; e++) if (logits[e] > v0) { v0 = logits[e]; i0 = e; }
        int i1 = -1; float v1 = -1e30f;
#pragma unroll
        for (int e = 0; e < 8; e++)
            if (e != i0 && logits[e] > v1) { v1 = logits[e]; i1 = e; }
        float e1 = __expf(v1 - v0);
        g_texp[t * 2 + 0] = i0;
        g_texp[t * 2 + 1] = i1;
        g_gw[t * 2 + 0] = 1.f / (1.f + e1);
        g_gw[t * 2 + 1] = e1 / (1.f + e1);
        atomicAdd(&g_cnt[i0], 1);
        atomicAdd(&g_cnt[i1], 1);
    }
}

__global__ void offsets_kernel() {
    if (threadIdx.x == 0) {
        int a = 0;
        for (int e = 0; e < Ee; e++) { g_off[e] = a; a += g_cnt[e]; g_fill[e] = 0; }
    }
}

__global__ void scatter_kernel() {
    int t = blockIdx.x * blockDim.x + threadIdx.x;
    if (t >= NT) return;
#pragma unroll
    for (int j = 0; j < 2; j++) {
        int e = g_texp[t * 2 + j];
        int p = atomicAdd(&g_fill[e], 1);
        int slot = g_off[e] + p;
        g_list[slot] = t;
        g_slot[t * 2 + j] = slot;
    }
}

// ---------------------------------------------------------------------------
// he = silu(gate) * up, split to fp16 hi/lo. Slots are compact [0, NSLOT).
// ---------------------------------------------------------------------------
__global__ void silu_split_kernel() {
    size_t off = (size_t)blockIdx.x * Ff + blockIdx.y * 256 + threadIdx.x;
    float g = g_ga[off], u = g_ua[off];
    float v = (g / (1.f + __expf(-g))) * u;
    __half hi = __float2half_rn(v);
    g_hehi[off] = hi;
    g_helo[off] = __float2half_rn(v - __half2float(hi));
}

// ---------------------------------------------------------------------------
// out = h + w0 * down[slot0] + w1 * down[slot1]
// ---------------------------------------------------------------------------
__global__ void combine_kernel(float* __restrict__ out) {
    int t = blockIdx.x;
    int d = blockIdx.y * 256 + threadIdx.x;
    int s0 = g_slot[t * 2], s1 = g_slot[t * 2 + 1];
    float w0 = g_gw[t * 2], w1 = g_gw[t * 2 + 1];
    size_t o = (size_t)t * Dd + d;
    out[o] = g_h[o] + w0 * g_dn[(size_t)s0 * Dd + d]
                    + w1 * g_dn[(size_t)s1 * Dd + d];
}

// ---------------------------------------------------------------------------
// Launch
// ---------------------------------------------------------------------------
extern "C" void kernel_launch(void* const* d_in, const int* in_sizes, int n_in,
                              void* d_out, int out_size) {
    const float* input  = (const float*)d_in[0];
    const float* cosb   = (const float*)d_in[1];
    const float* sinb   = (const float*)d_in[2];
    // d_in[3] = mask (causal, unused)
    const float* w_attn = (const float*)d_in[4];
    const float* w_moe  = (const float*)d_in[5];
    const float* Wq     = (const float*)d_in[6];
    const float* Wk     = (const float*)d_in[7];
    const float* Wv     = (const float*)d_in[8];
    const float* Wo     = (const float*)d_in[9];
    const float* rw     = (const float*)d_in[10];
    const float* Wg     = (const float*)d_in[11];
    const float* Wu     = (const float*)d_in[12];
    const float* Wd     = (const float*)d_in[13];

    cudaFuncSetAttribute(mma_gemm, cudaFuncAttributeMaxDynamicSharedMemorySize, GSMEM);

    float *pq, *pk, *pvs, *pks, *ph, *py, *pga, *pua, *pdn;
    cudaGetSymbolAddress((void**)&pq,  g_q);
    cudaGetSymbolAddress((void**)&pk,  g_k);
    cudaGetSymbolAddress((void**)&pvs, g_vscr);
    cudaGetSymbolAddress((void**)&pks, g_kscr);
    cudaGetSymbolAddress((void**)&ph,  g_h);
    cudaGetSymbolAddress((void**)&py,  g_y);
    cudaGetSymbolAddress((void**)&pga, g_ga);
    cudaGetSymbolAddress((void**)&pua, g_ua);
    cudaGetSymbolAddress((void**)&pdn, g_dn);

    __half *xhi, *xlo, *ahi, *alo, *yhi, *ylo, *hehi, *helo;
    __half *qh2, *ql2, *kh2, *vh2;
    __half *wq, *wk, *wv, *wo, *wg, *wu, *wd;
    cudaGetSymbolAddress((void**)&xhi, g_xhi);  cudaGetSymbolAddress((void**)&xlo, g_xlo);
    cudaGetSymbolAddress((void**)&ahi, g_ahi);  cudaGetSymbolAddress((void**)&alo, g_alo);
    cudaGetSymbolAddress((void**)&yhi, g_yhi);  cudaGetSymbolAddress((void**)&ylo, g_ylo);
    cudaGetSymbolAddress((void**)&hehi, g_hehi); cudaGetSymbolAddress((void**)&helo, g_helo);
    cudaGetSymbolAddress((void**)&qh2, g_qh2);  cudaGetSymbolAddress((void**)&ql2, g_ql2);
    cudaGetSymbolAddress((void**)&kh2, g_kh2);  cudaGetSymbolAddress((void**)&vh2, g_vh2);
    cudaGetSymbolAddress((void**)&wq, g_wq);
    cudaGetSymbolAddress((void**)&wk, g_wk);
    cudaGetSymbolAddress((void**)&wv, g_wv);
    cudaGetSymbolAddress((void**)&wo, g_wo);
    cudaGetSymbolAddress((void**)&wg, g_wg);
    cudaGetSymbolAddress((void**)&wu, g_wu);
    cudaGetSymbolAddress((void**)&wd, g_wd);

    float* out = (float*)d_out;
    size_t need = (size_t)NT * Dd + 2 * (size_t)NT * KD;
    bool full = ((size_t)out_size >= need);
    float* outk = full ? (out + (size_t)NT * Dd) : pks;
    float* outv = full ? (out + (size_t)NT * Dd + (size_t)NT * KD) : pvs;

    dim3 tb(32, 8);
    // weight transposes (fp16, [N,K])
    transpose_half_kernel<<<dim3(QD / 32, Dd / 32, 1),  tb>>>(Wq, wq, Dd, QD);
    transpose_half_kernel<<<dim3(KD / 32, Dd / 32, 1),  tb>>>(Wk, wk, Dd, KD);
    transpose_half_kernel<<<dim3(KD / 32, Dd / 32, 1),  tb>>>(Wv, wv, Dd, KD);
    transpose_half_kernel<<<dim3(Dd / 32, QD / 32, 1),  tb>>>(Wo, wo, QD, Dd);
    transpose_half_kernel<<<dim3(Ff / 32, Dd / 32, Ee), tb>>>(Wg, wg, Dd, Ff);
    transpose_half_kernel<<<dim3(Ff / 32, Dd / 32, Ee), tb>>>(Wu, wu, Dd, Ff);
    transpose_half_kernel<<<dim3(Dd / 32, Ff / 32, Ee), tb>>>(Wd, wd, Ff, Dd);

    // 1. x = rmsnorm(input) -> split
    rmsnorm_split_kernel<<<NT, 256>>>(input, w_attn, xhi, xlo, nullptr);
    // 2. q/k/v projections
    mma_gemm<<<dim3(QD / 128, NT / 128, 1), 256, GSMEM>>>(
        xhi, xlo, wq, 0, pq, nullptr, 0, NT, QD, Dd);
    mma_gemm<<<dim3(KD / 128, NT / 128, 1), 256, GSMEM>>>(
        xhi, xlo, wk, 0, pk, nullptr, 0, NT, KD, Dd);
    mma_gemm<<<dim3(KD / 128, NT / 128, 1), 256, GSMEM>>>(
        xhi, xlo, wv, 0, outv, nullptr, 0, NT, KD, Dd);
    // 3. RoPE -> fp16 q (hi/lo, scaled), fp32 k out, fp16 k/v
    rope_kernel<<<NT, 256>>>(cosb, sinb, pq, pk, outk, outv, qh2, ql2, kh2, vh2);
    // 4. attention (mma.sync) -> fp16 hi/lo output
    attn_mma_kernel<<<dim3(Ss / 128, Hh, Bb), 256, ASMEM>>>(
        qh2, ql2, kh2, vh2, ahi, alo);
    // 5. h = input + attn @ Wo
    mma_gemm<<<dim3(Dd / 128, NT / 128, 1), 256, GSMEM>>>(
        ahi, alo, wo, 0, ph, input, 0, NT, Dd, QD);
    // 6. y = rmsnorm(h) -> split + f32
    rmsnorm_split_kernel<<<NT, 256>>>(ph, w_moe, yhi, ylo, py);
    // 7. router + compact slots
    zero_cnt_kernel<<<1, 32>>>();
    router_kernel<<<NT / 8, 256>>>(py, rw);
    offsets_kernel<<<1, 32>>>();
    scatter_kernel<<<NT / 256, 256>>>();
    // 8. expert gate / up GEMMs (gathered A rows)
    mma_gemm<<<dim3(Ff / 128, NT / 128, Ee), 256, GSMEM>>>(
        yhi, ylo, wg, (size_t)Ff * Dd, pga, nullptr, 1, NT, Ff, Dd);
    mma_gemm<<<dim3(Ff / 128, NT / 128, Ee), 256, GSMEM>>>(
        yhi, ylo, wu, (size_t)Ff * Dd, pua, nullptr, 1, NT, Ff, Dd);
    // 9. he = silu(gate) * up -> split
    silu_split_kernel<<<dim3(NSLOT, Ff / 256), 256>>>();
    // 10. down projection (contiguous slot rows)
    mma_gemm<<<dim3(Dd / 128, NT / 128, Ee), 256, GSMEM>>>(
        hehi, helo, wd, (size_t)Dd * Ff, pdn, nullptr, 2, NT, Dd, Ff);
    // 11. combine
    combine_kernel<<<dim3(NT, Dd / 256), 256>>>(out);
}

// round 12
// speedup vs baseline: 4.3793x; 1.1486x over previous
#include <cuda_runtime.h>
#include <cuda_fp16.h>
#include <cstdint>

// ---------------------------------------------------------------------------
// MoE transformer block. fp16 warp-MMA GEMMs (selective 2-term) + FA2 attention.
// B=4 S=2048 D=1024 H=16 KV=4 HD=64 E=8 K(top)=2 F=1024
// Base sm_103 PTX only: mma.sync / ldmatrix / cp.async.
// ---------------------------------------------------------------------------

namespace {
constexpr int Bb  = 4;
constexpr int Ss  = 2048;
constexpr int Dd  = 1024;
constexpr int Hh  = 16;
constexpr int KVh = 4;
constexpr int HDd = 64;
constexpr int Ee  = 8;
constexpr int TKk = 2;
constexpr int Ff  = 1024;
constexpr int NT  = Bb * Ss;        // 8192 tokens
constexpr int QD  = Hh * HDd;       // 1024
constexpr int KD  = KVh * HDd;      // 256
constexpr int NSLOT = NT * TKk;     // 16384 expert slots

// GEMM tiling
constexpr int ROWB  = 80;                 // smem row stride bytes (32 fp16 + pad)
constexpr int TILEB = 128 * ROWB;         // one 128x32 fp16 tile = 10240 B
constexpr int GS2   = 3 * 2 * TILEB;      // 1-term: 3 stages x (AH,BH) = 61440
constexpr int GS3   = 3 * 3 * TILEB;      // 2-term: 3 stages x (AH,AL,BH) = 92160

// Attention smem: K/V tiles 64 rows x 64 halves, 144B row stride
constexpr int AROW   = 144;
constexpr int ATILE  = 64 * AROW;         // 9216 B
constexpr int ASTAGE = 2 * ATILE;         // K + V = 18432 B
constexpr int ASMEM  = 2 * ASTAGE;        // 36864 B (also fits Q hi/lo staging)
}

__device__ __forceinline__ uint32_t smem_u32(const void* p) {
    uint32_t a;
    asm("{ .reg .u64 t; cvta.to.shared.u64 t, %1; cvt.u32.u64 %0, t; }" : "=r"(a) : "l"(p));
    return a;
}
#define CP16(dst, src) asm volatile( \
    "cp.async.cg.shared.global [%0], [%1], 16;" :: "r"(dst), "l"(src))
#define CP_COMMIT() asm volatile("cp.async.commit_group;" ::: "memory")
#define CP_WAIT(n)  asm volatile("cp.async.wait_group %0;" :: "n"(n) : "memory")

__device__ __forceinline__ void ldsm_x4(uint32_t* r, uint32_t addr) {
    asm volatile("ldmatrix.sync.aligned.m8n8.x4.shared.b16 {%0,%1,%2,%3}, [%4];"
                 : "=r"(r[0]), "=r"(r[1]), "=r"(r[2]), "=r"(r[3]) : "r"(addr));
}
__device__ __forceinline__ void ldsm_x4_t(uint32_t* r, uint32_t addr) {
    asm volatile("ldmatrix.sync.aligned.m8n8.x4.trans.shared.b16 {%0,%1,%2,%3}, [%4];"
                 : "=r"(r[0]), "=r"(r[1]), "=r"(r[2]), "=r"(r[3]) : "r"(addr));
}
__device__ __forceinline__ void mma_fp16(float* c, const uint32_t* a, const uint32_t* b) {
    asm volatile(
        "mma.sync.aligned.m16n8k16.row.col.f32.f16.f16.f32 "
        "{%0,%1,%2,%3}, {%4,%5,%6,%7}, {%8,%9}, {%0,%1,%2,%3};"
        : "+f"(c[0]), "+f"(c[1]), "+f"(c[2]), "+f"(c[3])
        : "r"(a[0]), "r"(a[1]), "r"(a[2]), "r"(a[3]), "r"(b[0]), "r"(b[1]));
}
__device__ __forceinline__ uint32_t packh2(float a, float b) {
    __half2 h = __floats2half2_rn(a, b);
    return *reinterpret_cast<uint32_t*>(&h);
}

// ---------------------------------------------------------------------------
// Scratch (device globals; no runtime allocation)
// ---------------------------------------------------------------------------
__device__ __align__(128) float g_q[(size_t)NT * QD];
__device__ __align__(128) float g_k[(size_t)NT * KD];
__device__ __align__(128) float g_vscr[(size_t)NT * KD];
__device__ __align__(128) float g_kscr[(size_t)NT * KD];
__device__ __align__(128) float g_h[(size_t)NT * Dd];
__device__ __align__(128) float g_y[(size_t)NT * Dd];
__device__ __align__(128) float g_ga[(size_t)NSLOT * Ff];
__device__ __align__(128) float g_dn[(size_t)NSLOT * Dd];

__device__ __align__(128) __half g_xhi[(size_t)NT * Dd], g_xlo[(size_t)NT * Dd];
__device__ __align__(128) __half g_ahi[(size_t)NT * QD];
__device__ __align__(128) __half g_yhi[(size_t)NT * Dd];
__device__ __align__(128) __half g_hehi[(size_t)NSLOT * Ff];

// fp16 q (hi/lo, pre-scaled 1/8) and k/v for attention
__device__ __align__(128) __half g_qh2[(size_t)NT * QD], g_ql2[(size_t)NT * QD];
__device__ __align__(128) __half g_kh2[(size_t)NT * KD];
__device__ __align__(128) __half g_vh2[(size_t)NT * KD];

// transposed fp16 weights [N, K]
__device__ __align__(128) __half g_wq[(size_t)QD * Dd];
__device__ __align__(128) __half g_wk[(size_t)KD * Dd];
__device__ __align__(128) __half g_wv[(size_t)KD * Dd];
__device__ __align__(128) __half g_wo[(size_t)Dd * QD];
__device__ __align__(128) __half g_wg[(size_t)Ee * Ff * Dd];
__device__ __align__(128) __half g_wu[(size_t)Ee * Ff * Dd];
__device__ __align__(128) __half g_wd[(size_t)Ee * Dd * Ff];

__device__ int   g_cnt[Ee];
__device__ int   g_off[Ee];
__device__ int   g_fill[Ee];
__device__ int   g_list[NSLOT];
__device__ int   g_slot[NSLOT];
__device__ int   g_texp[NSLOT];
__device__ float g_gw[NSLOT];

// ---------------------------------------------------------------------------
// RMSNorm with fp16 hi (+optional lo split, +optional f32) outputs
// ---------------------------------------------------------------------------
__global__ void rmsnorm_split_kernel(const float* __restrict__ in,
                                     const float* __restrict__ w,
                                     __half* __restrict__ ohi,
                                     __half* __restrict__ olo,
                                     float* __restrict__ of32) {
    int t = blockIdx.x;
    const float* row = in + (size_t)t * Dd;
    float ss = 0.f;
#pragma unroll
    for (int i = 0; i < 4; i++) { float v = row[threadIdx.x + i * 256]; ss += v * v; }
#pragma unroll
    for (int o = 16; o > 0; o >>= 1) ss += __shfl_xor_sync(0xffffffffu, ss, o);
    __shared__ float sred[8];
    if ((threadIdx.x & 31) == 0) sred[threadIdx.x >> 5] = ss;
    __syncthreads();
    if (threadIdx.x < 32) {
        float v = (threadIdx.x < 8) ? sred[threadIdx.x] : 0.f;
#pragma unroll
        for (int o = 4; o > 0; o >>= 1) v += __shfl_xor_sync(0xffffffffu, v, o);
        if (threadIdx.x == 0) sred[0] = v;
    }
    __syncthreads();
    float inv = rsqrtf(sred[0] * (1.f / Dd) + 1e-6f);
    size_t base = (size_t)t * Dd;
#pragma unroll
    for (int i = 0; i < 4; i++) {
        int d = threadIdx.x + i * 256;
        float r = row[d] * inv * w[d];
        __half hi = __float2half_rn(r);
        ohi[base + d] = hi;
        if (olo) olo[base + d] = __float2half_rn(r - __half2float(hi));
        if (of32) of32[base + d] = r;
    }
}

// ---------------------------------------------------------------------------
// Transpose: W[K,N] fp32 -> T[N,K] fp16. Block (32,8).
// ---------------------------------------------------------------------------
__global__ void transpose_half_kernel(const float* __restrict__ W,
                                      __half* __restrict__ T,
                                      int K, int N) {
    __shared__ float tile[32][33];
    size_t zb = (size_t)blockIdx.z * K * N;
    int k0 = blockIdx.y * 32, n0 = blockIdx.x * 32;
    int tx = threadIdx.x, ty = threadIdx.y;
#pragma unroll
    for (int j = 0; j < 4; j++)
        tile[ty + 8 * j][tx] = W[zb + (size_t)(k0 + ty + 8 * j) * N + n0 + tx];
    __syncthreads();
#pragma unroll
    for (int j = 0; j < 4; j++) {
        float v = tile[tx][ty + 8 * j];
        T[zb + (size_t)(n0 + ty + 8 * j) * K + k0 + tx] = __float2half_rn(v);
    }
}

// ---------------------------------------------------------------------------
// Warp-MMA GEMM, templated on 2-term A.
// C[M,N] = Ahi@B (+ Alo@B if TT), fp32 accumulate; 3-stage cp.async pipeline.
// A: [M,K] fp16 K-major. B: [N,K] fp16 K-major. K % 32 == 0.
// Epilogue: if gatesrc != null -> Chi[co] = fp16(silu(gatesrc[co]) * acc)
//           else C[co] = acc (+ addsrc[co]).
// mode 0: plain. mode 1: A rows via g_list[g_off[z]+r], C rows g_off[z]+r,
//         Meff=g_cnt[z]. mode 2: A/C rows at g_off[z]+r.
// ---------------------------------------------------------------------------
template <bool TT>
__global__ void __launch_bounds__(256, 1)
mma_gemm(const __half* __restrict__ Ahi, const __half* __restrict__ Alo,
         const __half* __restrict__ Bw,
         size_t bz,
         float* __restrict__ C,
         const float* __restrict__ addsrc,
         __half* __restrict__ Chi,
         const float* __restrict__ gatesrc,
         int mode, int M, int N, int K) {
    extern __shared__ char smem[];
    constexpr int NTIL   = TT ? 3 : 2;
    constexpr int STAGET = NTIL * TILEB;
    constexpr int BOFF   = (TT ? 2 : 1) * TILEB;
    int z = blockIdx.z;
    int Meff = M, off = 0;
    if (mode) { Meff = g_cnt[z]; off = g_off[z]; }
    int m0 = blockIdx.y * 128;
    if (m0 >= Meff) return;
    int n0 = blockIdx.x * 128;
    const __half* bw = Bw + bz * z;

    int tid = threadIdx.x, lane = tid & 31, wid = tid >> 5;
    uint32_t sb = smem_u32(smem);

    int lrow = tid >> 1;
    int lcolh = (tid & 1) * 16;
    int ar = m0 + lrow;
    long grow;
    if (mode == 1) { int rr = (ar < Meff) ? ar : (Meff - 1); grow = g_list[off + rr]; }
    else if (mode == 2) { int rr = (ar < Meff) ? ar : (Meff - 1); grow = off + rr; }
    else grow = ar;
    const __half* pAH = Ahi + (size_t)grow * K + lcolh;
    const __half* pAL = TT ? (Alo + (size_t)grow * K + lcolh) : pAH;
    const __half* pBH = bw + (size_t)(n0 + lrow) * K + lcolh;
    uint32_t dstrel = (uint32_t)(lrow * ROWB + lcolh * 2);

    float acc[4][4][4];
#pragma unroll
    for (int i = 0; i < 4; i++)
#pragma unroll
        for (int j = 0; j < 4; j++)
#pragma unroll
            for (int q = 0; q < 4; q++) acc[i][j][q] = 0.f;

    const int NS = K / 32;
    // stage loader
    auto load_stage = [&](int s) {
        size_t ko = (size_t)s * 32;
        uint32_t d = sb + (s % 3) * STAGET + dstrel;
        CP16(d, pAH + ko); CP16(d + 16, pAH + ko + 8);
        if (TT) { CP16(d + TILEB, pAL + ko); CP16(d + TILEB + 16, pAL + ko + 8); }
        CP16(d + BOFF, pBH + ko); CP16(d + BOFF + 16, pBH + ko + 8);
        CP_COMMIT();
    };
    load_stage(0);
    if (NS > 1) load_stage(1);

    uint32_t a_rel = (uint32_t)(((wid & 1) * 64 + (lane & 15)) * ROWB + (lane >> 4) * 16);
    uint32_t b_rel = (uint32_t)(BOFF +
        ((wid >> 1) * 32 + (lane & 7) + ((lane >> 4) & 1) * 8) * ROWB +
        ((lane >> 3) & 1) * 16);

    for (int s = 0; s < NS; s++) {
        if (s + 2 < NS) { load_stage(s + 2); CP_WAIT(2); }
        else if (s + 1 < NS) { CP_WAIT(1); }
        else { CP_WAIT(0); }
        __syncthreads();
        uint32_t base = sb + (s % 3) * STAGET;
#pragma unroll
        for (int kh = 0; kh < 2; kh++) {
            uint32_t koffb = kh * 32;
            uint32_t ah[4][4], al[4][4];
            uint32_t aaddr = base + a_rel + koffb;
#pragma unroll
            for (int mi = 0; mi < 4; mi++) {
                ldsm_x4(ah[mi], aaddr + mi * 16 * ROWB);
                if (TT) ldsm_x4(al[mi], aaddr + mi * 16 * ROWB + TILEB);
            }
            uint32_t bh[4][2];
            uint32_t baddr = base + b_rel + koffb;
#pragma unroll
            for (int hf = 0; hf < 2; hf++) {
                uint32_t t4[4];
                ldsm_x4(t4, baddr + hf * 16 * ROWB);
                bh[2 * hf][0] = t4[0]; bh[2 * hf][1] = t4[1];
                bh[2 * hf + 1][0] = t4[2]; bh[2 * hf + 1][1] = t4[3];
            }
#pragma unroll
            for (int mi = 0; mi < 4; mi++)
#pragma unroll
                for (int ni = 0; ni < 4; ni++) {
                    mma_fp16(acc[mi][ni], ah[mi], bh[ni]);
                    if (TT) mma_fp16(acc[mi][ni], al[mi], bh[ni]);
                }
        }
        __syncthreads();
    }

    int mW = m0 + (wid & 1) * 64;
    int nW = n0 + (wid >> 1) * 32;
#pragma unroll
    for (int mi = 0; mi < 4; mi++) {
#pragma unroll
        for (int hf = 0; hf < 2; hf++) {
            int r = mW + mi * 16 + hf * 8 + (lane >> 2);
            if (r >= Meff) continue;
            int crow = mode ? (off + r) : r;
#pragma unroll
            for (int ni = 0; ni < 4; ni++) {
                int c = nW + ni * 8 + (lane & 3) * 2;
                size_t co = (size_t)crow * N + c;
                float v0 = acc[mi][ni][2 * hf + 0];
                float v1 = acc[mi][ni][2 * hf + 1];
                if (gatesrc) {
                    float gv0 = gatesrc[co], gv1 = gatesrc[co + 1];
                    float he0 = (gv0 / (1.f + __expf(-gv0))) * v0;
                    float he1 = (gv1 / (1.f + __expf(-gv1))) * v1;
                    *(__half2*)(Chi + co) = __floats2half2_rn(he0, he1);
                } else {
                    if (addsrc) {
                        v0 += addsrc[co];
                        v1 += addsrc[co + 1];
                    }
                    float2 v = {v0, v1};
                    *(float2*)(C + co) = v;
                }
            }
        }
    }
}

// ---------------------------------------------------------------------------
// RoPE: rotate q/k; emit q as fp16 hi/lo (pre-scaled 1/8), k as fp32 output +
// fp16, v converted to fp16.
// ---------------------------------------------------------------------------
__global__ void rope_kernel(const float* __restrict__ cosb,
                            const float* __restrict__ sinb,
                            const float* __restrict__ q,
                            const float* __restrict__ k,
                            float* __restrict__ outk,
                            const float* __restrict__ vin,
                            __half* __restrict__ qh, __half* __restrict__ ql,
                            __half* __restrict__ kh, __half* __restrict__ vh) {
    int t = blockIdx.x;
    int s = t % Ss;
    const float* cs = cosb + (size_t)s * HDd;
    const float* sn = sinb + (size_t)s * HDd;

    const float* qrow = q + (size_t)t * QD;
    for (int idx = threadIdx.x; idx < Hh * 32; idx += blockDim.x) {
        int hh = idx >> 5, d = idx & 31;
        float a = qrow[hh * HDd + d], b2 = qrow[hh * HDd + d + 32];
        float o1 = (a * cs[d] - b2 * sn[d]) * 0.125f;
        float o2 = (b2 * cs[d + 32] + a * sn[d + 32]) * 0.125f;
        size_t base = (size_t)t * QD + hh * HDd;
        __half h1 = __float2half_rn(o1);
        __half h2 = __float2half_rn(o2);
        qh[base + d] = h1;      ql[base + d] = __float2half_rn(o1 - __half2float(h1));
        qh[base + d + 32] = h2; ql[base + d + 32] = __float2half_rn(o2 - __half2float(h2));
    }
    const float* krow = k + (size_t)t * KD;
    for (int idx = threadIdx.x; idx < KVh * 32; idx += blockDim.x) {
        int hh = idx >> 5, d = idx & 31;
        float a = krow[hh * HDd + d], b2 = krow[hh * HDd + d + 32];
        float o1 = a * cs[d] - b2 * sn[d];
        float o2 = b2 * cs[d + 32] + a * sn[d + 32];
        size_t base = (size_t)t * KD + hh * HDd;
        outk[base + d] = o1;      outk[base + d + 32] = o2;
        kh[base + d] = __float2half_rn(o1);
        kh[base + d + 32] = __float2half_rn(o2);
    }
    for (int idx = threadIdx.x; idx < KD; idx += blockDim.x) {
        vh[(size_t)t * KD + idx] = __float2half_rn(vin[(size_t)t * KD + idx]);
    }
}

// ---------------------------------------------------------------------------
// FA2-style causal GQA attention on mma.sync. (unchanged except hi-only out)
// ---------------------------------------------------------------------------
__global__ void __launch_bounds__(256, 1)
attn_mma_kernel(const __half* __restrict__ qh, const __half* __restrict__ ql,
                const __half* __restrict__ kh, const __half* __restrict__ vh,
                __half* __restrict__ ohi) {
    extern __shared__ char smem[];
    int b = blockIdx.z, h = blockIdx.y, qt = blockIdx.x;
    int kvh = h >> 2;
    int tid = threadIdx.x, lane = tid & 31, wid = tid >> 5;
    int qrow0 = qt * 128;
    uint32_t sb = smem_u32(smem);

    {
        const __half* qsh = qh + ((size_t)(b * Ss + qrow0)) * QD + h * HDd;
        const __half* qsl = ql + ((size_t)(b * Ss + qrow0)) * QD + h * HDd;
#pragma unroll
        for (int i = 0; i < 4; i++) {
            int c = tid + 256 * i;
            int row = c >> 3, u = c & 7;
            CP16(sb + row * AROW + u * 16, qsh + (size_t)row * QD + u * 8);
            CP16(sb + ASTAGE + row * AROW + u * 16, qsl + (size_t)row * QD + u * 8);
        }
        CP_COMMIT(); CP_WAIT(0);
    }
    __syncthreads();

    int wr = wid * 16;
    uint32_t qfh[4][4], qfl[4][4];
    {
        uint32_t qa = sb + (wr + (lane & 15)) * AROW + (lane >> 4) * 16;
#pragma unroll
        for (int kc = 0; kc < 4; kc++) {
            ldsm_x4(qfh[kc], qa + kc * 32);
            ldsm_x4(qfl[kc], qa + kc * 32 + ASTAGE);
        }
    }
    __syncthreads();

    float o[8][4];
#pragma unroll
    for (int i = 0; i < 8; i++)
#pragma unroll
        for (int j = 0; j < 4; j++) o[i][j] = 0.f;
    float m0 = -1e30f, m1 = -1e30f, l0 = 0.f, l1 = 0.f;

    const __half* kbase = kh + ((size_t)(b * Ss)) * KD + kvh * HDd;
    const __half* vbase = vh + ((size_t)(b * Ss)) * KD + kvh * HDd;

    int ntiles = (qt + 1) * 2;
    {
#pragma unroll
        for (int i = 0; i < 2; i++) {
            int c = tid + 256 * i;
            int row = c >> 3, u = c & 7;
            CP16(sb + row * AROW + u * 16, kbase + (size_t)row * KD + u * 8);
            CP16(sb + ATILE + row * AROW + u * 16, vbase + (size_t)row * KD + u * 8);
        }
        CP_COMMIT();
    }

    for (int t = 0; t < ntiles; t++) {
        int k0 = t * 64;
        if (t + 1 < ntiles) {
            uint32_t dbuf = sb + ((t + 1) & 1) * ASTAGE;
            const __half* kb = kbase + (size_t)(k0 + 64) * KD;
            const __half* vb = vbase + (size_t)(k0 + 64) * KD;
#pragma unroll
            for (int i = 0; i < 2; i++) {
                int c = tid + 256 * i;
                int row = c >> 3, u = c & 7;
                CP16(dbuf + row * AROW + u * 16, kb + (size_t)row * KD + u * 8);
                CP16(dbuf + ATILE + row * AROW + u * 16, vb + (size_t)row * KD + u * 8);
            }
            CP_COMMIT(); CP_WAIT(1);
        } else {
            CP_WAIT(0);
        }
        __syncthreads();
        uint32_t kb0 = sb + (t & 1) * ASTAGE;
        uint32_t vb0 = kb0 + ATILE;

        float s[8][4];
#pragma unroll
        for (int nc16 = 0; nc16 < 4; nc16++) {
            uint32_t bk[4][4];
            uint32_t baddr = kb0 + (nc16 * 16 + (lane & 7) + ((lane >> 4) & 1) * 8) * AROW
                           + ((lane >> 3) & 1) * 16;
#pragma unroll
            for (int kc = 0; kc < 4; kc++) ldsm_x4(bk[kc], baddr + kc * 32);
#pragma unroll
            for (int j = 0; j < 2; j++) {
                int nc = nc16 * 2 + j;
                s[nc][0] = s[nc][1] = s[nc][2] = s[nc][3] = 0.f;
#pragma unroll
                for (int kc = 0; kc < 4; kc++) {
                    mma_fp16(s[nc], qfh[kc], &bk[kc][2 * j]);
                    mma_fp16(s[nc], qfl[kc], &bk[kc][2 * j]);
                }
            }
        }
        if (k0 + 63 > qrow0 + wr) {
            int row0 = qrow0 + wr + (lane >> 2);
            int colb = k0 + (lane & 3) * 2;
#pragma unroll
            for (int nc = 0; nc < 8; nc++) {
                int c0 = colb + nc * 8, c1 = c0 + 1;
                if (c0 > row0)     s[nc][0] = -1e9f;
                if (c1 > row0)     s[nc][1] = -1e9f;
                if (c0 > row0 + 8) s[nc][2] = -1e9f;
                if (c1 > row0 + 8) s[nc][3] = -1e9f;
            }
        }
        float mx0 = -1e30f, mx1 = -1e30f;
#pragma unroll
        for (int nc = 0; nc < 8; nc++) {
            mx0 = fmaxf(mx0, fmaxf(s[nc][0], s[nc][1]));
            mx1 = fmaxf(mx1, fmaxf(s[nc][2], s[nc][3]));
        }
        mx0 = fmaxf(mx0, __shfl_xor_sync(0xffffffffu, mx0, 1));
        mx0 = fmaxf(mx0, __shfl_xor_sync(0xffffffffu, mx0, 2));
        mx1 = fmaxf(mx1, __shfl_xor_sync(0xffffffffu, mx1, 1));
        mx1 = fmaxf(mx1, __shfl_xor_sync(0xffffffffu, mx1, 2));
        float mn0 = fmaxf(m0, mx0), mn1 = fmaxf(m1, mx1);
        float cr0 = __expf(m0 - mn0), cr1 = __expf(m1 - mn1);
        m0 = mn0; m1 = mn1;
        float sum0 = 0.f, sum1 = 0.f;
#pragma unroll
        for (int nc = 0; nc < 8; nc++) {
            s[nc][0] = __expf(s[nc][0] - m0);
            s[nc][1] = __expf(s[nc][1] - m0);
            s[nc][2] = __expf(s[nc][2] - m1);
            s[nc][3] = __expf(s[nc][3] - m1);
            sum0 += s[nc][0] + s[nc][1];
            sum1 += s[nc][2] + s[nc][3];
        }
        sum0 += __shfl_xor_sync(0xffffffffu, sum0, 1);
        sum0 += __shfl_xor_sync(0xffffffffu, sum0, 2);
        sum1 += __shfl_xor_sync(0xffffffffu, sum1, 1);
        sum1 += __shfl_xor_sync(0xffffffffu, sum1, 2);
        l0 = l0 * cr0 + sum0;
        l1 = l1 * cr1 + sum1;
#pragma unroll
        for (int nc = 0; nc < 8; nc++) {
            o[nc][0] *= cr0; o[nc][1] *= cr0;
            o[nc][2] *= cr1; o[nc][3] *= cr1;
        }
        uint32_t pa[4][4];
#pragma unroll
        for (int kc = 0; kc < 4; kc++) {
            pa[kc][0] = packh2(s[2 * kc][0],     s[2 * kc][1]);
            pa[kc][1] = packh2(s[2 * kc][2],     s[2 * kc][3]);
            pa[kc][2] = packh2(s[2 * kc + 1][0], s[2 * kc + 1][1]);
            pa[kc][3] = packh2(s[2 * kc + 1][2], s[2 * kc + 1][3]);
        }
#pragma unroll
        for (int kc = 0; kc < 4; kc++) {
            uint32_t baddr = vb0 + (kc * 16 + (lane & 7) + ((lane >> 3) & 1) * 8) * AROW
                           + ((lane >> 4) & 1) * 16;
#pragma unroll
            for (int n16 = 0; n16 < 4; n16++) {
                uint32_t t4[4];
                ldsm_x4_t(t4, baddr + n16 * 32);
                mma_fp16(o[n16 * 2],     pa[kc], &t4[0]);
                mma_fp16(o[n16 * 2 + 1], pa[kc], &t4[2]);
            }
        }
        __syncthreads();
    }

    float inv0 = 1.f / l0, inv1 = 1.f / l1;
    int row0 = qrow0 + wr + (lane >> 2);
#pragma unroll
    for (int nc = 0; nc < 8; nc++) {
        int col = h * HDd + nc * 8 + (lane & 3) * 2;
        float v0 = o[nc][0] * inv0, v1 = o[nc][1] * inv0;
        float v2 = o[nc][2] * inv1, v3 = o[nc][3] * inv1;
        size_t o0 = (size_t)(b * Ss + row0) * QD + col;
        size_t o1 = (size_t)(b * Ss + row0 + 8) * QD + col;
        *(__half2*)(ohi + o0) = __floats2half2_rn(v0, v1);
        *(__half2*)(ohi + o1) = __floats2half2_rn(v2, v3);
    }
}

// ---------------------------------------------------------------------------
// Router + compacted slot assignment
// ---------------------------------------------------------------------------
__global__ void zero_cnt_kernel() {
    if (threadIdx.x < Ee) g_cnt[threadIdx.x] = 0;
}

__global__ void router_kernel(const float* __restrict__ y,
                              const float* __restrict__ rw) {
    int t = (blockIdx.x * blockDim.x + threadIdx.x) >> 5;
    int lane = threadIdx.x & 31;
    if (t >= NT) return;
    const float* yrow = y + (size_t)t * Dd;
    float logits[8] = {};
    for (int i = 0; i < 32; i++) {
        int d = i * 32 + lane;
        float yv = yrow[d];
#pragma unroll
        for (int e = 0; e < 8; e++) logits[e] += yv * rw[d * 8 + e];
    }
#pragma unroll
    for (int e = 0; e < 8; e++) {
#pragma unroll
        for (int o = 16; o > 0; o >>= 1)
            logits[e] += __shfl_xor_sync(0xffffffffu, logits[e], o);
    }
    if (lane == 0) {
        int i0 = 0; float v0 = logits[0];
#pragma unroll
        for (int e = 1; e < 8; e++) if (logits[e] > v0) { v0 = logits[e]; i0 = e; }
        int i1 = -1; float v1 = -1e30f;
#pragma unroll
        for (int e = 0; e < 8; e++)
            if (e != i0 && logits[e] > v1) { v1 = logits[e]; i1 = e; }
        float e1 = __expf(v1 - v0);
        g_texp[t * 2 + 0] = i0;
        g_texp[t * 2 + 1] = i1;
        g_gw[t * 2 + 0] = 1.f / (1.f + e1);
        g_gw[t * 2 + 1] = e1 / (1.f + e1);
        atomicAdd(&g_cnt[i0], 1);
        atomicAdd(&g_cnt[i1], 1);
    }
}

__global__ void offsets_kernel() {
    if (threadIdx.x == 0) {
        int a = 0;
        for (int e = 0; e < Ee; e++) { g_off[e] = a; a += g_cnt[e]; g_fill[e] = 0; }
    }
}

__global__ void scatter_kernel() {
    int t = blockIdx.x * blockDim.x + threadIdx.x;
    if (t >= NT) return;
#pragma unroll
    for (int j = 0; j < 2; j++) {
        int e = g_texp[t * 2 + j];
        int p = atomicAdd(&g_fill[e], 1);
        int slot = g_off[e] + p;
        g_list[slot] = t;
        g_slot[t * 2 + j] = slot;
    }
}

// ---------------------------------------------------------------------------
// out = h + w0 * down[slot0] + w1 * down[slot1]
// ---------------------------------------------------------------------------
__global__ void combine_kernel(float* __restrict__ out) {
    int t = blockIdx.x;
    int d = blockIdx.y * 256 + threadIdx.x;
    int s0 = g_slot[t * 2], s1 = g_slot[t * 2 + 1];
    float w0 = g_gw[t * 2], w1 = g_gw[t * 2 + 1];
    size_t o = (size_t)t * Dd + d;
    out[o] = g_h[o] + w0 * g_dn[(size_t)s0 * Dd + d]
                    + w1 * g_dn[(size_t)s1 * Dd + d];
}

// ---------------------------------------------------------------------------
// Launch
// ---------------------------------------------------------------------------
extern "C" void kernel_launch(void* const* d_in, const int* in_sizes, int n_in,
                              void* d_out, int out_size) {
    const float* input  = (const float*)d_in[0];
    const float* cosb   = (const float*)d_in[1];
    const float* sinb   = (const float*)d_in[2];
    // d_in[3] = mask (causal, unused)
    const float* w_attn = (const float*)d_in[4];
    const float* w_moe  = (const float*)d_in[5];
    const float* Wq     = (const float*)d_in[6];
    const float* Wk     = (const float*)d_in[7];
    const float* Wv     = (const float*)d_in[8];
    const float* Wo     = (const float*)d_in[9];
    const float* rw     = (const float*)d_in[10];
    const float* Wg     = (const float*)d_in[11];
    const float* Wu     = (const float*)d_in[12];
    const float* Wd     = (const float*)d_in[13];

    cudaFuncSetAttribute(mma_gemm<false>, cudaFuncAttributeMaxDynamicSharedMemorySize, GS2);
    cudaFuncSetAttribute(mma_gemm<true>,  cudaFuncAttributeMaxDynamicSharedMemorySize, GS3);

    float *pq, *pk, *pvs, *pks, *ph, *py, *pga, *pdn;
    cudaGetSymbolAddress((void**)&pq,  g_q);
    cudaGetSymbolAddress((void**)&pk,  g_k);
    cudaGetSymbolAddress((void**)&pvs, g_vscr);
    cudaGetSymbolAddress((void**)&pks, g_kscr);
    cudaGetSymbolAddress((void**)&ph,  g_h);
    cudaGetSymbolAddress((void**)&py,  g_y);
    cudaGetSymbolAddress((void**)&pga, g_ga);
    cudaGetSymbolAddress((void**)&pdn, g_dn);

    __half *xhi, *xlo, *ahi, *yhi, *hehi;
    __half *qh2, *ql2, *kh2, *vh2;
    __half *wq, *wk, *wv, *wo, *wg, *wu, *wd;
    cudaGetSymbolAddress((void**)&xhi, g_xhi);  cudaGetSymbolAddress((void**)&xlo, g_xlo);
    cudaGetSymbolAddress((void**)&ahi, g_ahi);
    cudaGetSymbolAddress((void**)&yhi, g_yhi);
    cudaGetSymbolAddress((void**)&hehi, g_hehi);
    cudaGetSymbolAddress((void**)&qh2, g_qh2);  cudaGetSymbolAddress((void**)&ql2, g_ql2);
    cudaGetSymbolAddress((void**)&kh2, g_kh2);  cudaGetSymbolAddress((void**)&vh2, g_vh2);
    cudaGetSymbolAddress((void**)&wq, g_wq);
    cudaGetSymbolAddress((void**)&wk, g_wk);
    cudaGetSymbolAddress((void**)&wv, g_wv);
    cudaGetSymbolAddress((void**)&wo, g_wo);
    cudaGetSymbolAddress((void**)&wg, g_wg);
    cudaGetSymbolAddress((void**)&wu, g_wu);
    cudaGetSymbolAddress((void**)&wd, g_wd);

    float* out = (float*)d_out;
    size_t need = (size_t)NT * Dd + 2 * (size_t)NT * KD;
    bool full = ((size_t)out_size >= need);
    float* outk = full ? (out + (size_t)NT * Dd) : pks;
    float* outv = full ? (out + (size_t)NT * Dd + (size_t)NT * KD) : pvs;

    dim3 tb(32, 8);
    // weight transposes (fp16, [N,K])
    transpose_half_kernel<<<dim3(QD / 32, Dd / 32, 1),  tb>>>(Wq, wq, Dd, QD);
    transpose_half_kernel<<<dim3(KD / 32, Dd / 32, 1),  tb>>>(Wk, wk, Dd, KD);
    transpose_half_kernel<<<dim3(KD / 32, Dd / 32, 1),  tb>>>(Wv, wv, Dd, KD);
    transpose_half_kernel<<<dim3(Dd / 32, QD / 32, 1),  tb>>>(Wo, wo, QD, Dd);
    transpose_half_kernel<<<dim3(Ff / 32, Dd / 32, Ee), tb>>>(Wg, wg, Dd, Ff);
    transpose_half_kernel<<<dim3(Ff / 32, Dd / 32, Ee), tb>>>(Wu, wu, Dd, Ff);
    transpose_half_kernel<<<dim3(Dd / 32, Ff / 32, Ee), tb>>>(Wd, wd, Ff, Dd);

    // 1. x = rmsnorm(input) -> fp16 hi/lo
    rmsnorm_split_kernel<<<NT, 256>>>(input, w_attn, xhi, xlo, nullptr);
    // 2. q/k/v projections (q 1-term; k/v 2-term: direct outputs)
    mma_gemm<false><<<dim3(QD / 128, NT / 128, 1), 256, GS2>>>(
        xhi, nullptr, wq, 0, pq, nullptr, nullptr, nullptr, 0, NT, QD, Dd);
    mma_gemm<true><<<dim3(KD / 128, NT / 128, 1), 256, GS3>>>(
        xhi, xlo, wk, 0, pk, nullptr, nullptr, nullptr, 0, NT, KD, Dd);
    mma_gemm<true><<<dim3(KD / 128, NT / 128, 1), 256, GS3>>>(
        xhi, xlo, wv, 0, outv, nullptr, nullptr, nullptr, 0, NT, KD, Dd);
    // 3. RoPE -> fp16 q (hi/lo, scaled), fp32 k out, fp16 k/v
    rope_kernel<<<NT, 256>>>(cosb, sinb, pq, pk, outk, outv, qh2, ql2, kh2, vh2);
    // 4. attention (mma.sync) -> fp16 output
    attn_mma_kernel<<<dim3(Ss / 128, Hh, Bb), 256, ASMEM>>>(
        qh2, ql2, kh2, vh2, ahi);
    // 5. h = input + attn @ Wo
    mma_gemm<false><<<dim3(Dd / 128, NT / 128, 1), 256, GS2>>>(
        ahi, nullptr, wo, 0, ph, input, nullptr, nullptr, 0, NT, Dd, QD);
    // 6. y = rmsnorm(h) -> fp16 hi + f32
    rmsnorm_split_kernel<<<NT, 256>>>(ph, w_moe, yhi, nullptr, py);
    // 7. router + compact slots
    zero_cnt_kernel<<<1, 32>>>();
    router_kernel<<<NT / 8, 256>>>(py, rw);
    offsets_kernel<<<1, 32>>>();
    scatter_kernel<<<NT / 256, 256>>>();
    // 8. expert gate GEMM -> f32 ga
    mma_gemm<false><<<dim3(Ff / 128, NT / 128, Ee), 256, GS2>>>(
        yhi, nullptr, wg, (size_t)Ff * Dd, pga, nullptr, nullptr, nullptr, 1, NT, Ff, Dd);
    // 9. expert up GEMM with fused silu(ga)*up -> fp16 he
    mma_gemm<false><<<dim3(Ff / 128, NT / 128, Ee), 256, GS2>>>(
        yhi, nullptr, wu, (size_t)Ff * Dd, nullptr, nullptr, hehi, pga, 1, NT, Ff, Dd);
    // 10. down projection (contiguous slot rows)
    mma_gemm<false><<<dim3(Dd / 128, NT / 128, Ee), 256, GS2>>>(
        hehi, nullptr, wd, (size_t)Dd * Ff, pdn, nullptr, nullptr, nullptr, 2, NT, Dd, Ff);
    // 11. combine
    combine_kernel<<<dim3(NT, Dd / 256), 256>>>(out);
}

// round 13
// speedup vs baseline: 4.8280x; 1.1025x over previous
#include <cuda_runtime.h>
#include <cuda_fp16.h>
#include <cstdint>

// ---------------------------------------------------------------------------
// MoE transformer block. fp16 warp-MMA GEMMs (fused QKV, fused gate+up+silu)
// + FA2 attention. B=4 S=2048 D=1024 H=16 KV=4 HD=64 E=8 K(top)=2 F=1024
// Base sm_103 PTX only: mma.sync / ldmatrix / cp.async.
// ---------------------------------------------------------------------------

namespace {
constexpr int Bb  = 4;
constexpr int Ss  = 2048;
constexpr int Dd  = 1024;
constexpr int Hh  = 16;
constexpr int KVh = 4;
constexpr int HDd = 64;
constexpr int Ee  = 8;
constexpr int TKk = 2;
constexpr int Ff  = 1024;
constexpr int NT  = Bb * Ss;        // 8192 tokens
constexpr int QD  = Hh * HDd;       // 1024
constexpr int KD  = KVh * HDd;      // 256
constexpr int QKVN = QD + 2 * KD;   // 1536
constexpr int NSLOT = NT * TKk;     // 16384 expert slots

// GEMM tiling
constexpr int ROWB   = 80;                // smem row stride bytes (32 fp16 + pad)
constexpr int TILEB  = 128 * ROWB;        // 128x32 fp16 tile = 10240 B
constexpr int TILEBB = 64 * ROWB;         // 64x32 fp16 tile  = 5120 B
constexpr int GS2    = 3 * 2 * TILEB;     // gemm: 3 stages x (A,B) = 61440
constexpr int DSTAGE = TILEB + 2 * TILEBB;            // A + Bg + Bu = 20480
constexpr int GSD    = 3 * DSTAGE;                    // 61440

// Attention smem
constexpr int AROW   = 144;
constexpr int ATILE  = 64 * AROW;
constexpr int ASTAGE = 2 * ATILE;
constexpr int ASMEM  = 2 * ASTAGE;        // 36864
}

__device__ __forceinline__ uint32_t smem_u32(const void* p) {
    uint32_t a;
    asm("{ .reg .u64 t; cvta.to.shared.u64 t, %1; cvt.u32.u64 %0, t; }" : "=r"(a) : "l"(p));
    return a;
}
#define CP16(dst, src) asm volatile( \
    "cp.async.cg.shared.global [%0], [%1], 16;" :: "r"(dst), "l"(src))
#define CP_COMMIT() asm volatile("cp.async.commit_group;" ::: "memory")
#define CP_WAIT(n)  asm volatile("cp.async.wait_group %0;" :: "n"(n) : "memory")

__device__ __forceinline__ void ldsm_x4(uint32_t* r, uint32_t addr) {
    asm volatile("ldmatrix.sync.aligned.m8n8.x4.shared.b16 {%0,%1,%2,%3}, [%4];"
                 : "=r"(r[0]), "=r"(r[1]), "=r"(r[2]), "=r"(r[3]) : "r"(addr));
}
__device__ __forceinline__ void ldsm_x4_t(uint32_t* r, uint32_t addr) {
    asm volatile("ldmatrix.sync.aligned.m8n8.x4.trans.shared.b16 {%0,%1,%2,%3}, [%4];"
                 : "=r"(r[0]), "=r"(r[1]), "=r"(r[2]), "=r"(r[3]) : "r"(addr));
}
__device__ __forceinline__ void mma_fp16(float* c, const uint32_t* a, const uint32_t* b) {
    asm volatile(
        "mma.sync.aligned.m16n8k16.row.col.f32.f16.f16.f32 "
        "{%0,%1,%2,%3}, {%4,%5,%6,%7}, {%8,%9}, {%0,%1,%2,%3};"
        : "+f"(c[0]), "+f"(c[1]), "+f"(c[2]), "+f"(c[3])
        : "r"(a[0]), "r"(a[1]), "r"(a[2]), "r"(a[3]), "r"(b[0]), "r"(b[1]));
}
__device__ __forceinline__ uint32_t packh2(float a, float b) {
    __half2 h = __floats2half2_rn(a, b);
    return *reinterpret_cast<uint32_t*>(&h);
}

// ---------------------------------------------------------------------------
// Scratch
// ---------------------------------------------------------------------------
__device__ __align__(128) float g_q[(size_t)NT * QD];
__device__ __align__(128) float g_k[(size_t)NT * KD];
__device__ __align__(128) float g_vscr[(size_t)NT * KD];
__device__ __align__(128) float g_kscr[(size_t)NT * KD];
__device__ __align__(128) float g_h[(size_t)NT * Dd];
__device__ __align__(128) float g_y[(size_t)NT * Dd];
__device__ __align__(128) __half g_dnh[(size_t)NSLOT * Dd];

__device__ __align__(128) __half g_xhi[(size_t)NT * Dd];
__device__ __align__(128) __half g_ahi[(size_t)NT * QD];
__device__ __align__(128) __half g_yhi[(size_t)NT * Dd];
__device__ __align__(128) __half g_hehi[(size_t)NSLOT * Ff];

// fp16 q (hi/lo, pre-scaled 1/8) and k/v for attention
__device__ __align__(128) __half g_qh2[(size_t)NT * QD], g_ql2[(size_t)NT * QD];
__device__ __align__(128) __half g_kh2[(size_t)NT * KD];
__device__ __align__(128) __half g_vh2[(size_t)NT * KD];

// transposed fp16 weights [N, K]
__device__ __align__(128) __half g_wqkv[(size_t)QKVN * Dd];
__device__ __align__(128) __half g_wo[(size_t)Dd * QD];
__device__ __align__(128) __half g_wg[(size_t)Ee * Ff * Dd];
__device__ __align__(128) __half g_wu[(size_t)Ee * Ff * Dd];
__device__ __align__(128) __half g_wd[(size_t)Ee * Dd * Ff];

__device__ int   g_cnt[Ee];
__device__ int   g_off[Ee];
__device__ int   g_fill[Ee];
__device__ int   g_list[NSLOT];
__device__ int   g_slot[NSLOT];
__device__ int   g_texp[NSLOT];
__device__ float g_gw[NSLOT];

// ---------------------------------------------------------------------------
// RMSNorm -> fp16 hi (+optional f32)
// ---------------------------------------------------------------------------
__global__ void rmsnorm_kernel(const float* __restrict__ in,
                               const float* __restrict__ w,
                               __half* __restrict__ ohi,
                               float* __restrict__ of32) {
    int t = blockIdx.x;
    const float* row = in + (size_t)t * Dd;
    float ss = 0.f;
#pragma unroll
    for (int i = 0; i < 4; i++) { float v = row[threadIdx.x + i * 256]; ss += v * v; }
#pragma unroll
    for (int o = 16; o > 0; o >>= 1) ss += __shfl_xor_sync(0xffffffffu, ss, o);
    __shared__ float sred[8];
    if ((threadIdx.x & 31) == 0) sred[threadIdx.x >> 5] = ss;
    __syncthreads();
    if (threadIdx.x < 32) {
        float v = (threadIdx.x < 8) ? sred[threadIdx.x] : 0.f;
#pragma unroll
        for (int o = 4; o > 0; o >>= 1) v += __shfl_xor_sync(0xffffffffu, v, o);
        if (threadIdx.x == 0) sred[0] = v;
    }
    __syncthreads();
    float inv = rsqrtf(sred[0] * (1.f / Dd) + 1e-6f);
    size_t base = (size_t)t * Dd;
#pragma unroll
    for (int i = 0; i < 4; i++) {
        int d = threadIdx.x + i * 256;
        float r = row[d] * inv * w[d];
        ohi[base + d] = __float2half_rn(r);
        if (of32) of32[base + d] = r;
    }
}

// ---------------------------------------------------------------------------
// Transpose: W[K,N] fp32 -> T[N,K] fp16. Block (32,8).
// ---------------------------------------------------------------------------
__global__ void transpose_half_kernel(const float* __restrict__ W,
                                      __half* __restrict__ T,
                                      int K, int N) {
    __shared__ float tile[32][33];
    size_t zb = (size_t)blockIdx.z * K * N;
    int k0 = blockIdx.y * 32, n0 = blockIdx.x * 32;
    int tx = threadIdx.x, ty = threadIdx.y;
#pragma unroll
    for (int j = 0; j < 4; j++)
        tile[ty + 8 * j][tx] = W[zb + (size_t)(k0 + ty + 8 * j) * N + n0 + tx];
    __syncthreads();
#pragma unroll
    for (int j = 0; j < 4; j++) {
        float v = tile[tx][ty + 8 * j];
        T[(size_t)blockIdx.z * K * N + (size_t)(n0 + ty + 8 * j) * K + k0 + tx] =
            __float2half_rn(v);
    }
}

// ---------------------------------------------------------------------------
// Warp-MMA GEMM (1-term): C[M,N] = A@B, fp32 accum, 3-stage cp.async.
// A [M,K] fp16 K-major; B [N,K] fp16 K-major.
// Epilogue variants:
//  - Ck != null: QKV split (N=1536): cols [0,1024)->C f32 stride 1024,
//    [1024,1280)->Ck f32 stride 256, [1280,1536)->Cv f32 stride 256.
//  - Chi != null: fp16 output (stride N).
//  - else: f32 C (+addsrc).
// mode 0: plain; mode 1: A rows via g_list[off+r], C rows off+r;
// mode 2: A/C rows at off+r. (off=g_off[z], Meff=g_cnt[z])
// ---------------------------------------------------------------------------
__global__ void __launch_bounds__(256, 1)
mma_gemm(const __half* __restrict__ Ah,
         const __half* __restrict__ Bw, size_t bz,
         float* __restrict__ C, const float* __restrict__ addsrc,
         float* __restrict__ Ck, float* __restrict__ Cv,
         __half* __restrict__ Chi,
         int mode, int M, int N, int K) {
    extern __shared__ char smem[];
    int z = blockIdx.z;
    int Meff = M, off = 0;
    if (mode) { Meff = g_cnt[z]; off = g_off[z]; }
    int m0 = blockIdx.y * 128;
    if (m0 >= Meff) return;
    int n0 = blockIdx.x * 128;
    const __half* bw = Bw + bz * z;

    int tid = threadIdx.x, lane = tid & 31, wid = tid >> 5;
    uint32_t sb = smem_u32(smem);

    int lrow = tid >> 1;
    int lcolh = (tid & 1) * 16;
    int ar = m0 + lrow;
    long grow;
    if (mode == 1) { int rr = (ar < Meff) ? ar : (Meff - 1); grow = g_list[off + rr]; }
    else if (mode == 2) { int rr = (ar < Meff) ? ar : (Meff - 1); grow = off + rr; }
    else grow = ar;
    const __half* pA = Ah + (size_t)grow * K + lcolh;
    const __half* pB = bw + (size_t)(n0 + lrow) * K + lcolh;
    uint32_t dstrel = (uint32_t)(lrow * ROWB + lcolh * 2);

    float acc[4][4][4];
#pragma unroll
    for (int i = 0; i < 4; i++)
#pragma unroll
        for (int j = 0; j < 4; j++)
#pragma unroll
            for (int q = 0; q < 4; q++) acc[i][j][q] = 0.f;

    const int NS = K / 32;
    auto load_stage = [&](int s) {
        size_t ko = (size_t)s * 32;
        uint32_t d = sb + (s % 3) * (2 * TILEB) + dstrel;
        CP16(d, pA + ko); CP16(d + 16, pA + ko + 8);
        CP16(d + TILEB, pB + ko); CP16(d + TILEB + 16, pB + ko + 8);
        CP_COMMIT();
    };
    load_stage(0);
    if (NS > 1) load_stage(1);

    uint32_t a_rel = (uint32_t)(((wid & 1) * 64 + (lane & 15)) * ROWB + (lane >> 4) * 16);
    uint32_t b_rel = (uint32_t)(TILEB +
        ((wid >> 1) * 32 + (lane & 7) + ((lane >> 4) & 1) * 8) * ROWB +
        ((lane >> 3) & 1) * 16);

    for (int s = 0; s < NS; s++) {
        if (s + 2 < NS) { load_stage(s + 2); CP_WAIT(2); }
        else if (s + 1 < NS) { CP_WAIT(1); }
        else { CP_WAIT(0); }
        __syncthreads();
        uint32_t base = sb + (s % 3) * (2 * TILEB);
#pragma unroll
        for (int kh = 0; kh < 2; kh++) {
            uint32_t koffb = kh * 32;
            uint32_t ah[4][4];
            uint32_t aaddr = base + a_rel + koffb;
#pragma unroll
            for (int mi = 0; mi < 4; mi++)
                ldsm_x4(ah[mi], aaddr + mi * 16 * ROWB);
            uint32_t bh[4][2];
            uint32_t baddr = base + b_rel + koffb;
#pragma unroll
            for (int hf = 0; hf < 2; hf++) {
                uint32_t t4[4];
                ldsm_x4(t4, baddr + hf * 16 * ROWB);
                bh[2 * hf][0] = t4[0]; bh[2 * hf][1] = t4[1];
                bh[2 * hf + 1][0] = t4[2]; bh[2 * hf + 1][1] = t4[3];
            }
#pragma unroll
            for (int mi = 0; mi < 4; mi++)
#pragma unroll
                for (int ni = 0; ni < 4; ni++)
                    mma_fp16(acc[mi][ni], ah[mi], bh[ni]);
        }
        __syncthreads();
    }

    int mW = m0 + (wid & 1) * 64;
    int nW = n0 + (wid >> 1) * 32;
#pragma unroll
    for (int mi = 0; mi < 4; mi++) {
#pragma unroll
        for (int hf = 0; hf < 2; hf++) {
            int r = mW + mi * 16 + hf * 8 + (lane >> 2);
            if (r >= Meff) continue;
            int crow = mode ? (off + r) : r;
#pragma unroll
            for (int ni = 0; ni < 4; ni++) {
                int c = nW + ni * 8 + (lane & 3) * 2;
                float v0 = acc[mi][ni][2 * hf + 0];
                float v1 = acc[mi][ni][2 * hf + 1];
                if (Ck) {
                    float2 v = {v0, v1};
                    if (c < QD)
                        *(float2*)(C + (size_t)crow * QD + c) = v;
                    else if (c < QD + KD)
                        *(float2*)(Ck + (size_t)crow * KD + (c - QD)) = v;
                    else
                        *(float2*)(Cv + (size_t)crow * KD + (c - QD - KD)) = v;
                } else if (Chi) {
                    *(__half2*)(Chi + (size_t)crow * N + c) = __floats2half2_rn(v0, v1);
                } else {
                    size_t co = (size_t)crow * N + c;
                    if (addsrc) { v0 += addsrc[co]; v1 += addsrc[co + 1]; }
                    float2 v = {v0, v1};
                    *(float2*)(C + co) = v;
                }
            }
        }
    }
}

// ---------------------------------------------------------------------------
// Dual-B GEMM: gate = A@Wg, up = A@Wu; he = silu(gate)*up -> fp16.
// CTA tile 128 x 64 (per output); A gathered rows (mode-1 semantics).
// ---------------------------------------------------------------------------
__global__ void __launch_bounds__(256, 1)
mma_gateup(const __half* __restrict__ Ah,
           const __half* __restrict__ Wg_, const __half* __restrict__ Wu_,
           size_t bz, __half* __restrict__ He, int K) {
    extern __shared__ char smem[];
    int z = blockIdx.z;
    int Meff = g_cnt[z], off = g_off[z];
    int m0 = blockIdx.y * 128;
    if (m0 >= Meff) return;
    int n0 = blockIdx.x * 64;
    const __half* wg = Wg_ + bz * z;
    const __half* wu = Wu_ + bz * z;

    int tid = threadIdx.x, lane = tid & 31, wid = tid >> 5;
    int wm = wid & 3, wn = wid >> 2;
    uint32_t sb = smem_u32(smem);

    // A loader: 2 chunks/thread over 128 rows
    int lrow = tid >> 1;
    int lcolh = (tid & 1) * 16;
    int ar = m0 + lrow;
    int rr = (ar < Meff) ? ar : (Meff - 1);
    long grow = g_list[off + rr];
    const __half* pA = Ah + (size_t)grow * K + lcolh;
    uint32_t adst = (uint32_t)(lrow * ROWB + lcolh * 2);
    // B loaders: 1 chunk/thread over 64 rows each
    int brow = tid >> 2;
    int bch = (tid & 3) * 8;
    const __half* pG = wg + (size_t)(n0 + brow) * K + bch;
    const __half* pU = wu + (size_t)(n0 + brow) * K + bch;
    uint32_t bdst = (uint32_t)(brow * ROWB + bch * 2);

    float accG[2][4][4], accU[2][4][4];
#pragma unroll
    for (int i = 0; i < 2; i++)
#pragma unroll
        for (int j = 0; j < 4; j++)
#pragma unroll
            for (int q = 0; q < 4; q++) { accG[i][j][q] = 0.f; accU[i][j][q] = 0.f; }

    const int NS = K / 32;
    auto load_stage = [&](int s) {
        size_t ko = (size_t)s * 32;
        uint32_t d = sb + (s % 3) * DSTAGE;
        CP16(d + adst, pA + ko); CP16(d + adst + 16, pA + ko + 8);
        CP16(d + TILEB + bdst, pG + ko);
        CP16(d + TILEB + TILEBB + bdst, pU + ko);
        CP_COMMIT();
    };
    load_stage(0);
    if (NS > 1) load_stage(1);

    uint32_t a_rel = (uint32_t)((wm * 32 + (lane & 15)) * ROWB + (lane >> 4) * 16);
    uint32_t b_rel = (uint32_t)((wn * 32 + (lane & 7) + ((lane >> 4) & 1) * 8) * ROWB +
                                ((lane >> 3) & 1) * 16);

    for (int s = 0; s < NS; s++) {
        if (s + 2 < NS) { load_stage(s + 2); CP_WAIT(2); }
        else if (s + 1 < NS) { CP_WAIT(1); }
        else { CP_WAIT(0); }
        __syncthreads();
        uint32_t base = sb + (s % 3) * DSTAGE;
#pragma unroll
        for (int kh = 0; kh < 2; kh++) {
            uint32_t koffb = kh * 32;
            uint32_t ah[2][4];
            uint32_t aaddr = base + a_rel + koffb;
#pragma unroll
            for (int mi = 0; mi < 2; mi++)
                ldsm_x4(ah[mi], aaddr + mi * 16 * ROWB);
            uint32_t bg[4][2], bu[4][2];
#pragma unroll
            for (int hf = 0; hf < 2; hf++) {
                uint32_t t4[4];
                ldsm_x4(t4, base + TILEB + b_rel + koffb + hf * 16 * ROWB);
                bg[2 * hf][0] = t4[0]; bg[2 * hf][1] = t4[1];
                bg[2 * hf + 1][0] = t4[2]; bg[2 * hf + 1][1] = t4[3];
                ldsm_x4(t4, base + TILEB + TILEBB + b_rel + koffb + hf * 16 * ROWB);
                bu[2 * hf][0] = t4[0]; bu[2 * hf][1] = t4[1];
                bu[2 * hf + 1][0] = t4[2]; bu[2 * hf + 1][1] = t4[3];
            }
#pragma unroll
            for (int mi = 0; mi < 2; mi++)
#pragma unroll
                for (int ni = 0; ni < 4; ni++) {
                    mma_fp16(accG[mi][ni], ah[mi], bg[ni]);
                    mma_fp16(accU[mi][ni], ah[mi], bu[ni]);
                }
        }
        __syncthreads();
    }

    int mW = m0 + wm * 32;
    int nW = n0 + wn * 32;
#pragma unroll
    for (int mi = 0; mi < 2; mi++) {
#pragma unroll
        for (int hf = 0; hf < 2; hf++) {
            int r = mW + mi * 16 + hf * 8 + (lane >> 2);
            if (r >= Meff) continue;
            int crow = off + r;
#pragma unroll
            for (int ni = 0; ni < 4; ni++) {
                int c = nW + ni * 8 + (lane & 3) * 2;
                float gv0 = accG[mi][ni][2 * hf + 0];
                float gv1 = accG[mi][ni][2 * hf + 1];
                float uv0 = accU[mi][ni][2 * hf + 0];
                float uv1 = accU[mi][ni][2 * hf + 1];
                float he0 = (gv0 / (1.f + __expf(-gv0))) * uv0;
                float he1 = (gv1 / (1.f + __expf(-gv1))) * uv1;
                *(__half2*)(He + (size_t)crow * Ff + c) = __floats2half2_rn(he0, he1);
            }
        }
    }
}

// ---------------------------------------------------------------------------
// RoPE: rotate q/k; emit q fp16 hi/lo (pre-scaled 1/8), k fp32 + fp16, v fp16.
// ---------------------------------------------------------------------------
__global__ void rope_kernel(const float* __restrict__ cosb,
                            const float* __restrict__ sinb,
                            const float* __restrict__ q,
                            const float* __restrict__ k,
                            float* __restrict__ outk,
                            const float* __restrict__ vin,
                            __half* __restrict__ qh, __half* __restrict__ ql,
                            __half* __restrict__ kh, __half* __restrict__ vh) {
    int t = blockIdx.x;
    int s = t % Ss;
    const float* cs = cosb + (size_t)s * HDd;
    const float* sn = sinb + (size_t)s * HDd;

    const float* qrow = q + (size_t)t * QD;
    for (int idx = threadIdx.x; idx < Hh * 32; idx += blockDim.x) {
        int hh = idx >> 5, d = idx & 31;
        float a = qrow[hh * HDd + d], b2 = qrow[hh * HDd + d + 32];
        float o1 = (a * cs[d] - b2 * sn[d]) * 0.125f;
        float o2 = (b2 * cs[d + 32] + a * sn[d + 32]) * 0.125f;
        size_t base = (size_t)t * QD + hh * HDd;
        __half h1 = __float2half_rn(o1);
        __half h2 = __float2half_rn(o2);
        qh[base + d] = h1;      ql[base + d] = __float2half_rn(o1 - __half2float(h1));
        qh[base + d + 32] = h2; ql[base + d + 32] = __float2half_rn(o2 - __half2float(h2));
    }
    const float* krow = k + (size_t)t * KD;
    for (int idx = threadIdx.x; idx < KVh * 32; idx += blockDim.x) {
        int hh = idx >> 5, d = idx & 31;
        float a = krow[hh * HDd + d], b2 = krow[hh * HDd + d + 32];
        float o1 = a * cs[d] - b2 * sn[d];
        float o2 = b2 * cs[d + 32] + a * sn[d + 32];
        size_t base = (size_t)t * KD + hh * HDd;
        outk[base + d] = o1;      outk[base + d + 32] = o2;
        kh[base + d] = __float2half_rn(o1);
        kh[base + d + 32] = __float2half_rn(o2);
    }
    for (int idx = threadIdx.x; idx < KD; idx += blockDim.x) {
        vh[(size_t)t * KD + idx] = __float2half_rn(vin[(size_t)t * KD + idx]);
    }
}

// ---------------------------------------------------------------------------
// FA2-style causal GQA attention on mma.sync.
// ---------------------------------------------------------------------------
__global__ void __launch_bounds__(256, 1)
attn_mma_kernel(const __half* __restrict__ qh, const __half* __restrict__ ql,
                const __half* __restrict__ kh, const __half* __restrict__ vh,
                __half* __restrict__ ohi) {
    extern __shared__ char smem[];
    int b = blockIdx.z, h = blockIdx.y, qt = blockIdx.x;
    int kvh = h >> 2;
    int tid = threadIdx.x, lane = tid & 31, wid = tid >> 5;
    int qrow0 = qt * 128;
    uint32_t sb = smem_u32(smem);

    {
        const __half* qsh = qh + ((size_t)(b * Ss + qrow0)) * QD + h * HDd;
        const __half* qsl = ql + ((size_t)(b * Ss + qrow0)) * QD + h * HDd;
#pragma unroll
        for (int i = 0; i < 4; i++) {
            int c = tid + 256 * i;
            int row = c >> 3, u = c & 7;
            CP16(sb + row * AROW + u * 16, qsh + (size_t)row * QD + u * 8);
            CP16(sb + ASTAGE + row * AROW + u * 16, qsl + (size_t)row * QD + u * 8);
        }
        CP_COMMIT(); CP_WAIT(0);
    }
    __syncthreads();

    int wr = wid * 16;
    uint32_t qfh[4][4], qfl[4][4];
    {
        uint32_t qa = sb + (wr + (lane & 15)) * AROW + (lane >> 4) * 16;
#pragma unroll
        for (int kc = 0; kc < 4; kc++) {
            ldsm_x4(qfh[kc], qa + kc * 32);
            ldsm_x4(qfl[kc], qa + kc * 32 + ASTAGE);
        }
    }
    __syncthreads();

    float o[8][4];
#pragma unroll
    for (int i = 0; i < 8; i++)
#pragma unroll
        for (int j = 0; j < 4; j++) o[i][j] = 0.f;
    float m0 = -1e30f, m1 = -1e30f, l0 = 0.f, l1 = 0.f;

    const __half* kbase = kh + ((size_t)(b * Ss)) * KD + kvh * HDd;
    const __half* vbase = vh + ((size_t)(b * Ss)) * KD + kvh * HDd;

    int ntiles = (qt + 1) * 2;
    {
#pragma unroll
        for (int i = 0; i < 2; i++) {
            int c = tid + 256 * i;
            int row = c >> 3, u = c & 7;
            CP16(sb + row * AROW + u * 16, kbase + (size_t)row * KD + u * 8);
            CP16(sb + ATILE + row * AROW + u * 16, vbase + (size_t)row * KD + u * 8);
        }
        CP_COMMIT();
    }

    for (int t = 0; t < ntiles; t++) {
        int k0 = t * 64;
        if (t + 1 < ntiles) {
            uint32_t dbuf = sb + ((t + 1) & 1) * ASTAGE;
            const __half* kb = kbase + (size_t)(k0 + 64) * KD;
            const __half* vb = vbase + (size_t)(k0 + 64) * KD;
#pragma unroll
            for (int i = 0; i < 2; i++) {
                int c = tid + 256 * i;
                int row = c >> 3, u = c & 7;
                CP16(dbuf + row * AROW + u * 16, kb + (size_t)row * KD + u * 8);
                CP16(dbuf + ATILE + row * AROW + u * 16, vb + (size_t)row * KD + u * 8);
            }
            CP_COMMIT(); CP_WAIT(1);
        } else {
            CP_WAIT(0);
        }
        __syncthreads();
        uint32_t kb0 = sb + (t & 1) * ASTAGE;
        uint32_t vb0 = kb0 + ATILE;

        float s[8][4];
#pragma unroll
        for (int nc16 = 0; nc16 < 4; nc16++) {
            uint32_t bk[4][4];
            uint32_t baddr = kb0 + (nc16 * 16 + (lane & 7) + ((lane >> 4) & 1) * 8) * AROW
                           + ((lane >> 3) & 1) * 16;
#pragma unroll
            for (int kc = 0; kc < 4; kc++) ldsm_x4(bk[kc], baddr + kc * 32);
#pragma unroll
            for (int j = 0; j < 2; j++) {
                int nc = nc16 * 2 + j;
                s[nc][0] = s[nc][1] = s[nc][2] = s[nc][3] = 0.f;
#pragma unroll
                for (int kc = 0; kc < 4; kc++) {
                    mma_fp16(s[nc], qfh[kc], &bk[kc][2 * j]);
                    mma_fp16(s[nc], qfl[kc], &bk[kc][2 * j]);
                }
            }
        }
        if (k0 + 63 > qrow0 + wr) {
            int row0 = qrow0 + wr + (lane >> 2);
            int colb = k0 + (lane & 3) * 2;
#pragma unroll
            for (int nc = 0; nc < 8; nc++) {
                int c0 = colb + nc * 8, c1 = c0 + 1;
                if (c0 > row0)     s[nc][0] = -1e9f;
                if (c1 > row0)     s[nc][1] = -1e9f;
                if (c0 > row0 + 8) s[nc][2] = -1e9f;
                if (c1 > row0 + 8) s[nc][3] = -1e9f;
            }
        }
        float mx0 = -1e30f, mx1 = -1e30f;
#pragma unroll
        for (int nc = 0; nc < 8; nc++) {
            mx0 = fmaxf(mx0, fmaxf(s[nc][0], s[nc][1]));
            mx1 = fmaxf(mx1, fmaxf(s[nc][2], s[nc][3]));
        }
        mx0 = fmaxf(mx0, __shfl_xor_sync(0xffffffffu, mx0, 1));
        mx0 = fmaxf(mx0, __shfl_xor_sync(0xffffffffu, mx0, 2));
        mx1 = fmaxf(mx1, __shfl_xor_sync(0xffffffffu, mx1, 1));
        mx1 = fmaxf(mx1, __shfl_xor_sync(0xffffffffu, mx1, 2));
        float mn0 = fmaxf(m0, mx0), mn1 = fmaxf(m1, mx1);
        float cr0 = __expf(m0 - mn0), cr1 = __expf(m1 - mn1);
        m0 = mn0; m1 = mn1;
        float sum0 = 0.f, sum1 = 0.f;
#pragma unroll
        for (int nc = 0; nc < 8; nc++) {
            s[nc][0] = __expf(s[nc][0] - m0);
            s[nc][1] = __expf(s[nc][1] - m0);
            s[nc][2] = __expf(s[nc][2] - m1);
            s[nc][3] = __expf(s[nc][3] - m1);
            sum0 += s[nc][0] + s[nc][1];
            sum1 += s[nc][2] + s[nc][3];
        }
        sum0 += __shfl_xor_sync(0xffffffffu, sum0, 1);
        sum0 += __shfl_xor_sync(0xffffffffu, sum0, 2);
        sum1 += __shfl_xor_sync(0xffffffffu, sum1, 1);
        sum1 += __shfl_xor_sync(0xffffffffu, sum1, 2);
        l0 = l0 * cr0 + sum0;
        l1 = l1 * cr1 + sum1;
#pragma unroll
        for (int nc = 0; nc < 8; nc++) {
            o[nc][0] *= cr0; o[nc][1] *= cr0;
            o[nc][2] *= cr1; o[nc][3] *= cr1;
        }
        uint32_t pa[4][4];
#pragma unroll
        for (int kc = 0; kc < 4; kc++) {
            pa[kc][0] = packh2(s[2 * kc][0],     s[2 * kc][1]);
            pa[kc][1] = packh2(s[2 * kc][2],     s[2 * kc][3]);
            pa[kc][2] = packh2(s[2 * kc + 1][0], s[2 * kc + 1][1]);
            pa[kc][3] = packh2(s[2 * kc + 1][2], s[2 * kc + 1][3]);
        }
#pragma unroll
        for (int kc = 0; kc < 4; kc++) {
            uint32_t baddr = vb0 + (kc * 16 + (lane & 7) + ((lane >> 3) & 1) * 8) * AROW
                           + ((lane >> 4) & 1) * 16;
#pragma unroll
            for (int n16 = 0; n16 < 4; n16++) {
                uint32_t t4[4];
                ldsm_x4_t(t4, baddr + n16 * 32);
                mma_fp16(o[n16 * 2],     pa[kc], &t4[0]);
                mma_fp16(o[n16 * 2 + 1], pa[kc], &t4[2]);
            }
        }
        __syncthreads();
    }

    float inv0 = 1.f / l0, inv1 = 1.f / l1;
    int row0 = qrow0 + wr + (lane >> 2);
#pragma unroll
    for (int nc = 0; nc < 8; nc++) {
        int col = h * HDd + nc * 8 + (lane & 3) * 2;
        float v0 = o[nc][0] * inv0, v1 = o[nc][1] * inv0;
        float v2 = o[nc][2] * inv1, v3 = o[nc][3] * inv1;
        size_t o0 = (size_t)(b * Ss + row0) * QD + col;
        size_t o1 = (size_t)(b * Ss + row0 + 8) * QD + col;
        *(__half2*)(ohi + o0) = __floats2half2_rn(v0, v1);
        *(__half2*)(ohi + o1) = __floats2half2_rn(v2, v3);
    }
}

// ---------------------------------------------------------------------------
// Router + compacted slot assignment
// ---------------------------------------------------------------------------
__global__ void zero_cnt_kernel() {
    if (threadIdx.x < Ee) g_cnt[threadIdx.x] = 0;
}

__global__ void router_kernel(const float* __restrict__ y,
                              const float* __restrict__ rw) {
    int t = (blockIdx.x * blockDim.x + threadIdx.x) >> 5;
    int lane = threadIdx.x & 31;
    if (t >= NT) return;
    const float* yrow = y + (size_t)t * Dd;
    float logits[8] = {};
    for (int i = 0; i < 32; i++) {
        int d = i * 32 + lane;
        float yv = yrow[d];
#pragma unroll
        for (int e = 0; e < 8; e++) logits[e] += yv * rw[d * 8 + e];
    }
#pragma unroll
    for (int e = 0; e < 8; e++) {
#pragma unroll
        for (int o = 16; o > 0; o >>= 1)
            logits[e] += __shfl_xor_sync(0xffffffffu, logits[e], o);
    }
    if (lane == 0) {
        int i0 = 0; float v0 = logits[0];
#pragma unroll
        for (int e = 1; e < 8; e++) if (logits[e] > v0) { v0 = logits[e]; i0 = e; }
        int i1 = -1; float v1 = -1e30f;
#pragma unroll
        for (int e = 0; e < 8; e++)
            if (e != i0 && logits[e] > v1) { v1 = logits[e]; i1 = e; }
        float e1 = __expf(v1 - v0);
        g_texp[t * 2 + 0] = i0;
        g_texp[t * 2 + 1] = i1;
        g_gw[t * 2 + 0] = 1.f / (1.f + e1);
        g_gw[t * 2 + 1] = e1 / (1.f + e1);
        atomicAdd(&g_cnt[i0], 1);
        atomicAdd(&g_cnt[i1], 1);
    }
}

__global__ void offsets_kernel() {
    if (threadIdx.x == 0) {
        int a = 0;
        for (int e = 0; e < Ee; e++) { g_off[e] = a; a += g_cnt[e]; g_fill[e] = 0; }
    }
}

__global__ void scatter_kernel() {
    int t = blockIdx.x * blockDim.x + threadIdx.x;
    if (t >= NT) return;
#pragma unroll
    for (int j = 0; j < 2; j++) {
        int e = g_texp[t * 2 + j];
        int p = atomicAdd(&g_fill[e], 1);
        int slot = g_off[e] + p;
        g_list[slot] = t;
        g_slot[t * 2 + j] = slot;
    }
}

// ---------------------------------------------------------------------------
// out = h + w0 * down[slot0] + w1 * down[slot1]   (dn in fp16)
// ---------------------------------------------------------------------------
__global__ void combine_kernel(float* __restrict__ out) {
    int t = blockIdx.x;
    int d = (blockIdx.y * 256 + threadIdx.x) * 2;
    int s0 = g_slot[t * 2], s1 = g_slot[t * 2 + 1];
    float w0 = g_gw[t * 2], w1 = g_gw[t * 2 + 1];
    size_t o = (size_t)t * Dd + d;
    float2 hv = *(const float2*)(g_h + o);
    __half2 d0 = *(const __half2*)(g_dnh + (size_t)s0 * Dd + d);
    __half2 d1 = *(const __half2*)(g_dnh + (size_t)s1 * Dd + d);
    float2 f0 = __half22float2(d0);
    float2 f1 = __half22float2(d1);
    float2 r;
    r.x = hv.x + w0 * f0.x + w1 * f1.x;
    r.y = hv.y + w0 * f0.y + w1 * f1.y;
    *(float2*)(out + o) = r;
}

// ---------------------------------------------------------------------------
// Launch
// ---------------------------------------------------------------------------
extern "C" void kernel_launch(void* const* d_in, const int* in_sizes, int n_in,
                              void* d_out, int out_size) {
    const float* input  = (const float*)d_in[0];
    const float* cosb   = (const float*)d_in[1];
    const float* sinb   = (const float*)d_in[2];
    // d_in[3] = mask (causal, unused)
    const float* w_attn = (const float*)d_in[4];
    const float* w_moe  = (const float*)d_in[5];
    const float* Wq     = (const float*)d_in[6];
    const float* Wk     = (const float*)d_in[7];
    const float* Wv     = (const float*)d_in[8];
    const float* Wo     = (const float*)d_in[9];
    const float* rw     = (const float*)d_in[10];
    const float* Wg     = (const float*)d_in[11];
    const float* Wu     = (const float*)d_in[12];
    const float* Wd     = (const float*)d_in[13];

    cudaFuncSetAttribute(mma_gemm,   cudaFuncAttributeMaxDynamicSharedMemorySize, GS2);
    cudaFuncSetAttribute(mma_gateup, cudaFuncAttributeMaxDynamicSharedMemorySize, GSD);

    float *pq, *pk, *pvs, *pks, *ph, *py;
    cudaGetSymbolAddress((void**)&pq,  g_q);
    cudaGetSymbolAddress((void**)&pk,  g_k);
    cudaGetSymbolAddress((void**)&pvs, g_vscr);
    cudaGetSymbolAddress((void**)&pks, g_kscr);
    cudaGetSymbolAddress((void**)&ph,  g_h);
    cudaGetSymbolAddress((void**)&py,  g_y);

    __half *xhi, *ahi, *yhi, *hehi, *dnh;
    __half *qh2, *ql2, *kh2, *vh2;
    __half *wqkv, *wo, *wg, *wu, *wd;
    cudaGetSymbolAddress((void**)&xhi, g_xhi);
    cudaGetSymbolAddress((void**)&ahi, g_ahi);
    cudaGetSymbolAddress((void**)&yhi, g_yhi);
    cudaGetSymbolAddress((void**)&hehi, g_hehi);
    cudaGetSymbolAddress((void**)&dnh, g_dnh);
    cudaGetSymbolAddress((void**)&qh2, g_qh2);  cudaGetSymbolAddress((void**)&ql2, g_ql2);
    cudaGetSymbolAddress((void**)&kh2, g_kh2);  cudaGetSymbolAddress((void**)&vh2, g_vh2);
    cudaGetSymbolAddress((void**)&wqkv, g_wqkv);
    cudaGetSymbolAddress((void**)&wo, g_wo);
    cudaGetSymbolAddress((void**)&wg, g_wg);
    cudaGetSymbolAddress((void**)&wu, g_wu);
    cudaGetSymbolAddress((void**)&wd, g_wd);

    float* out = (float*)d_out;
    size_t need = (size_t)NT * Dd + 2 * (size_t)NT * KD;
    bool full = ((size_t)out_size >= need);
    float* outk = full ? (out + (size_t)NT * Dd) : pks;
    float* outv = full ? (out + (size_t)NT * Dd + (size_t)NT * KD) : pvs;

    dim3 tb(32, 8);
    // weight transposes (fp16, [N,K]); wq/wk/wv concatenated into wqkv
    transpose_half_kernel<<<dim3(QD / 32, Dd / 32, 1),  tb>>>(Wq, wqkv, Dd, QD);
    transpose_half_kernel<<<dim3(KD / 32, Dd / 32, 1),  tb>>>(Wk, wqkv + (size_t)QD * Dd, Dd, KD);
    transpose_half_kernel<<<dim3(KD / 32, Dd / 32, 1),  tb>>>(Wv, wqkv + (size_t)(QD + KD) * Dd, Dd, KD);
    transpose_half_kernel<<<dim3(Dd / 32, QD / 32, 1),  tb>>>(Wo, wo, QD, Dd);
    transpose_half_kernel<<<dim3(Ff / 32, Dd / 32, Ee), tb>>>(Wg, wg, Dd, Ff);
    transpose_half_kernel<<<dim3(Ff / 32, Dd / 32, Ee), tb>>>(Wu, wu, Dd, Ff);
    transpose_half_kernel<<<dim3(Dd / 32, Ff / 32, Ee), tb>>>(Wd, wd, Ff, Dd);

    // 1. x = rmsnorm(input) -> fp16
    rmsnorm_kernel<<<NT, 256>>>(input, w_attn, xhi, nullptr);
    // 2. fused QKV projection (epilogue routes q/k/v)
    mma_gemm<<<dim3(QKVN / 128, NT / 128, 1), 256, GS2>>>(
        xhi, wqkv, 0, pq, nullptr, pk, outv, nullptr, 0, NT, QKVN, Dd);
    // 3. RoPE -> fp16 q (hi/lo, scaled), fp32 k out, fp16 k/v
    rope_kernel<<<NT, 256>>>(cosb, sinb, pq, pk, outk, outv, qh2, ql2, kh2, vh2);
    // 4. attention (mma.sync) -> fp16 output
    attn_mma_kernel<<<dim3(Ss / 128, Hh, Bb), 256, ASMEM>>>(
        qh2, ql2, kh2, vh2, ahi);
    // 5. h = input + attn @ Wo
    mma_gemm<<<dim3(Dd / 128, NT / 128, 1), 256, GS2>>>(
        ahi, wo, 0, ph, input, nullptr, nullptr, nullptr, 0, NT, Dd, QD);
    // 6. y = rmsnorm(h) -> fp16 + f32
    rmsnorm_kernel<<<NT, 256>>>(ph, w_moe, yhi, py);
    // 7. router + compact slots
    zero_cnt_kernel<<<1, 32>>>();
    router_kernel<<<NT / 8, 256>>>(py, rw);
    offsets_kernel<<<1, 32>>>();
    scatter_kernel<<<NT / 256, 256>>>();
    // 8. fused gate+up GEMM with silu epilogue -> fp16 he
    mma_gateup<<<dim3(Ff / 64, NT / 128, Ee), 256, GSD>>>(
        yhi, wg, wu, (size_t)Ff * Dd, hehi, Dd);
    // 9. down projection (contiguous slot rows) -> fp16 dn
    mma_gemm<<<dim3(Dd / 128, NT / 128, Ee), 256, GS2>>>(
        hehi, wd, (size_t)Dd * Ff, nullptr, nullptr, nullptr, nullptr, dnh,
        2, NT, Dd, Ff);
    // 10. combine
    combine_kernel<<<dim3(NT, Dd / 512), 256>>>(out);
}

// round 15
// speedup vs baseline: 4.9759x; 1.0306x over previous
#include <cuda_runtime.h>
#include <cuda_fp16.h>
#include <cstdint>

// ---------------------------------------------------------------------------
// MoE transformer block. fp16 warp-MMA GEMMs (fused QKV, fused gate+up+silu)
// + FA2 attention (1-term Q). B=4 S=2048 D=1024 H=16 KV=4 HD=64 E=8 K=2 F=1024
// Base sm_103 PTX only: mma.sync / ldmatrix / cp.async.
// ---------------------------------------------------------------------------

namespace {
constexpr int Bb  = 4;
constexpr int Ss  = 2048;
constexpr int Dd  = 1024;
constexpr int Hh  = 16;
constexpr int KVh = 4;
constexpr int HDd = 64;
constexpr int Ee  = 8;
constexpr int TKk = 2;
constexpr int Ff  = 1024;
constexpr int NT  = Bb * Ss;        // 8192 tokens
constexpr int QD  = Hh * HDd;       // 1024
constexpr int KD  = KVh * HDd;      // 256
constexpr int QKVN = QD + 2 * KD;   // 1536
constexpr int NSLOT = NT * TKk;     // 16384 expert slots

// GEMM tiling
constexpr int ROWB   = 80;                // smem row stride bytes (32 fp16 + pad)
constexpr int TILEB  = 128 * ROWB;        // 128x32 fp16 tile = 10240 B
constexpr int TILEBB = 64 * ROWB;         // 64x32 fp16 tile  = 5120 B
constexpr int GS2    = 3 * 2 * TILEB;     // gemm: 3 stages x (A,B) = 61440
constexpr int DSTAGE = TILEB + 2 * TILEBB;            // A + Bg + Bu = 20480
constexpr int GSD    = 3 * DSTAGE;                    // 61440

// Attention smem
constexpr int AROW   = 144;
constexpr int ATILE  = 64 * AROW;
constexpr int ASTAGE = 2 * ATILE;
constexpr int ASMEM  = 2 * ASTAGE;        // 36864 (Q staging reuses buf 0)
}

__device__ __forceinline__ uint32_t smem_u32(const void* p) {
    uint32_t a;
    asm("{ .reg .u64 t; cvta.to.shared.u64 t, %1; cvt.u32.u64 %0, t; }" : "=r"(a) : "l"(p));
    return a;
}
#define CP16(dst, src) asm volatile( \
    "cp.async.cg.shared.global [%0], [%1], 16;" :: "r"(dst), "l"(src))
#define CP_COMMIT() asm volatile("cp.async.commit_group;" ::: "memory")
#define CP_WAIT(n)  asm volatile("cp.async.wait_group %0;" :: "n"(n) : "memory")

__device__ __forceinline__ void ldsm_x4(uint32_t* r, uint32_t addr) {
    asm volatile("ldmatrix.sync.aligned.m8n8.x4.shared.b16 {%0,%1,%2,%3}, [%4];"
                 : "=r"(r[0]), "=r"(r[1]), "=r"(r[2]), "=r"(r[3]) : "r"(addr));
}
__device__ __forceinline__ void ldsm_x4_t(uint32_t* r, uint32_t addr) {
    asm volatile("ldmatrix.sync.aligned.m8n8.x4.trans.shared.b16 {%0,%1,%2,%3}, [%4];"
                 : "=r"(r[0]), "=r"(r[1]), "=r"(r[2]), "=r"(r[3]) : "r"(addr));
}
__device__ __forceinline__ void mma_fp16(float* c, const uint32_t* a, const uint32_t* b) {
    asm volatile(
        "mma.sync.aligned.m16n8k16.row.col.f32.f16.f16.f32 "
        "{%0,%1,%2,%3}, {%4,%5,%6,%7}, {%8,%9}, {%0,%1,%2,%3};"
        : "+f"(c[0]), "+f"(c[1]), "+f"(c[2]), "+f"(c[3])
        : "r"(a[0]), "r"(a[1]), "r"(a[2]), "r"(a[3]), "r"(b[0]), "r"(b[1]));
}
__device__ __forceinline__ uint32_t packh2(float a, float b) {
    __half2 h = __floats2half2_rn(a, b);
    return *reinterpret_cast<uint32_t*>(&h);
}

// ---------------------------------------------------------------------------
// Scratch
// ---------------------------------------------------------------------------
__device__ __align__(128) float g_q[(size_t)NT * QD];
__device__ __align__(128) float g_k[(size_t)NT * KD];
__device__ __align__(128) float g_vscr[(size_t)NT * KD];
__device__ __align__(128) float g_kscr[(size_t)NT * KD];
__device__ __align__(128) float g_h[(size_t)NT * Dd];
__device__ __align__(128) float g_y[(size_t)NT * Dd];
__device__ __align__(128) __half g_dnh[(size_t)NSLOT * Dd];

__device__ __align__(128) __half g_xhi[(size_t)NT * Dd];
__device__ __align__(128) __half g_ahi[(size_t)NT * QD];
__device__ __align__(128) __half g_yhi[(size_t)NT * Dd];
__device__ __align__(128) __half g_hehi[(size_t)NSLOT * Ff];

// fp16 q (pre-scaled 1/8) and k/v for attention
__device__ __align__(128) __half g_qh2[(size_t)NT * QD];
__device__ __align__(128) __half g_kh2[(size_t)NT * KD];
__device__ __align__(128) __half g_vh2[(size_t)NT * KD];

// transposed fp16 weights [N, K]
__device__ __align__(128) __half g_wqkv[(size_t)QKVN * Dd];
__device__ __align__(128) __half g_wo[(size_t)Dd * QD];
__device__ __align__(128) __half g_wg[(size_t)Ee * Ff * Dd];
__device__ __align__(128) __half g_wu[(size_t)Ee * Ff * Dd];
__device__ __align__(128) __half g_wd[(size_t)Ee * Dd * Ff];

__device__ int   g_cnt[Ee];
__device__ int   g_off[Ee];
__device__ int   g_fill[Ee];
__device__ int   g_list[NSLOT];
__device__ int   g_slot[NSLOT];
__device__ int   g_texp[NSLOT];
__device__ float g_gw[NSLOT];

// ---------------------------------------------------------------------------
// RMSNorm -> fp16 hi (+optional f32)
// ---------------------------------------------------------------------------
__global__ void rmsnorm_kernel(const float* __restrict__ in,
                               const float* __restrict__ w,
                               __half* __restrict__ ohi,
                               float* __restrict__ of32) {
    int t = blockIdx.x;
    const float* row = in + (size_t)t * Dd;
    float ss = 0.f;
#pragma unroll
    for (int i = 0; i < 4; i++) { float v = row[threadIdx.x + i * 256]; ss += v * v; }
#pragma unroll
    for (int o = 16; o > 0; o >>= 1) ss += __shfl_xor_sync(0xffffffffu, ss, o);
    __shared__ float sred[8];
    if ((threadIdx.x & 31) == 0) sred[threadIdx.x >> 5] = ss;
    __syncthreads();
    if (threadIdx.x < 32) {
        float v = (threadIdx.x < 8) ? sred[threadIdx.x] : 0.f;
#pragma unroll
        for (int o = 4; o > 0; o >>= 1) v += __shfl_xor_sync(0xffffffffu, v, o);
        if (threadIdx.x == 0) sred[0] = v;
    }
    __syncthreads();
    float inv = rsqrtf(sred[0] * (1.f / Dd) + 1e-6f);
    size_t base = (size_t)t * Dd;
#pragma unroll
    for (int i = 0; i < 4; i++) {
        int d = threadIdx.x + i * 256;
        float r = row[d] * inv * w[d];
        ohi[base + d] = __float2half_rn(r);
        if (of32) of32[base + d] = r;
    }
}

// ---------------------------------------------------------------------------
// Transpose: W[K,N] fp32 -> T[N,K] fp16. 64x64 tiles, vectorized (MLP=16).
// Block (32,8).
// ---------------------------------------------------------------------------
__global__ void transpose_half_kernel(const float* __restrict__ W,
                                      __half* __restrict__ T,
                                      int K, int N) {
    __shared__ float tile[64][65];
    size_t zb = (size_t)blockIdx.z * K * N;
    int k0 = blockIdx.y * 64, n0 = blockIdx.x * 64;
    int tx = threadIdx.x, ty = threadIdx.y;
#pragma unroll
    for (int j = 0; j < 8; j++) {
        float2 v = *(const float2*)&W[zb + (size_t)(k0 + ty + 8 * j) * N + n0 + tx * 2];
        tile[ty + 8 * j][tx * 2]     = v.x;
        tile[ty + 8 * j][tx * 2 + 1] = v.y;
    }
    __syncthreads();
#pragma unroll
    for (int j = 0; j < 8; j++) {
        int n = ty + 8 * j;
        __half2 h = __floats2half2_rn(tile[tx * 2][n], tile[tx * 2 + 1][n]);
        *(__half2*)&T[zb + (size_t)(n0 + n) * K + k0 + tx * 2] = h;
    }
}

// ---------------------------------------------------------------------------
// Warp-MMA GEMM (1-term): C[M,N] = A@B, fp32 accum, 3-stage cp.async.
// A [M,K] fp16 K-major; B [N,K] fp16 K-major.
// Epilogue variants:
//  - Ck != null: QKV split (N=1536): cols [0,1024)->C f32 stride 1024,
//    [1024,1280)->Ck f32 stride 256, [1280,1536)->Cv f32 stride 256.
//  - Chi != null: fp16 output (stride N).
//  - else: f32 C (+addsrc).
// mode 0: plain; mode 1: A rows via g_list[off+r], C rows off+r;
// mode 2: A/C rows at off+r. (off=g_off[z], Meff=g_cnt[z])
// ---------------------------------------------------------------------------
__global__ void __launch_bounds__(256, 1)
mma_gemm(const __half* __restrict__ Ah,
         const __half* __restrict__ Bw, size_t bz,
         float* __restrict__ C, const float* __restrict__ addsrc,
         float* __restrict__ Ck, float* __restrict__ Cv,
         __half* __restrict__ Chi,
         int mode, int M, int N, int K) {
    extern __shared__ char smem[];
    int z = blockIdx.z;
    int Meff = M, off = 0;
    if (mode) { Meff = g_cnt[z]; off = g_off[z]; }
    int m0 = blockIdx.y * 128;
    if (m0 >= Meff) return;
    int n0 = blockIdx.x * 128;
    const __half* bw = Bw + bz * z;

    int tid = threadIdx.x, lane = tid & 31, wid = tid >> 5;
    uint32_t sb = smem_u32(smem);

    int lrow = tid >> 1;
    int lcolh = (tid & 1) * 16;
    int ar = m0 + lrow;
    long grow;
    if (mode == 1) { int rr = (ar < Meff) ? ar : (Meff - 1); grow = g_list[off + rr]; }
    else if (mode == 2) { int rr = (ar < Meff) ? ar : (Meff - 1); grow = off + rr; }
    else grow = ar;
    const __half* pA = Ah + (size_t)grow * K + lcolh;
    const __half* pB = bw + (size_t)(n0 + lrow) * K + lcolh;
    uint32_t dstrel = (uint32_t)(lrow * ROWB + lcolh * 2);

    float acc[4][4][4];
#pragma unroll
    for (int i = 0; i < 4; i++)
#pragma unroll
        for (int j = 0; j < 4; j++)
#pragma unroll
            for (int q = 0; q < 4; q++) acc[i][j][q] = 0.f;

    const int NS = K / 32;
    auto load_stage = [&](int s) {
        size_t ko = (size_t)s * 32;
        uint32_t d = sb + (s % 3) * (2 * TILEB) + dstrel;
        CP16(d, pA + ko); CP16(d + 16, pA + ko + 8);
        CP16(d + TILEB, pB + ko); CP16(d + TILEB + 16, pB + ko + 8);
        CP_COMMIT();
    };
    load_stage(0);
    if (NS > 1) load_stage(1);

    uint32_t a_rel = (uint32_t)(((wid & 1) * 64 + (lane & 15)) * ROWB + (lane >> 4) * 16);
    uint32_t b_rel = (uint32_t)(TILEB +
        ((wid >> 1) * 32 + (lane & 7) + ((lane >> 4) & 1) * 8) * ROWB +
        ((lane >> 3) & 1) * 16);

    for (int s = 0; s < NS; s++) {
        if (s + 2 < NS) { load_stage(s + 2); CP_WAIT(2); }
        else if (s + 1 < NS) { CP_WAIT(1); }
        else { CP_WAIT(0); }
        __syncthreads();
        uint32_t base = sb + (s % 3) * (2 * TILEB);
#pragma unroll
        for (int kh = 0; kh < 2; kh++) {
            uint32_t koffb = kh * 32;
            uint32_t ah[4][4];
            uint32_t aaddr = base + a_rel + koffb;
#pragma unroll
            for (int mi = 0; mi < 4; mi++)
                ldsm_x4(ah[mi], aaddr + mi * 16 * ROWB);
            uint32_t bh[4][2];
            uint32_t baddr = base + b_rel + koffb;
#pragma unroll
            for (int hf = 0; hf < 2; hf++) {
                uint32_t t4[4];
                ldsm_x4(t4, baddr + hf * 16 * ROWB);
                bh[2 * hf][0] = t4[0]; bh[2 * hf][1] = t4[1];
                bh[2 * hf + 1][0] = t4[2]; bh[2 * hf + 1][1] = t4[3];
            }
#pragma unroll
            for (int mi = 0; mi < 4; mi++)
#pragma unroll
                for (int ni = 0; ni < 4; ni++)
                    mma_fp16(acc[mi][ni], ah[mi], bh[ni]);
        }
        __syncthreads();
    }

    int mW = m0 + (wid & 1) * 64;
    int nW = n0 + (wid >> 1) * 32;
#pragma unroll
    for (int mi = 0; mi < 4; mi++) {
#pragma unroll
        for (int hf = 0; hf < 2; hf++) {
            int r = mW + mi * 16 + hf * 8 + (lane >> 2);
            if (r >= Meff) continue;
            int crow = mode ? (off + r) : r;
#pragma unroll
            for (int ni = 0; ni < 4; ni++) {
                int c = nW + ni * 8 + (lane & 3) * 2;
                float v0 = acc[mi][ni][2 * hf + 0];
                float v1 = acc[mi][ni][2 * hf + 1];
                if (Ck) {
                    float2 v = {v0, v1};
                    if (c < QD)
                        *(float2*)(C + (size_t)crow * QD + c) = v;
                    else if (c < QD + KD)
                        *(float2*)(Ck + (size_t)crow * KD + (c - QD)) = v;
                    else
                        *(float2*)(Cv + (size_t)crow * KD + (c - QD - KD)) = v;
                } else if (Chi) {
                    *(__half2*)(Chi + (size_t)crow * N + c) = __floats2half2_rn(v0, v1);
                } else {
                    size_t co = (size_t)crow * N + c;
                    if (addsrc) { v0 += addsrc[co]; v1 += addsrc[co + 1]; }
                    float2 v = {v0, v1};
                    *(float2*)(C + co) = v;
                }
            }
        }
    }
}

// ---------------------------------------------------------------------------
// Dual-B GEMM: gate = A@Wg, up = A@Wu; he = silu(gate)*up -> fp16.
// CTA tile 128 x 64 (per output); A gathered rows (mode-1 semantics).
// ---------------------------------------------------------------------------
__global__ void __launch_bounds__(256, 1)
mma_gateup(const __half* __restrict__ Ah,
           const __half* __restrict__ Wg_, const __half* __restrict__ Wu_,
           size_t bz, __half* __restrict__ He, int K) {
    extern __shared__ char smem[];
    int z = blockIdx.z;
    int Meff = g_cnt[z], off = g_off[z];
    int m0 = blockIdx.y * 128;
    if (m0 >= Meff) return;
    int n0 = blockIdx.x * 64;
    const __half* wg = Wg_ + bz * z;
    const __half* wu = Wu_ + bz * z;

    int tid = threadIdx.x, lane = tid & 31, wid = tid >> 5;
    int wm = wid & 3, wn = wid >> 2;
    uint32_t sb = smem_u32(smem);

    int lrow = tid >> 1;
    int lcolh = (tid & 1) * 16;
    int ar = m0 + lrow;
    int rr = (ar < Meff) ? ar : (Meff - 1);
    long grow = g_list[off + rr];
    const __half* pA = Ah + (size_t)grow * K + lcolh;
    uint32_t adst = (uint32_t)(lrow * ROWB + lcolh * 2);
    int brow = tid >> 2;
    int bch = (tid & 3) * 8;
    const __half* pG = wg + (size_t)(n0 + brow) * K + bch;
    const __half* pU = wu + (size_t)(n0 + brow) * K + bch;
    uint32_t bdst = (uint32_t)(brow * ROWB + bch * 2);

    float accG[2][4][4], accU[2][4][4];
#pragma unroll
    for (int i = 0; i < 2; i++)
#pragma unroll
        for (int j = 0; j < 4; j++)
#pragma unroll
            for (int q = 0; q < 4; q++) { accG[i][j][q] = 0.f; accU[i][j][q] = 0.f; }

    const int NS = K / 32;
    auto load_stage = [&](int s) {
        size_t ko = (size_t)s * 32;
        uint32_t d = sb + (s % 3) * DSTAGE;
        CP16(d + adst, pA + ko); CP16(d + adst + 16, pA + ko + 8);
        CP16(d + TILEB + bdst, pG + ko);
        CP16(d + TILEB + TILEBB + bdst, pU + ko);
        CP_COMMIT();
    };
    load_stage(0);
    if (NS > 1) load_stage(1);

    uint32_t a_rel = (uint32_t)((wm * 32 + (lane & 15)) * ROWB + (lane >> 4) * 16);
    uint32_t b_rel = (uint32_t)((wn * 32 + (lane & 7) + ((lane >> 4) & 1) * 8) * ROWB +
                                ((lane >> 3) & 1) * 16);

    for (int s = 0; s < NS; s++) {
        if (s + 2 < NS) { load_stage(s + 2); CP_WAIT(2); }
        else if (s + 1 < NS) { CP_WAIT(1); }
        else { CP_WAIT(0); }
        __syncthreads();
        uint32_t base = sb + (s % 3) * DSTAGE;
#pragma unroll
        for (int kh = 0; kh < 2; kh++) {
            uint32_t koffb = kh * 32;
            uint32_t ah[2][4];
            uint32_t aaddr = base + a_rel + koffb;
#pragma unroll
            for (int mi = 0; mi < 2; mi++)
                ldsm_x4(ah[mi], aaddr + mi * 16 * ROWB);
            uint32_t bg[4][2], bu[4][2];
#pragma unroll
            for (int hf = 0; hf < 2; hf++) {
                uint32_t t4[4];
                ldsm_x4(t4, base + TILEB + b_rel + koffb + hf * 16 * ROWB);
                bg[2 * hf][0] = t4[0]; bg[2 * hf][1] = t4[1];
                bg[2 * hf + 1][0] = t4[2]; bg[2 * hf + 1][1] = t4[3];
                ldsm_x4(t4, base + TILEB + TILEBB + b_rel + koffb + hf * 16 * ROWB);
                bu[2 * hf][0] = t4[0]; bu[2 * hf][1] = t4[1];
                bu[2 * hf + 1][0] = t4[2]; bu[2 * hf + 1][1] = t4[3];
            }
#pragma unroll
            for (int mi = 0; mi < 2; mi++)
#pragma unroll
                for (int ni = 0; ni < 4; ni++) {
                    mma_fp16(accG[mi][ni], ah[mi], bg[ni]);
                    mma_fp16(accU[mi][ni], ah[mi], bu[ni]);
                }
        }
        __syncthreads();
    }

    int mW = m0 + wm * 32;
    int nW = n0 + wn * 32;
#pragma unroll
    for (int mi = 0; mi < 2; mi++) {
#pragma unroll
        for (int hf = 0; hf < 2; hf++) {
            int r = mW + mi * 16 + hf * 8 + (lane >> 2);
            if (r >= Meff) continue;
            int crow = off + r;
#pragma unroll
            for (int ni = 0; ni < 4; ni++) {
                int c = nW + ni * 8 + (lane & 3) * 2;
                float gv0 = accG[mi][ni][2 * hf + 0];
                float gv1 = accG[mi][ni][2 * hf + 1];
                float uv0 = accU[mi][ni][2 * hf + 0];
                float uv1 = accU[mi][ni][2 * hf + 1];
                float he0 = (gv0 / (1.f + __expf(-gv0))) * uv0;
                float he1 = (gv1 / (1.f + __expf(-gv1))) * uv1;
                *(__half2*)(He + (size_t)crow * Ff + c) = __floats2half2_rn(he0, he1);
            }
        }
    }
}

// ---------------------------------------------------------------------------
// RoPE: rotate q/k; emit q fp16 (pre-scaled 1/8), k fp32 + fp16, v fp16.
// ---------------------------------------------------------------------------
__global__ void rope_kernel(const float* __restrict__ cosb,
                            const float* __restrict__ sinb,
                            const float* __restrict__ q,
                            const float* __restrict__ k,
                            float* __restrict__ outk,
                            const float* __restrict__ vin,
                            __half* __restrict__ qh,
                            __half* __restrict__ kh, __half* __restrict__ vh) {
    int t = blockIdx.x;
    int s = t % Ss;
    const float* cs = cosb + (size_t)s * HDd;
    const float* sn = sinb + (size_t)s * HDd;

    const float* qrow = q + (size_t)t * QD;
    for (int idx = threadIdx.x; idx < Hh * 32; idx += blockDim.x) {
        int hh = idx >> 5, d = idx & 31;
        float a = qrow[hh * HDd + d], b2 = qrow[hh * HDd + d + 32];
        float o1 = (a * cs[d] - b2 * sn[d]) * 0.125f;
        float o2 = (b2 * cs[d + 32] + a * sn[d + 32]) * 0.125f;
        size_t base = (size_t)t * QD + hh * HDd;
        qh[base + d] = __float2half_rn(o1);
        qh[base + d + 32] = __float2half_rn(o2);
    }
    const float* krow = k + (size_t)t * KD;
    for (int idx = threadIdx.x; idx < KVh * 32; idx += blockDim.x) {
        int hh = idx >> 5, d = idx & 31;
        float a = krow[hh * HDd + d], b2 = krow[hh * HDd + d + 32];
        float o1 = a * cs[d] - b2 * sn[d];
        float o2 = b2 * cs[d + 32] + a * sn[d + 32];
        size_t base = (size_t)t * KD + hh * HDd;
        outk[base + d] = o1;      outk[base + d + 32] = o2;
        kh[base + d] = __float2half_rn(o1);
        kh[base + d + 32] = __float2half_rn(o2);
    }
    for (int idx = threadIdx.x; idx < KD; idx += blockDim.x) {
        vh[(size_t)t * KD + idx] = __float2half_rn(vin[(size_t)t * KD + idx]);
    }
}

// ---------------------------------------------------------------------------
// FA2-style causal GQA attention on mma.sync (1-term Q).
// ---------------------------------------------------------------------------
__global__ void __launch_bounds__(256, 1)
attn_mma_kernel(const __half* __restrict__ qh,
                const __half* __restrict__ kh, const __half* __restrict__ vh,
                __half* __restrict__ ohi) {
    extern __shared__ char smem[];
    int b = blockIdx.z, h = blockIdx.y, qt = blockIdx.x;
    int kvh = h >> 2;
    int tid = threadIdx.x, lane = tid & 31, wid = tid >> 5;
    int qrow0 = qt * 128;
    uint32_t sb = smem_u32(smem);

    {
        const __half* qsh = qh + ((size_t)(b * Ss + qrow0)) * QD + h * HDd;
#pragma unroll
        for (int i = 0; i < 4; i++) {
            int c = tid + 256 * i;
            int row = c >> 3, u = c & 7;
            CP16(sb + row * AROW + u * 16, qsh + (size_t)row * QD + u * 8);
        }
        CP_COMMIT(); CP_WAIT(0);
    }
    __syncthreads();

    int wr = wid * 16;
    uint32_t qfh[4][4];
    {
        uint32_t qa = sb + (wr + (lane & 15)) * AROW + (lane >> 4) * 16;
#pragma unroll
        for (int kc = 0; kc < 4; kc++)
            ldsm_x4(qfh[kc], qa + kc * 32);
    }
    __syncthreads();

    float o[8][4];
#pragma unroll
    for (int i = 0; i < 8; i++)
#pragma unroll
        for (int j = 0; j < 4; j++) o[i][j] = 0.f;
    float m0 = -1e30f, m1 = -1e30f, l0 = 0.f, l1 = 0.f;

    const __half* kbase = kh + ((size_t)(b * Ss)) * KD + kvh * HDd;
    const __half* vbase = vh + ((size_t)(b * Ss)) * KD + kvh * HDd;

    int ntiles = (qt + 1) * 2;
    {
#pragma unroll
        for (int i = 0; i < 2; i++) {
            int c = tid + 256 * i;
            int row = c >> 3, u = c & 7;
            CP16(sb + row * AROW + u * 16, kbase + (size_t)row * KD + u * 8);
            CP16(sb + ATILE + row * AROW + u * 16, vbase + (size_t)row * KD + u * 8);
        }
        CP_COMMIT();
    }

    for (int t = 0; t < ntiles; t++) {
        int k0 = t * 64;
        if (t + 1 < ntiles) {
            uint32_t dbuf = sb + ((t + 1) & 1) * ASTAGE;
            const __half* kb = kbase + (size_t)(k0 + 64) * KD;
            const __half* vb = vbase + (size_t)(k0 + 64) * KD;
#pragma unroll
            for (int i = 0; i < 2; i++) {
                int c = tid + 256 * i;
                int row = c >> 3, u = c & 7;
                CP16(dbuf + row * AROW + u * 16, kb + (size_t)row * KD + u * 8);
                CP16(dbuf + ATILE + row * AROW + u * 16, vb + (size_t)row * KD + u * 8);
            }
            CP_COMMIT(); CP_WAIT(1);
        } else {
            CP_WAIT(0);
        }
        __syncthreads();
        uint32_t kb0 = sb + (t & 1) * ASTAGE;
        uint32_t vb0 = kb0 + ATILE;

        float s[8][4];
#pragma unroll
        for (int nc16 = 0; nc16 < 4; nc16++) {
            uint32_t bk[4][4];
            uint32_t baddr = kb0 + (nc16 * 16 + (lane & 7) + ((lane >> 4) & 1) * 8) * AROW
                           + ((lane >> 3) & 1) * 16;
#pragma unroll
            for (int kc = 0; kc < 4; kc++) ldsm_x4(bk[kc], baddr + kc * 32);
#pragma unroll
            for (int j = 0; j < 2; j++) {
                int nc = nc16 * 2 + j;
                s[nc][0] = s[nc][1] = s[nc][2] = s[nc][3] = 0.f;
#pragma unroll
                for (int kc = 0; kc < 4; kc++)
                    mma_fp16(s[nc], qfh[kc], &bk[kc][2 * j]);
            }
        }
        if (k0 + 63 > qrow0 + wr) {
            int row0 = qrow0 + wr + (lane >> 2);
            int colb = k0 + (lane & 3) * 2;
#pragma unroll
            for (int nc = 0; nc < 8; nc++) {
                int c0 = colb + nc * 8, c1 = c0 + 1;
                if (c0 > row0)     s[nc][0] = -1e9f;
                if (c1 > row0)     s[nc][1] = -1e9f;
                if (c0 > row0 + 8) s[nc][2] = -1e9f;
                if (c1 > row0 + 8) s[nc][3] = -1e9f;
            }
        }
        float mx0 = -1e30f, mx1 = -1e30f;
#pragma unroll
        for (int nc = 0; nc < 8; nc++) {
            mx0 = fmaxf(mx0, fmaxf(s[nc][0], s[nc][1]));
            mx1 = fmaxf(mx1, fmaxf(s[nc][2], s[nc][3]));
        }
        mx0 = fmaxf(mx0, __shfl_xor_sync(0xffffffffu, mx0, 1));
        mx0 = fmaxf(mx0, __shfl_xor_sync(0xffffffffu, mx0, 2));
        mx1 = fmaxf(mx1, __shfl_xor_sync(0xffffffffu, mx1, 1));
        mx1 = fmaxf(mx1, __shfl_xor_sync(0xffffffffu, mx1, 2));
        float mn0 = fmaxf(m0, mx0), mn1 = fmaxf(m1, mx1);
        float cr0 = __expf(m0 - mn0), cr1 = __expf(m1 - mn1);
        m0 = mn0; m1 = mn1;
        float sum0 = 0.f, sum1 = 0.f;
#pragma unroll
        for (int nc = 0; nc < 8; nc++) {
            s[nc][0] = __expf(s[nc][0] - m0);
            s[nc][1] = __expf(s[nc][1] - m0);
            s[nc][2] = __expf(s[nc][2] - m1);
            s[nc][3] = __expf(s[nc][3] - m1);
            sum0 += s[nc][0] + s[nc][1];
            sum1 += s[nc][2] + s[nc][3];
        }
        sum0 += __shfl_xor_sync(0xffffffffu, sum0, 1);
        sum0 += __shfl_xor_sync(0xffffffffu, sum0, 2);
        sum1 += __shfl_xor_sync(0xffffffffu, sum1, 1);
        sum1 += __shfl_xor_sync(0xffffffffu, sum1, 2);
        l0 = l0 * cr0 + sum0;
        l1 = l1 * cr1 + sum1;
#pragma unroll
        for (int nc = 0; nc < 8; nc++) {
            o[nc][0] *= cr0; o[nc][1] *= cr0;
            o[nc][2] *= cr1; o[nc][3] *= cr1;
        }
        uint32_t pa[4][4];
#pragma unroll
        for (int kc = 0; kc < 4; kc++) {
            pa[kc][0] = packh2(s[2 * kc][0],     s[2 * kc][1]);
            pa[kc][1] = packh2(s[2 * kc][2],     s[2 * kc][3]);
            pa[kc][2] = packh2(s[2 * kc + 1][0], s[2 * kc + 1][1]);
            pa[kc][3] = packh2(s[2 * kc + 1][2], s[2 * kc + 1][3]);
        }
#pragma unroll
        for (int kc = 0; kc < 4; kc++) {
            uint32_t baddr = vb0 + (kc * 16 + (lane & 7) + ((lane >> 3) & 1) * 8) * AROW
                           + ((lane >> 4) & 1) * 16;
#pragma unroll
            for (int n16 = 0; n16 < 4; n16++) {
                uint32_t t4[4];
                ldsm_x4_t(t4, baddr + n16 * 32);
                mma_fp16(o[n16 * 2],     pa[kc], &t4[0]);
                mma_fp16(o[n16 * 2 + 1], pa[kc], &t4[2]);
            }
        }
        __syncthreads();
    }

    float inv0 = 1.f / l0, inv1 = 1.f / l1;
    int row0 = qrow0 + wr + (lane >> 2);
#pragma unroll
    for (int nc = 0; nc < 8; nc++) {
        int col = h * HDd + nc * 8 + (lane & 3) * 2;
        float v0 = o[nc][0] * inv0, v1 = o[nc][1] * inv0;
        float v2 = o[nc][2] * inv1, v3 = o[nc][3] * inv1;
        size_t o0 = (size_t)(b * Ss + row0) * QD + col;
        size_t o1 = (size_t)(b * Ss + row0 + 8) * QD + col;
        *(__half2*)(ohi + o0) = __floats2half2_rn(v0, v1);
        *(__half2*)(ohi + o1) = __floats2half2_rn(v2, v3);
    }
}

// ---------------------------------------------------------------------------
// Router + compacted slot assignment
// ---------------------------------------------------------------------------
__global__ void zero_cnt_kernel() {
    if (threadIdx.x < Ee) g_cnt[threadIdx.x] = 0;
}

__global__ void router_kernel(const float* __restrict__ y,
                              const float* __restrict__ rw) {
    int t = (blockIdx.x * blockDim.x + threadIdx.x) >> 5;
    int lane = threadIdx.x & 31;
    if (t >= NT) return;
    const float* yrow = y + (size_t)t * Dd;
    float logits[8] = {};
    for (int i = 0; i < 32; i++) {
        int d = i * 32 + lane;
        float yv = yrow[d];
#pragma unroll
        for (int e = 0; e < 8; e++) logits[e] += yv * rw[d * 8 + e];
    }
#pragma unroll
    for (int e = 0; e < 8; e++) {
#pragma unroll
        for (int o = 16; o > 0; o >>= 1)
            logits[e] += __shfl_xor_sync(0xffffffffu, logits[e], o);
    }
    if (lane == 0) {
        int i0 = 0; float v0 = logits[0];
#pragma unroll
        for (int e = 1; e < 8; e++) if (logits[e] > v0) { v0 = logits[e]; i0 = e; }
        int i1 = -1; float v1 = -1e30f;
#pragma unroll
        for (int e = 0; e < 8; e++)
            if (e != i0 && logits[e] > v1) { v1 = logits[e]; i1 = e; }
        float e1 = __expf(v1 - v0);
        g_texp[t * 2 + 0] = i0;
        g_texp[t * 2 + 1] = i1;
        g_gw[t * 2 + 0] = 1.f / (1.f + e1);
        g_gw[t * 2 + 1] = e1 / (1.f + e1);
        atomicAdd(&g_cnt[i0], 1);
        atomicAdd(&g_cnt[i1], 1);
    }
}

__global__ void offsets_kernel() {
    if (threadIdx.x == 0) {
        int a = 0;
        for (int e = 0; e < Ee; e++) { g_off[e] = a; a += g_cnt[e]; g_fill[e] = 0; }
    }
}

__global__ void scatter_kernel() {
    int t = blockIdx.x * blockDim.x + threadIdx.x;
    if (t >= NT) return;
#pragma unroll
    for (int j = 0; j < 2; j++) {
        int e = g_texp[t * 2 + j];
        int p = atomicAdd(&g_fill[e], 1);
        int slot = g_off[e] + p;
        g_list[slot] = t;
        g_slot[t * 2 + j] = slot;
    }
}

// ---------------------------------------------------------------------------
// out = h + w0 * down[slot0] + w1 * down[slot1]   (dn in fp16)
// ---------------------------------------------------------------------------
__global__ void combine_kernel(float* __restrict__ out) {
    int t = blockIdx.x;
    int d = (blockIdx.y * 256 + threadIdx.x) * 2;
    int s0 = g_slot[t * 2], s1 = g_slot[t * 2 + 1];
    float w0 = g_gw[t * 2], w1 = g_gw[t * 2 + 1];
    size_t o = (size_t)t * Dd + d;
    float2 hv = *(const float2*)(g_h + o);
    __half2 d0 = *(const __half2*)(g_dnh + (size_t)s0 * Dd + d);
    __half2 d1 = *(const __half2*)(g_dnh + (size_t)s1 * Dd + d);
    float2 f0 = __half22float2(d0);
    float2 f1 = __half22float2(d1);
    float2 r;
    r.x = hv.x + w0 * f0.x + w1 * f1.x;
    r.y = hv.y + w0 * f0.y + w1 * f1.y;
    *(float2*)(out + o) = r;
}

// ---------------------------------------------------------------------------
// Launch
// ---------------------------------------------------------------------------
extern "C" void kernel_launch(void* const* d_in, const int* in_sizes, int n_in,
                              void* d_out, int out_size) {
    const float* input  = (const float*)d_in[0];
    const float* cosb   = (const float*)d_in[1];
    const float* sinb   = (const float*)d_in[2];
    // d_in[3] = mask (causal, unused)
    const float* w_attn = (const float*)d_in[4];
    const float* w_moe  = (const float*)d_in[5];
    const float* Wq     = (const float*)d_in[6];
    const float* Wk     = (const float*)d_in[7];
    const float* Wv     = (const float*)d_in[8];
    const float* Wo     = (const float*)d_in[9];
    const float* rw     = (const float*)d_in[10];
    const float* Wg     = (const float*)d_in[11];
    const float* Wu     = (const float*)d_in[12];
    const float* Wd     = (const float*)d_in[13];

    cudaFuncSetAttribute(mma_gemm,   cudaFuncAttributeMaxDynamicSharedMemorySize, GS2);
    cudaFuncSetAttribute(mma_gateup, cudaFuncAttributeMaxDynamicSharedMemorySize, GSD);

    float *pq, *pk, *pvs, *pks, *ph, *py;
    cudaGetSymbolAddress((void**)&pq,  g_q);
    cudaGetSymbolAddress((void**)&pk,  g_k);
    cudaGetSymbolAddress((void**)&pvs, g_vscr);
    cudaGetSymbolAddress((void**)&pks, g_kscr);
    cudaGetSymbolAddress((void**)&ph,  g_h);
    cudaGetSymbolAddress((void**)&py,  g_y);

    __half *xhi, *ahi, *yhi, *hehi, *dnh;
    __half *qh2, *kh2, *vh2;
    __half *wqkv, *wo, *wg, *wu, *wd;
    cudaGetSymbolAddress((void**)&xhi, g_xhi);
    cudaGetSymbolAddress((void**)&ahi, g_ahi);
    cudaGetSymbolAddress((void**)&yhi, g_yhi);
    cudaGetSymbolAddress((void**)&hehi, g_hehi);
    cudaGetSymbolAddress((void**)&dnh, g_dnh);
    cudaGetSymbolAddress((void**)&qh2, g_qh2);
    cudaGetSymbolAddress((void**)&kh2, g_kh2);  cudaGetSymbolAddress((void**)&vh2, g_vh2);
    cudaGetSymbolAddress((void**)&wqkv, g_wqkv);
    cudaGetSymbolAddress((void**)&wo, g_wo);
    cudaGetSymbolAddress((void**)&wg, g_wg);
    cudaGetSymbolAddress((void**)&wu, g_wu);
    cudaGetSymbolAddress((void**)&wd, g_wd);

    float* out = (float*)d_out;
    size_t need = (size_t)NT * Dd + 2 * (size_t)NT * KD;
    bool full = ((size_t)out_size >= need);
    float* outk = full ? (out + (size_t)NT * Dd) : pks;
    float* outv = full ? (out + (size_t)NT * Dd + (size_t)NT * KD) : pvs;

    dim3 tb(32, 8);
    // weight transposes (fp16, [N,K]); wq/wk/wv concatenated into wqkv
    transpose_half_kernel<<<dim3(QD / 64, Dd / 64, 1),  tb>>>(Wq, wqkv, Dd, QD);
    transpose_half_kernel<<<dim3(KD / 64, Dd / 64, 1),  tb>>>(Wk, wqkv + (size_t)QD * Dd, Dd, KD);
    transpose_half_kernel<<<dim3(KD / 64, Dd / 64, 1),  tb>>>(Wv, wqkv + (size_t)(QD + KD) * Dd, Dd, KD);
    transpose_half_kernel<<<dim3(Dd / 64, QD / 64, 1),  tb>>>(Wo, wo, QD, Dd);
    transpose_half_kernel<<<dim3(Ff / 64, Dd / 64, Ee), tb>>>(Wg, wg, Dd, Ff);
    transpose_half_kernel<<<dim3(Ff / 64, Dd / 64, Ee), tb>>>(Wu, wu, Dd, Ff);
    transpose_half_kernel<<<dim3(Dd / 64, Ff / 64, Ee), tb>>>(Wd, wd, Ff, Dd);

    // 1. x = rmsnorm(input) -> fp16
    rmsnorm_kernel<<<NT, 256>>>(input, w_attn, xhi, nullptr);
    // 2. fused QKV projection (epilogue routes q/k/v)
    mma_gemm<<<dim3(QKVN / 128, NT / 128, 1), 256, GS2>>>(
        xhi, wqkv, 0, pq, nullptr, pk, outv, nullptr, 0, NT, QKVN, Dd);
    // 3. RoPE -> fp16 q (scaled), fp32 k out, fp16 k/v
    rope_kernel<<<NT, 256>>>(cosb, sinb, pq, pk, outk, outv, qh2, kh2, vh2);
    // 4. attention (mma.sync) -> fp16 output
    attn_mma_kernel<<<dim3(Ss / 128, Hh, Bb), 256, ASMEM>>>(qh2, kh2, vh2, ahi);
    // 5. h = input + attn @ Wo
    mma_gemm<<<dim3(Dd / 128, NT / 128, 1), 256, GS2>>>(
        ahi, wo, 0, ph, input, nullptr, nullptr, nullptr, 0, NT, Dd, QD);
    // 6. y = rmsnorm(h) -> fp16 + f32
    rmsnorm_kernel<<<NT, 256>>>(ph, w_moe, yhi, py);
    // 7. router + compact slots
    zero_cnt_kernel<<<1, 32>>>();
    router_kernel<<<NT / 8, 256>>>(py, rw);
    offsets_kernel<<<1, 32>>>();
    scatter_kernel<<<NT / 256, 256>>>();
    // 8. fused gate+up GEMM with silu epilogue -> fp16 he
    mma_gateup<<<dim3(Ff / 64, NT / 128, Ee), 256, GSD>>>(
        yhi, wg, wu, (size_t)Ff * Dd, hehi, Dd);
    // 9. down projection (contiguous slot rows) -> fp16 dn
    mma_gemm<<<dim3(Dd / 128, NT / 128, Ee), 256, GS2>>>(
        hehi, wd, (size_t)Dd * Ff, nullptr, nullptr, nullptr, nullptr, dnh,
        2, NT, Dd, Ff);
    // 10. combine
    combine_kernel<<<dim3(NT, Dd / 512), 256>>>(out);
}

// round 16
// speedup vs baseline: 6.0379x; 1.2134x over previous
#include <cuda_runtime.h>
#include <cuda_fp16.h>
#include <cstdint>

// ---------------------------------------------------------------------------
// MoE transformer block. fp16 warp-MMA GEMMs (fused QKV, fused gate+up+silu)
// + FA2 attention (1-term Q). B=4 S=2048 D=1024 H=16 KV=4 HD=64 E=8 K=2 F=1024
// Base sm_103 PTX only: mma.sync / ldmatrix / cp.async.
// R16: __launch_bounds__(256, 2) on the three MMA kernels (2 CTAs/SM).
// ---------------------------------------------------------------------------

namespace {
constexpr int Bb  = 4;
constexpr int Ss  = 2048;
constexpr int Dd  = 1024;
constexpr int Hh  = 16;
constexpr int KVh = 4;
constexpr int HDd = 64;
constexpr int Ee  = 8;
constexpr int TKk = 2;
constexpr int Ff  = 1024;
constexpr int NT  = Bb * Ss;        // 8192 tokens
constexpr int QD  = Hh * HDd;       // 1024
constexpr int KD  = KVh * HDd;      // 256
constexpr int QKVN = QD + 2 * KD;   // 1536
constexpr int NSLOT = NT * TKk;     // 16384 expert slots

// GEMM tiling
constexpr int ROWB   = 80;                // smem row stride bytes (32 fp16 + pad)
constexpr int TILEB  = 128 * ROWB;        // 128x32 fp16 tile = 10240 B
constexpr int TILEBB = 64 * ROWB;         // 64x32 fp16 tile  = 5120 B
constexpr int GS2    = 3 * 2 * TILEB;     // gemm: 3 stages x (A,B) = 61440
constexpr int DSTAGE = TILEB + 2 * TILEBB;            // A + Bg + Bu = 20480
constexpr int GSD    = 3 * DSTAGE;                    // 61440

// Attention smem
constexpr int AROW   = 144;
constexpr int ATILE  = 64 * AROW;
constexpr int ASTAGE = 2 * ATILE;
constexpr int ASMEM  = 2 * ASTAGE;        // 36864 (Q staging reuses buf 0)
}

__device__ __forceinline__ uint32_t smem_u32(const void* p) {
    uint32_t a;
    asm("{ .reg .u64 t; cvta.to.shared.u64 t, %1; cvt.u32.u64 %0, t; }" : "=r"(a) : "l"(p));
    return a;
}
#define CP16(dst, src) asm volatile( \
    "cp.async.cg.shared.global [%0], [%1], 16;" :: "r"(dst), "l"(src))
#define CP_COMMIT() asm volatile("cp.async.commit_group;" ::: "memory")
#define CP_WAIT(n)  asm volatile("cp.async.wait_group %0;" :: "n"(n) : "memory")

__device__ __forceinline__ void ldsm_x4(uint32_t* r, uint32_t addr) {
    asm volatile("ldmatrix.sync.aligned.m8n8.x4.shared.b16 {%0,%1,%2,%3}, [%4];"
                 : "=r"(r[0]), "=r"(r[1]), "=r"(r[2]), "=r"(r[3]) : "r"(addr));
}
__device__ __forceinline__ void ldsm_x4_t(uint32_t* r, uint32_t addr) {
    asm volatile("ldmatrix.sync.aligned.m8n8.x4.trans.shared.b16 {%0,%1,%2,%3}, [%4];"
                 : "=r"(r[0]), "=r"(r[1]), "=r"(r[2]), "=r"(r[3]) : "r"(addr));
}
__device__ __forceinline__ void mma_fp16(float* c, const uint32_t* a, const uint32_t* b) {
    asm volatile(
        "mma.sync.aligned.m16n8k16.row.col.f32.f16.f16.f32 "
        "{%0,%1,%2,%3}, {%4,%5,%6,%7}, {%8,%9}, {%0,%1,%2,%3};"
        : "+f"(c[0]), "+f"(c[1]), "+f"(c[2]), "+f"(c[3])
        : "r"(a[0]), "r"(a[1]), "r"(a[2]), "r"(a[3]), "r"(b[0]), "r"(b[1]));
}
__device__ __forceinline__ uint32_t packh2(float a, float b) {
    __half2 h = __floats2half2_rn(a, b);
    return *reinterpret_cast<uint32_t*>(&h);
}

// ---------------------------------------------------------------------------
// Scratch
// ---------------------------------------------------------------------------
__device__ __align__(128) float g_q[(size_t)NT * QD];
__device__ __align__(128) float g_k[(size_t)NT * KD];
__device__ __align__(128) float g_vscr[(size_t)NT * KD];
__device__ __align__(128) float g_kscr[(size_t)NT * KD];
__device__ __align__(128) float g_h[(size_t)NT * Dd];
__device__ __align__(128) float g_y[(size_t)NT * Dd];
__device__ __align__(128) __half g_dnh[(size_t)NSLOT * Dd];

__device__ __align__(128) __half g_xhi[(size_t)NT * Dd];
__device__ __align__(128) __half g_ahi[(size_t)NT * QD];
__device__ __align__(128) __half g_yhi[(size_t)NT * Dd];
__device__ __align__(128) __half g_hehi[(size_t)NSLOT * Ff];

// fp16 q (pre-scaled 1/8) and k/v for attention
__device__ __align__(128) __half g_qh2[(size_t)NT * QD];
__device__ __align__(128) __half g_kh2[(size_t)NT * KD];
__device__ __align__(128) __half g_vh2[(size_t)NT * KD];

// transposed fp16 weights [N, K]
__device__ __align__(128) __half g_wqkv[(size_t)QKVN * Dd];
__device__ __align__(128) __half g_wo[(size_t)Dd * QD];
__device__ __align__(128) __half g_wg[(size_t)Ee * Ff * Dd];
__device__ __align__(128) __half g_wu[(size_t)Ee * Ff * Dd];
__device__ __align__(128) __half g_wd[(size_t)Ee * Dd * Ff];

__device__ int   g_cnt[Ee];
__device__ int   g_off[Ee];
__device__ int   g_fill[Ee];
__device__ int   g_list[NSLOT];
__device__ int   g_slot[NSLOT];
__device__ int   g_texp[NSLOT];
__device__ float g_gw[NSLOT];

// ---------------------------------------------------------------------------
// RMSNorm -> fp16 hi (+optional f32)
// ---------------------------------------------------------------------------
__global__ void rmsnorm_kernel(const float* __restrict__ in,
                               const float* __restrict__ w,
                               __half* __restrict__ ohi,
                               float* __restrict__ of32) {
    int t = blockIdx.x;
    const float* row = in + (size_t)t * Dd;
    float ss = 0.f;
#pragma unroll
    for (int i = 0; i < 4; i++) { float v = row[threadIdx.x + i * 256]; ss += v * v; }
#pragma unroll
    for (int o = 16; o > 0; o >>= 1) ss += __shfl_xor_sync(0xffffffffu, ss, o);
    __shared__ float sred[8];
    if ((threadIdx.x & 31) == 0) sred[threadIdx.x >> 5] = ss;
    __syncthreads();
    if (threadIdx.x < 32) {
        float v = (threadIdx.x < 8) ? sred[threadIdx.x] : 0.f;
#pragma unroll
        for (int o = 4; o > 0; o >>= 1) v += __shfl_xor_sync(0xffffffffu, v, o);
        if (threadIdx.x == 0) sred[0] = v;
    }
    __syncthreads();
    float inv = rsqrtf(sred[0] * (1.f / Dd) + 1e-6f);
    size_t base = (size_t)t * Dd;
#pragma unroll
    for (int i = 0; i < 4; i++) {
        int d = threadIdx.x + i * 256;
        float r = row[d] * inv * w[d];
        ohi[base + d] = __float2half_rn(r);
        if (of32) of32[base + d] = r;
    }
}

// ---------------------------------------------------------------------------
// Transpose: W[K,N] fp32 -> T[N,K] fp16. 64x64 tiles, vectorized.
// Block (32,8).
// ---------------------------------------------------------------------------
__global__ void transpose_half_kernel(const float* __restrict__ W,
                                      __half* __restrict__ T,
                                      int K, int N) {
    __shared__ float tile[64][65];
    size_t zb = (size_t)blockIdx.z * K * N;
    int k0 = blockIdx.y * 64, n0 = blockIdx.x * 64;
    int tx = threadIdx.x, ty = threadIdx.y;
#pragma unroll
    for (int j = 0; j < 8; j++) {
        float2 v = *(const float2*)&W[zb + (size_t)(k0 + ty + 8 * j) * N + n0 + tx * 2];
        tile[ty + 8 * j][tx * 2]     = v.x;
        tile[ty + 8 * j][tx * 2 + 1] = v.y;
    }
    __syncthreads();
#pragma unroll
    for (int j = 0; j < 8; j++) {
        int n = ty + 8 * j;
        __half2 h = __floats2half2_rn(tile[tx * 2][n], tile[tx * 2 + 1][n]);
        *(__half2*)&T[zb + (size_t)(n0 + n) * K + k0 + tx * 2] = h;
    }
}

// ---------------------------------------------------------------------------
// Warp-MMA GEMM (1-term): C[M,N] = A@B, fp32 accum, 3-stage cp.async.
// A [M,K] fp16 K-major; B [N,K] fp16 K-major.
// Epilogue variants:
//  - Ck != null: QKV split (N=1536): cols [0,1024)->C f32 stride 1024,
//    [1024,1280)->Ck f32 stride 256, [1280,1536)->Cv f32 stride 256.
//  - Chi != null: fp16 output (stride N).
//  - else: f32 C (+addsrc).
// mode 0: plain; mode 1: A rows via g_list[off+r], C rows off+r;
// mode 2: A/C rows at off+r. (off=g_off[z], Meff=g_cnt[z])
// ---------------------------------------------------------------------------
__global__ void __launch_bounds__(256, 2)
mma_gemm(const __half* __restrict__ Ah,
         const __half* __restrict__ Bw, size_t bz,
         float* __restrict__ C, const float* __restrict__ addsrc,
         float* __restrict__ Ck, float* __restrict__ Cv,
         __half* __restrict__ Chi,
         int mode, int M, int N, int K) {
    extern __shared__ char smem[];
    int z = blockIdx.z;
    int Meff = M, off = 0;
    if (mode) { Meff = g_cnt[z]; off = g_off[z]; }
    int m0 = blockIdx.y * 128;
    if (m0 >= Meff) return;
    int n0 = blockIdx.x * 128;
    const __half* bw = Bw + bz * z;

    int tid = threadIdx.x, lane = tid & 31, wid = tid >> 5;
    uint32_t sb = smem_u32(smem);

    int lrow = tid >> 1;
    int lcolh = (tid & 1) * 16;
    int ar = m0 + lrow;
    long grow;
    if (mode == 1) { int rr = (ar < Meff) ? ar : (Meff - 1); grow = g_list[off + rr]; }
    else if (mode == 2) { int rr = (ar < Meff) ? ar : (Meff - 1); grow = off + rr; }
    else grow = ar;
    const __half* pA = Ah + (size_t)grow * K + lcolh;
    const __half* pB = bw + (size_t)(n0 + lrow) * K + lcolh;
    uint32_t dstrel = (uint32_t)(lrow * ROWB + lcolh * 2);

    float acc[4][4][4];
#pragma unroll
    for (int i = 0; i < 4; i++)
#pragma unroll
        for (int j = 0; j < 4; j++)
#pragma unroll
            for (int q = 0; q < 4; q++) acc[i][j][q] = 0.f;

    const int NS = K / 32;
    auto load_stage = [&](int s) {
        size_t ko = (size_t)s * 32;
        uint32_t d = sb + (s % 3) * (2 * TILEB) + dstrel;
        CP16(d, pA + ko); CP16(d + 16, pA + ko + 8);
        CP16(d + TILEB, pB + ko); CP16(d + TILEB + 16, pB + ko + 8);
        CP_COMMIT();
    };
    load_stage(0);
    if (NS > 1) load_stage(1);

    uint32_t a_rel = (uint32_t)(((wid & 1) * 64 + (lane & 15)) * ROWB + (lane >> 4) * 16);
    uint32_t b_rel = (uint32_t)(TILEB +
        ((wid >> 1) * 32 + (lane & 7) + ((lane >> 4) & 1) * 8) * ROWB +
        ((lane >> 3) & 1) * 16);

    for (int s = 0; s < NS; s++) {
        if (s + 2 < NS) { load_stage(s + 2); CP_WAIT(2); }
        else if (s + 1 < NS) { CP_WAIT(1); }
        else { CP_WAIT(0); }
        __syncthreads();
        uint32_t base = sb + (s % 3) * (2 * TILEB);
#pragma unroll
        for (int kh = 0; kh < 2; kh++) {
            uint32_t koffb = kh * 32;
            uint32_t ah[4][4];
            uint32_t aaddr = base + a_rel + koffb;
#pragma unroll
            for (int mi = 0; mi < 4; mi++)
                ldsm_x4(ah[mi], aaddr + mi * 16 * ROWB);
            uint32_t bh[4][2];
            uint32_t baddr = base + b_rel + koffb;
#pragma unroll
            for (int hf = 0; hf < 2; hf++) {
                uint32_t t4[4];
                ldsm_x4(t4, baddr + hf * 16 * ROWB);
                bh[2 * hf][0] = t4[0]; bh[2 * hf][1] = t4[1];
                bh[2 * hf + 1][0] = t4[2]; bh[2 * hf + 1][1] = t4[3];
            }
#pragma unroll
            for (int mi = 0; mi < 4; mi++)
#pragma unroll
                for (int ni = 0; ni < 4; ni++)
                    mma_fp16(acc[mi][ni], ah[mi], bh[ni]);
        }
        __syncthreads();
    }

    int mW = m0 + (wid & 1) * 64;
    int nW = n0 + (wid >> 1) * 32;
#pragma unroll
    for (int mi = 0; mi < 4; mi++) {
#pragma unroll
        for (int hf = 0; hf < 2; hf++) {
            int r = mW + mi * 16 + hf * 8 + (lane >> 2);
            if (r >= Meff) continue;
            int crow = mode ? (off + r) : r;
#pragma unroll
            for (int ni = 0; ni < 4; ni++) {
                int c = nW + ni * 8 + (lane & 3) * 2;
                float v0 = acc[mi][ni][2 * hf + 0];
                float v1 = acc[mi][ni][2 * hf + 1];
                if (Ck) {
                    float2 v = {v0, v1};
                    if (c < QD)
                        *(float2*)(C + (size_t)crow * QD + c) = v;
                    else if (c < QD + KD)
                        *(float2*)(Ck + (size_t)crow * KD + (c - QD)) = v;
                    else
                        *(float2*)(Cv + (size_t)crow * KD + (c - QD - KD)) = v;
                } else if (Chi) {
                    *(__half2*)(Chi + (size_t)crow * N + c) = __floats2half2_rn(v0, v1);
                } else {
                    size_t co = (size_t)crow * N + c;
                    if (addsrc) { v0 += addsrc[co]; v1 += addsrc[co + 1]; }
                    float2 v = {v0, v1};
                    *(float2*)(C + co) = v;
                }
            }
        }
    }
}

// ---------------------------------------------------------------------------
// Dual-B GEMM: gate = A@Wg, up = A@Wu; he = silu(gate)*up -> fp16.
// CTA tile 128 x 64 (per output); A gathered rows (mode-1 semantics).
// ---------------------------------------------------------------------------
__global__ void __launch_bounds__(256, 2)
mma_gateup(const __half* __restrict__ Ah,
           const __half* __restrict__ Wg_, const __half* __restrict__ Wu_,
           size_t bz, __half* __restrict__ He, int K) {
    extern __shared__ char smem[];
    int z = blockIdx.z;
    int Meff = g_cnt[z], off = g_off[z];
    int m0 = blockIdx.y * 128;
    if (m0 >= Meff) return;
    int n0 = blockIdx.x * 64;
    const __half* wg = Wg_ + bz * z;
    const __half* wu = Wu_ + bz * z;

    int tid = threadIdx.x, lane = tid & 31, wid = tid >> 5;
    int wm = wid & 3, wn = wid >> 2;
    uint32_t sb = smem_u32(smem);

    int lrow = tid >> 1;
    int lcolh = (tid & 1) * 16;
    int ar = m0 + lrow;
    int rr = (ar < Meff) ? ar : (Meff - 1);
    long grow = g_list[off + rr];
    const __half* pA = Ah + (size_t)grow * K + lcolh;
    uint32_t adst = (uint32_t)(lrow * ROWB + lcolh * 2);
    int brow = tid >> 2;
    int bch = (tid & 3) * 8;
    const __half* pG = wg + (size_t)(n0 + brow) * K + bch;
    const __half* pU = wu + (size_t)(n0 + brow) * K + bch;
    uint32_t bdst = (uint32_t)(brow * ROWB + bch * 2);

    float accG[2][4][4], accU[2][4][4];
#pragma unroll
    for (int i = 0; i < 2; i++)
#pragma unroll
        for (int j = 0; j < 4; j++)
#pragma unroll
            for (int q = 0; q < 4; q++) { accG[i][j][q] = 0.f; accU[i][j][q] = 0.f; }

    const int NS = K / 32;
    auto load_stage = [&](int s) {
        size_t ko = (size_t)s * 32;
        uint32_t d = sb + (s % 3) * DSTAGE;
        CP16(d + adst, pA + ko); CP16(d + adst + 16, pA + ko + 8);
        CP16(d + TILEB + bdst, pG + ko);
        CP16(d + TILEB + TILEBB + bdst, pU + ko);
        CP_COMMIT();
    };
    load_stage(0);
    if (NS > 1) load_stage(1);

    uint32_t a_rel = (uint32_t)((wm * 32 + (lane & 15)) * ROWB + (lane >> 4) * 16);
    uint32_t b_rel = (uint32_t)((wn * 32 + (lane & 7) + ((lane >> 4) & 1) * 8) * ROWB +
                                ((lane >> 3) & 1) * 16);

    for (int s = 0; s < NS; s++) {
        if (s + 2 < NS) { load_stage(s + 2); CP_WAIT(2); }
        else if (s + 1 < NS) { CP_WAIT(1); }
        else { CP_WAIT(0); }
        __syncthreads();
        uint32_t base = sb + (s % 3) * DSTAGE;
#pragma unroll
        for (int kh = 0; kh < 2; kh++) {
            uint32_t koffb = kh * 32;
            uint32_t ah[2][4];
            uint32_t aaddr = base + a_rel + koffb;
#pragma unroll
            for (int mi = 0; mi < 2; mi++)
                ldsm_x4(ah[mi], aaddr + mi * 16 * ROWB);
            uint32_t bg[4][2], bu[4][2];
#pragma unroll
            for (int hf = 0; hf < 2; hf++) {
                uint32_t t4[4];
                ldsm_x4(t4, base + TILEB + b_rel + koffb + hf * 16 * ROWB);
                bg[2 * hf][0] = t4[0]; bg[2 * hf][1] = t4[1];
                bg[2 * hf + 1][0] = t4[2]; bg[2 * hf + 1][1] = t4[3];
                ldsm_x4(t4, base + TILEB + TILEBB + b_rel + koffb + hf * 16 * ROWB);
                bu[2 * hf][0] = t4[0]; bu[2 * hf][1] = t4[1];
                bu[2 * hf + 1][0] = t4[2]; bu[2 * hf + 1][1] = t4[3];
            }
#pragma unroll
            for (int mi = 0; mi < 2; mi++)
#pragma unroll
                for (int ni = 0; ni < 4; ni++) {
                    mma_fp16(accG[mi][ni], ah[mi], bg[ni]);
                    mma_fp16(accU[mi][ni], ah[mi], bu[ni]);
                }
        }
        __syncthreads();
    }

    int mW = m0 + wm * 32;
    int nW = n0 + wn * 32;
#pragma unroll
    for (int mi = 0; mi < 2; mi++) {
#pragma unroll
        for (int hf = 0; hf < 2; hf++) {
            int r = mW + mi * 16 + hf * 8 + (lane >> 2);
            if (r >= Meff) continue;
            int crow = off + r;
#pragma unroll
            for (int ni = 0; ni < 4; ni++) {
                int c = nW + ni * 8 + (lane & 3) * 2;
                float gv0 = accG[mi][ni][2 * hf + 0];
                float gv1 = accG[mi][ni][2 * hf + 1];
                float uv0 = accU[mi][ni][2 * hf + 0];
                float uv1 = accU[mi][ni][2 * hf + 1];
                float he0 = (gv0 / (1.f + __expf(-gv0))) * uv0;
                float he1 = (gv1 / (1.f + __expf(-gv1))) * uv1;
                *(__half2*)(He + (size_t)crow * Ff + c) = __floats2half2_rn(he0, he1);
            }
        }
    }
}

// ---------------------------------------------------------------------------
// RoPE: rotate q/k; emit q fp16 (pre-scaled 1/8), k fp32 + fp16, v fp16.
// ---------------------------------------------------------------------------
__global__ void rope_kernel(const float* __restrict__ cosb,
                            const float* __restrict__ sinb,
                            const float* __restrict__ q,
                            const float* __restrict__ k,
                            float* __restrict__ outk,
                            const float* __restrict__ vin,
                            __half* __restrict__ qh,
                            __half* __restrict__ kh, __half* __restrict__ vh) {
    int t = blockIdx.x;
    int s = t % Ss;
    const float* cs = cosb + (size_t)s * HDd;
    const float* sn = sinb + (size_t)s * HDd;

    const float* qrow = q + (size_t)t * QD;
    for (int idx = threadIdx.x; idx < Hh * 32; idx += blockDim.x) {
        int hh = idx >> 5, d = idx & 31;
        float a = qrow[hh * HDd + d], b2 = qrow[hh * HDd + d + 32];
        float o1 = (a * cs[d] - b2 * sn[d]) * 0.125f;
        float o2 = (b2 * cs[d + 32] + a * sn[d + 32]) * 0.125f;
        size_t base = (size_t)t * QD + hh * HDd;
        qh[base + d] = __float2half_rn(o1);
        qh[base + d + 32] = __float2half_rn(o2);
    }
    const float* krow = k + (size_t)t * KD;
    for (int idx = threadIdx.x; idx < KVh * 32; idx += blockDim.x) {
        int hh = idx >> 5, d = idx & 31;
        float a = krow[hh * HDd + d], b2 = krow[hh * HDd + d + 32];
        float o1 = a * cs[d] - b2 * sn[d];
        float o2 = b2 * cs[d + 32] + a * sn[d + 32];
        size_t base = (size_t)t * KD + hh * HDd;
        outk[base + d] = o1;      outk[base + d + 32] = o2;
        kh[base + d] = __float2half_rn(o1);
        kh[base + d + 32] = __float2half_rn(o2);
    }
    for (int idx = threadIdx.x; idx < KD; idx += blockDim.x) {
        vh[(size_t)t * KD + idx] = __float2half_rn(vin[(size_t)t * KD + idx]);
    }
}

// ---------------------------------------------------------------------------
// FA2-style causal GQA attention on mma.sync (1-term Q).
// ---------------------------------------------------------------------------
__global__ void __launch_bounds__(256, 2)
attn_mma_kernel(const __half* __restrict__ qh,
                const __half* __restrict__ kh, const __half* __restrict__ vh,
                __half* __restrict__ ohi) {
    extern __shared__ char smem[];
    int b = blockIdx.z, h = blockIdx.y, qt = blockIdx.x;
    int kvh = h >> 2;
    int tid = threadIdx.x, lane = tid & 31, wid = tid >> 5;
    int qrow0 = qt * 128;
    uint32_t sb = smem_u32(smem);

    {
        const __half* qsh = qh + ((size_t)(b * Ss + qrow0)) * QD + h * HDd;
#pragma unroll
        for (int i = 0; i < 4; i++) {
            int c = tid + 256 * i;
            int row = c >> 3, u = c & 7;
            CP16(sb + row * AROW + u * 16, qsh + (size_t)row * QD + u * 8);
        }
        CP_COMMIT(); CP_WAIT(0);
    }
    __syncthreads();

    int wr = wid * 16;
    uint32_t qfh[4][4];
    {
        uint32_t qa = sb + (wr + (lane & 15)) * AROW + (lane >> 4) * 16;
#pragma unroll
        for (int kc = 0; kc < 4; kc++)
            ldsm_x4(qfh[kc], qa + kc * 32);
    }
    __syncthreads();

    float o[8][4];
#pragma unroll
    for (int i = 0; i < 8; i++)
#pragma unroll
        for (int j = 0; j < 4; j++) o[i][j] = 0.f;
    float m0 = -1e30f, m1 = -1e30f, l0 = 0.f, l1 = 0.f;

    const __half* kbase = kh + ((size_t)(b * Ss)) * KD + kvh * HDd;
    const __half* vbase = vh + ((size_t)(b * Ss)) * KD + kvh * HDd;

    int ntiles = (qt + 1) * 2;
    {
#pragma unroll
        for (int i = 0; i < 2; i++) {
            int c = tid + 256 * i;
            int row = c >> 3, u = c & 7;
            CP16(sb + row * AROW + u * 16, kbase + (size_t)row * KD + u * 8);
            CP16(sb + ATILE + row * AROW + u * 16, vbase + (size_t)row * KD + u * 8);
        }
        CP_COMMIT();
    }

    for (int t = 0; t < ntiles; t++) {
        int k0 = t * 64;
        if (t + 1 < ntiles) {
            uint32_t dbuf = sb + ((t + 1) & 1) * ASTAGE;
            const __half* kb = kbase + (size_t)(k0 + 64) * KD;
            const __half* vb = vbase + (size_t)(k0 + 64) * KD;
#pragma unroll
            for (int i = 0; i < 2; i++) {
                int c = tid + 256 * i;
                int row = c >> 3, u = c & 7;
                CP16(dbuf + row * AROW + u * 16, kb + (size_t)row * KD + u * 8);
                CP16(dbuf + ATILE + row * AROW + u * 16, vb + (size_t)row * KD + u * 8);
            }
            CP_COMMIT(); CP_WAIT(1);
        } else {
            CP_WAIT(0);
        }
        __syncthreads();
        uint32_t kb0 = sb + (t & 1) * ASTAGE;
        uint32_t vb0 = kb0 + ATILE;

        float s[8][4];
#pragma unroll
        for (int nc16 = 0; nc16 < 4; nc16++) {
            uint32_t bk[4][4];
            uint32_t baddr = kb0 + (nc16 * 16 + (lane & 7) + ((lane >> 4) & 1) * 8) * AROW
                           + ((lane >> 3) & 1) * 16;
#pragma unroll
            for (int kc = 0; kc < 4; kc++) ldsm_x4(bk[kc], baddr + kc * 32);
#pragma unroll
            for (int j = 0; j < 2; j++) {
                int nc = nc16 * 2 + j;
                s[nc][0] = s[nc][1] = s[nc][2] = s[nc][3] = 0.f;
#pragma unroll
                for (int kc = 0; kc < 4; kc++)
                    mma_fp16(s[nc], qfh[kc], &bk[kc][2 * j]);
            }
        }
        if (k0 + 63 > qrow0 + wr) {
            int row0 = qrow0 + wr + (lane >> 2);
            int colb = k0 + (lane & 3) * 2;
#pragma unroll
            for (int nc = 0; nc < 8; nc++) {
                int c0 = colb + nc * 8, c1 = c0 + 1;
                if (c0 > row0)     s[nc][0] = -1e9f;
                if (c1 > row0)     s[nc][1] = -1e9f;
                if (c0 > row0 + 8) s[nc][2] = -1e9f;
                if (c1 > row0 + 8) s[nc][3] = -1e9f;
            }
        }
        float mx0 = -1e30f, mx1 = -1e30f;
#pragma unroll
        for (int nc = 0; nc < 8; nc++) {
            mx0 = fmaxf(mx0, fmaxf(s[nc][0], s[nc][1]));
            mx1 = fmaxf(mx1, fmaxf(s[nc][2], s[nc][3]));
        }
        mx0 = fmaxf(mx0, __shfl_xor_sync(0xffffffffu, mx0, 1));
        mx0 = fmaxf(mx0, __shfl_xor_sync(0xffffffffu, mx0, 2));
        mx1 = fmaxf(mx1, __shfl_xor_sync(0xffffffffu, mx1, 1));
        mx1 = fmaxf(mx1, __shfl_xor_sync(0xffffffffu, mx1, 2));
        float mn0 = fmaxf(m0, mx0), mn1 = fmaxf(m1, mx1);
        float cr0 = __expf(m0 - mn0), cr1 = __expf(m1 - mn1);
        m0 = mn0; m1 = mn1;
        float sum0 = 0.f, sum1 = 0.f;
#pragma unroll
        for (int nc = 0; nc < 8; nc++) {
            s[nc][0] = __expf(s[nc][0] - m0);
            s[nc][1] = __expf(s[nc][1] - m0);
            s[nc][2] = __expf(s[nc][2] - m1);
            s[nc][3] = __expf(s[nc][3] - m1);
            sum0 += s[nc][0] + s[nc][1];
            sum1 += s[nc][2] + s[nc][3];
        }
        sum0 += __shfl_xor_sync(0xffffffffu, sum0, 1);
        sum0 += __shfl_xor_sync(0xffffffffu, sum0, 2);
        sum1 += __shfl_xor_sync(0xffffffffu, sum1, 1);
        sum1 += __shfl_xor_sync(0xffffffffu, sum1, 2);
        l0 = l0 * cr0 + sum0;
        l1 = l1 * cr1 + sum1;
#pragma unroll
        for (int nc = 0; nc < 8; nc++) {
            o[nc][0] *= cr0; o[nc][1] *= cr0;
            o[nc][2] *= cr1; o[nc][3] *= cr1;
        }
        uint32_t pa[4][4];
#pragma unroll
        for (int kc = 0; kc < 4; kc++) {
            pa[kc][0] = packh2(s[2 * kc][0],     s[2 * kc][1]);
            pa[kc][1] = packh2(s[2 * kc][2],     s[2 * kc][3]);
            pa[kc][2] = packh2(s[2 * kc + 1][0], s[2 * kc + 1][1]);
            pa[kc][3] = packh2(s[2 * kc + 1][2], s[2 * kc + 1][3]);
        }
#pragma unroll
        for (int kc = 0; kc < 4; kc++) {
            uint32_t baddr = vb0 + (kc * 16 + (lane & 7) + ((lane >> 3) & 1) * 8) * AROW
                           + ((lane >> 4) & 1) * 16;
#pragma unroll
            for (int n16 = 0; n16 < 4; n16++) {
                uint32_t t4[4];
                ldsm_x4_t(t4, baddr + n16 * 32);
                mma_fp16(o[n16 * 2],     pa[kc], &t4[0]);
                mma_fp16(o[n16 * 2 + 1], pa[kc], &t4[2]);
            }
        }
        __syncthreads();
    }

    float inv0 = 1.f / l0, inv1 = 1.f / l1;
    int row0 = qrow0 + wr + (lane >> 2);
#pragma unroll
    for (int nc = 0; nc < 8; nc++) {
        int col = h * HDd + nc * 8 + (lane & 3) * 2;
        float v0 = o[nc][0] * inv0, v1 = o[nc][1] * inv0;
        float v2 = o[nc][2] * inv1, v3 = o[nc][3] * inv1;
        size_t o0 = (size_t)(b * Ss + row0) * QD + col;
        size_t o1 = (size_t)(b * Ss + row0 + 8) * QD + col;
        *(__half2*)(ohi + o0) = __floats2half2_rn(v0, v1);
        *(__half2*)(ohi + o1) = __floats2half2_rn(v2, v3);
    }
}

// ---------------------------------------------------------------------------
// Router + compacted slot assignment
// ---------------------------------------------------------------------------
__global__ void zero_cnt_kernel() {
    if (threadIdx.x < Ee) g_cnt[threadIdx.x] = 0;
}

__global__ void router_kernel(const float* __restrict__ y,
                              const float* __restrict__ rw) {
    int t = (blockIdx.x * blockDim.x + threadIdx.x) >> 5;
    int lane = threadIdx.x & 31;
    if (t >= NT) return;
    const float* yrow = y + (size_t)t * Dd;
    float logits[8] = {};
    for (int i = 0; i < 32; i++) {
        int d = i * 32 + lane;
        float yv = yrow[d];
#pragma unroll
        for (int e = 0; e < 8; e++) logits[e] += yv * rw[d * 8 + e];
    }
#pragma unroll
    for (int e = 0; e < 8; e++) {
#pragma unroll
        for (int o = 16; o > 0; o >>= 1)
            logits[e] += __shfl_xor_sync(0xffffffffu, logits[e], o);
    }
    if (lane == 0) {
        int i0 = 0; float v0 = logits[0];
#pragma unroll
        for (int e = 1; e < 8; e++) if (logits[e] > v0) { v0 = logits[e]; i0 = e; }
        int i1 = -1; float v1 = -1e30f;
#pragma unroll
        for (int e = 0; e < 8; e++)
            if (e != i0 && logits[e] > v1) { v1 = logits[e]; i1 = e; }
        float e1 = __expf(v1 - v0);
        g_texp[t * 2 + 0] = i0;
        g_texp[t * 2 + 1] = i1;
        g_gw[t * 2 + 0] = 1.f / (1.f + e1);
        g_gw[t * 2 + 1] = e1 / (1.f + e1);
        atomicAdd(&g_cnt[i0], 1);
        atomicAdd(&g_cnt[i1], 1);
    }
}

__global__ void offsets_kernel() {
    if (threadIdx.x == 0) {
        int a = 0;
        for (int e = 0; e < Ee; e++) { g_off[e] = a; a += g_cnt[e]; g_fill[e] = 0; }
    }
}

__global__ void scatter_kernel() {
    int t = blockIdx.x * blockDim.x + threadIdx.x;
    if (t >= NT) return;
#pragma unroll
    for (int j = 0; j < 2; j++) {
        int e = g_texp[t * 2 + j];
        int p = atomicAdd(&g_fill[e], 1);
        int slot = g_off[e] + p;
        g_list[slot] = t;
        g_slot[t * 2 + j] = slot;
    }
}

// ---------------------------------------------------------------------------
// out = h + w0 * down[slot0] + w1 * down[slot1]   (dn in fp16)
// ---------------------------------------------------------------------------
__global__ void combine_kernel(float* __restrict__ out) {
    int t = blockIdx.x;
    int d = (blockIdx.y * 256 + threadIdx.x) * 2;
    int s0 = g_slot[t * 2], s1 = g_slot[t * 2 + 1];
    float w0 = g_gw[t * 2], w1 = g_gw[t * 2 + 1];
    size_t o = (size_t)t * Dd + d;
    float2 hv = *(const float2*)(g_h + o);
    __half2 d0 = *(const __half2*)(g_dnh + (size_t)s0 * Dd + d);
    __half2 d1 = *(const __half2*)(g_dnh + (size_t)s1 * Dd + d);
    float2 f0 = __half22float2(d0);
    float2 f1 = __half22float2(d1);
    float2 r;
    r.x = hv.x + w0 * f0.x + w1 * f1.x;
    r.y = hv.y + w0 * f0.y + w1 * f1.y;
    *(float2*)(out + o) = r;
}

// ---------------------------------------------------------------------------
// Launch
// ---------------------------------------------------------------------------
extern "C" void kernel_launch(void* const* d_in, const int* in_sizes, int n_in,
                              void* d_out, int out_size) {
    const float* input  = (const float*)d_in[0];
    const float* cosb   = (const float*)d_in[1];
    const float* sinb   = (const float*)d_in[2];
    // d_in[3] = mask (causal, unused)
    const float* w_attn = (const float*)d_in[4];
    const float* w_moe  = (const float*)d_in[5];
    const float* Wq     = (const float*)d_in[6];
    const float* Wk     = (const float*)d_in[7];
    const float* Wv     = (const float*)d_in[8];
    const float* Wo     = (const float*)d_in[9];
    const float* rw     = (const float*)d_in[10];
    const float* Wg     = (const float*)d_in[11];
    const float* Wu     = (const float*)d_in[12];
    const float* Wd     = (const float*)d_in[13];

    cudaFuncSetAttribute(mma_gemm,   cudaFuncAttributeMaxDynamicSharedMemorySize, GS2);
    cudaFuncSetAttribute(mma_gateup, cudaFuncAttributeMaxDynamicSharedMemorySize, GSD);

    float *pq, *pk, *pvs, *pks, *ph, *py;
    cudaGetSymbolAddress((void**)&pq,  g_q);
    cudaGetSymbolAddress((void**)&pk,  g_k);
    cudaGetSymbolAddress((void**)&pvs, g_vscr);
    cudaGetSymbolAddress((void**)&pks, g_kscr);
    cudaGetSymbolAddress((void**)&ph,  g_h);
    cudaGetSymbolAddress((void**)&py,  g_y);

    __half *xhi, *ahi, *yhi, *hehi, *dnh;
    __half *qh2, *kh2, *vh2;
    __half *wqkv, *wo, *wg, *wu, *wd;
    cudaGetSymbolAddress((void**)&xhi, g_xhi);
    cudaGetSymbolAddress((void**)&ahi, g_ahi);
    cudaGetSymbolAddress((void**)&yhi, g_yhi);
    cudaGetSymbolAddress((void**)&hehi, g_hehi);
    cudaGetSymbolAddress((void**)&dnh, g_dnh);
    cudaGetSymbolAddress((void**)&qh2, g_qh2);
    cudaGetSymbolAddress((void**)&kh2, g_kh2);  cudaGetSymbolAddress((void**)&vh2, g_vh2);
    cudaGetSymbolAddress((void**)&wqkv, g_wqkv);
    cudaGetSymbolAddress((void**)&wo, g_wo);
    cudaGetSymbolAddress((void**)&wg, g_wg);
    cudaGetSymbolAddress((void**)&wu, g_wu);
    cudaGetSymbolAddress((void**)&wd, g_wd);

    float* out = (float*)d_out;
    size_t need = (size_t)NT * Dd + 2 * (size_t)NT * KD;
    bool full = ((size_t)out_size >= need);
    float* outk = full ? (out + (size_t)NT * Dd) : pks;
    float* outv = full ? (out + (size_t)NT * Dd + (size_t)NT * KD) : pvs;

    dim3 tb(32, 8);
    // weight transposes (fp16, [N,K]); wq/wk/wv concatenated into wqkv
    transpose_half_kernel<<<dim3(QD / 64, Dd / 64, 1),  tb>>>(Wq, wqkv, Dd, QD);
    transpose_half_kernel<<<dim3(KD / 64, Dd / 64, 1),  tb>>>(Wk, wqkv + (size_t)QD * Dd, Dd, KD);
    transpose_half_kernel<<<dim3(KD / 64, Dd / 64, 1),  tb>>>(Wv, wqkv + (size_t)(QD + KD) * Dd, Dd, KD);
    transpose_half_kernel<<<dim3(Dd / 64, QD / 64, 1),  tb>>>(Wo, wo, QD, Dd);
    transpose_half_kernel<<<dim3(Ff / 64, Dd / 64, Ee), tb>>>(Wg, wg, Dd, Ff);
    transpose_half_kernel<<<dim3(Ff / 64, Dd / 64, Ee), tb>>>(Wu, wu, Dd, Ff);
    transpose_half_kernel<<<dim3(Dd / 64, Ff / 64, Ee), tb>>>(Wd, wd, Ff, Dd);

    // 1. x = rmsnorm(input) -> fp16
    rmsnorm_kernel<<<NT, 256>>>(input, w_attn, xhi, nullptr);
    // 2. fused QKV projection (epilogue routes q/k/v)
    mma_gemm<<<dim3(QKVN / 128, NT / 128, 1), 256, GS2>>>(
        xhi, wqkv, 0, pq, nullptr, pk, outv, nullptr, 0, NT, QKVN, Dd);
    // 3. RoPE -> fp16 q (scaled), fp32 k out, fp16 k/v
    rope_kernel<<<NT, 256>>>(cosb, sinb, pq, pk, outk, outv, qh2, kh2, vh2);
    // 4. attention (mma.sync) -> fp16 output
    attn_mma_kernel<<<dim3(Ss / 128, Hh, Bb), 256, ASMEM>>>(qh2, kh2, vh2, ahi);
    // 5. h = input + attn @ Wo
    mma_gemm<<<dim3(Dd / 128, NT / 128, 1), 256, GS2>>>(
        ahi, wo, 0, ph, input, nullptr, nullptr, nullptr, 0, NT, Dd, QD);
    // 6. y = rmsnorm(h) -> fp16 + f32
    rmsnorm_kernel<<<NT, 256>>>(ph, w_moe, yhi, py);
    // 7. router + compact slots
    zero_cnt_kernel<<<1, 32>>>();
    router_kernel<<<NT / 8, 256>>>(py, rw);
    offsets_kernel<<<1, 32>>>();
    scatter_kernel<<<NT / 256, 256>>>();
    // 8. fused gate+up GEMM with silu epilogue -> fp16 he
    mma_gateup<<<dim3(Ff / 64, NT / 128, Ee), 256, GSD>>>(
        yhi, wg, wu, (size_t)Ff * Dd, hehi, Dd);
    // 9. down projection (contiguous slot rows) -> fp16 dn
    mma_gemm<<<dim3(Dd / 128, NT / 128, Ee), 256, GS2>>>(
        hehi, wd, (size_t)Dd * Ff, nullptr, nullptr, nullptr, nullptr, dnh,
        2, NT, Dd, Ff);
    // 10. combine
    combine_kernel<<<dim3(NT, Dd / 512), 256>>>(out);
}

// round 17
// speedup vs baseline: 6.7686x; 1.1210x over previous
#include <cuda_runtime.h>
#include <cuda_fp16.h>
#include <cstdint>

// ---------------------------------------------------------------------------
// MoE transformer block. fp16 warp-MMA GEMMs (fused QKV, fused gate+up+silu)
// + FA2 attention (1-term Q, exp2 softmax). Base sm_103 PTX only.
// R17: merged transpose launch; 4-deep single-sync GEMM pipes; 3-deep attn.
// ---------------------------------------------------------------------------

namespace {
constexpr int Bb  = 4;
constexpr int Ss  = 2048;
constexpr int Dd  = 1024;
constexpr int Hh  = 16;
constexpr int KVh = 4;
constexpr int HDd = 64;
constexpr int Ee  = 8;
constexpr int TKk = 2;
constexpr int Ff  = 1024;
constexpr int NT  = Bb * Ss;        // 8192 tokens
constexpr int QD  = Hh * HDd;       // 1024
constexpr int KD  = KVh * HDd;      // 256
constexpr int QKVN = QD + 2 * KD;   // 1536
constexpr int NSLOT = NT * TKk;     // 16384 expert slots

// GEMM tiling
constexpr int ROWB   = 80;                // smem row stride bytes (32 fp16 + pad)
constexpr int TILEB  = 128 * ROWB;        // 128x32 fp16 tile = 10240 B
constexpr int TILEBB = 64 * ROWB;         // 64x32 fp16 tile  = 5120 B
constexpr int GS2    = 4 * 2 * TILEB;     // gemm: 4 stages x (A,B) = 81920
constexpr int DSTAGE = TILEB + 2 * TILEBB;            // A + Bg + Bu = 20480
constexpr int GSD    = 4 * DSTAGE;                    // 81920

// Attention smem
constexpr int AROW   = 144;
constexpr int ATILE  = 64 * AROW;
constexpr int ASTAGE = 2 * ATILE;         // K + V = 18432
constexpr int ASMEM  = 3 * ASTAGE;        // 55296 (Q staging reuses buf 0)

constexpr float LOG2E = 1.44269504088896340736f;
}

__device__ __forceinline__ uint32_t smem_u32(const void* p) {
    uint32_t a;
    asm("{ .reg .u64 t; cvta.to.shared.u64 t, %1; cvt.u32.u64 %0, t; }" : "=r"(a) : "l"(p));
    return a;
}
#define CP16(dst, src) asm volatile( \
    "cp.async.cg.shared.global [%0], [%1], 16;" :: "r"(dst), "l"(src))
#define CP_COMMIT() asm volatile("cp.async.commit_group;" ::: "memory")
#define CP_WAIT(n)  asm volatile("cp.async.wait_group %0;" :: "n"(n) : "memory")

__device__ __forceinline__ void ldsm_x4(uint32_t* r, uint32_t addr) {
    asm volatile("ldmatrix.sync.aligned.m8n8.x4.shared.b16 {%0,%1,%2,%3}, [%4];"
                 : "=r"(r[0]), "=r"(r[1]), "=r"(r[2]), "=r"(r[3]) : "r"(addr));
}
__device__ __forceinline__ void ldsm_x4_t(uint32_t* r, uint32_t addr) {
    asm volatile("ldmatrix.sync.aligned.m8n8.x4.trans.shared.b16 {%0,%1,%2,%3}, [%4];"
                 : "=r"(r[0]), "=r"(r[1]), "=r"(r[2]), "=r"(r[3]) : "r"(addr));
}
__device__ __forceinline__ void mma_fp16(float* c, const uint32_t* a, const uint32_t* b) {
    asm volatile(
        "mma.sync.aligned.m16n8k16.row.col.f32.f16.f16.f32 "
        "{%0,%1,%2,%3}, {%4,%5,%6,%7}, {%8,%9}, {%0,%1,%2,%3};"
        : "+f"(c[0]), "+f"(c[1]), "+f"(c[2]), "+f"(c[3])
        : "r"(a[0]), "r"(a[1]), "r"(a[2]), "r"(a[3]), "r"(b[0]), "r"(b[1]));
}
__device__ __forceinline__ uint32_t packh2(float a, float b) {
    __half2 h = __floats2half2_rn(a, b);
    return *reinterpret_cast<uint32_t*>(&h);
}

// ---------------------------------------------------------------------------
// Scratch
// ---------------------------------------------------------------------------
__device__ __align__(128) float g_q[(size_t)NT * QD];
__device__ __align__(128) float g_k[(size_t)NT * KD];
__device__ __align__(128) float g_vscr[(size_t)NT * KD];
__device__ __align__(128) float g_kscr[(size_t)NT * KD];
__device__ __align__(128) float g_h[(size_t)NT * Dd];
__device__ __align__(128) float g_y[(size_t)NT * Dd];
__device__ __align__(128) __half g_dnh[(size_t)NSLOT * Dd];

__device__ __align__(128) __half g_xhi[(size_t)NT * Dd];
__device__ __align__(128) __half g_ahi[(size_t)NT * QD];
__device__ __align__(128) __half g_yhi[(size_t)NT * Dd];
__device__ __align__(128) __half g_hehi[(size_t)NSLOT * Ff];

// fp16 q (pre-scaled 1/8 * log2e) and k/v for attention
__device__ __align__(128) __half g_qh2[(size_t)NT * QD];
__device__ __align__(128) __half g_kh2[(size_t)NT * KD];
__device__ __align__(128) __half g_vh2[(size_t)NT * KD];

// transposed fp16 weights [N, K]
__device__ __align__(128) __half g_wqkv[(size_t)QKVN * Dd];
__device__ __align__(128) __half g_wo[(size_t)Dd * QD];
__device__ __align__(128) __half g_wg[(size_t)Ee * Ff * Dd];
__device__ __align__(128) __half g_wu[(size_t)Ee * Ff * Dd];
__device__ __align__(128) __half g_wd[(size_t)Ee * Dd * Ff];

__device__ int   g_cnt[Ee];
__device__ int   g_off[Ee];
__device__ int   g_fill[Ee];
__device__ int   g_list[NSLOT];
__device__ int   g_slot[NSLOT];
__device__ int   g_texp[NSLOT];
__device__ float g_gw[NSLOT];

// ---------------------------------------------------------------------------
// RMSNorm -> fp16 hi (+optional f32)
// ---------------------------------------------------------------------------
__global__ void rmsnorm_kernel(const float* __restrict__ in,
                               const float* __restrict__ w,
                               __half* __restrict__ ohi,
                               float* __restrict__ of32) {
    int t = blockIdx.x;
    const float* row = in + (size_t)t * Dd;
    float ss = 0.f;
#pragma unroll
    for (int i = 0; i < 4; i++) { float v = row[threadIdx.x + i * 256]; ss += v * v; }
#pragma unroll
    for (int o = 16; o > 0; o >>= 1) ss += __shfl_xor_sync(0xffffffffu, ss, o);
    __shared__ float sred[8];
    if ((threadIdx.x & 31) == 0) sred[threadIdx.x >> 5] = ss;
    __syncthreads();
    if (threadIdx.x < 32) {
        float v = (threadIdx.x < 8) ? sred[threadIdx.x] : 0.f;
#pragma unroll
        for (int o = 4; o > 0; o >>= 1) v += __shfl_xor_sync(0xffffffffu, v, o);
        if (threadIdx.x == 0) sred[0] = v;
    }
    __syncthreads();
    float inv = rsqrtf(sred[0] * (1.f / Dd) + 1e-6f);
    size_t base = (size_t)t * Dd;
#pragma unroll
    for (int i = 0; i < 4; i++) {
        int d = threadIdx.x + i * 256;
        float r = row[d] * inv * w[d];
        ohi[base + d] = __float2half_rn(r);
        if (of32) of32[base + d] = r;
    }
}

// ---------------------------------------------------------------------------
// Merged transpose: all 7 weight transposes in ONE launch. 64x64 tiles.
// Flattened grid; compile-time segment boundaries. All K = 1024.
// ---------------------------------------------------------------------------
__global__ void merged_transpose_kernel(
    const float* __restrict__ Wq, const float* __restrict__ Wk,
    const float* __restrict__ Wv, const float* __restrict__ Wo,
    const float* __restrict__ Wg, const float* __restrict__ Wu,
    const float* __restrict__ Wd,
    __half* __restrict__ wqkv, __half* __restrict__ wo,
    __half* __restrict__ wg, __half* __restrict__ wu, __half* __restrict__ wd) {
    __shared__ float tile[64][65];
    int b = blockIdx.x;
    const float* src; __half* dst; int N, loc;
    // segments: Wq 256 | Wk 64 | Wv 64 | Wo 256 | Wg 2048 | Wu 2048 | Wd 2048
    if (b < 256)       { src = Wq; dst = wqkv;                          N = 1024; loc = b; }
    else if (b < 320)  { src = Wk; dst = wqkv + (size_t)QD * Dd;        N = 256;  loc = b - 256; }
    else if (b < 384)  { src = Wv; dst = wqkv + (size_t)(QD + KD) * Dd; N = 256;  loc = b - 320; }
    else if (b < 640)  { src = Wo; dst = wo;                            N = 1024; loc = b - 384; }
    else if (b < 2688) { int l = b - 640;  int z = l >> 8; l &= 255;
                         src = Wg + (size_t)z * Dd * Ff; dst = wg + (size_t)z * Dd * Ff;
                         N = 1024; loc = l; }
    else if (b < 4736) { int l = b - 2688; int z = l >> 8; l &= 255;
                         src = Wu + (size_t)z * Dd * Ff; dst = wu + (size_t)z * Dd * Ff;
                         N = 1024; loc = l; }
    else               { int l = b - 4736; int z = l >> 8; l &= 255;
                         src = Wd + (size_t)z * Ff * Dd; dst = wd + (size_t)z * Ff * Dd;
                         N = 1024; loc = l; }
    int nx = N >> 6;                        // tiles along N
    int n0 = (loc % nx) * 64, k0 = (loc / nx) * 64;
    int tx = threadIdx.x, ty = threadIdx.y;
    const int K = 1024;
#pragma unroll
    for (int j = 0; j < 8; j++) {
        float2 v = *(const float2*)&src[(size_t)(k0 + ty + 8 * j) * N + n0 + tx * 2];
        tile[ty + 8 * j][tx * 2]     = v.x;
        tile[ty + 8 * j][tx * 2 + 1] = v.y;
    }
    __syncthreads();
#pragma unroll
    for (int j = 0; j < 8; j++) {
        int n = ty + 8 * j;
        __half2 h = __floats2half2_rn(tile[tx * 2][n], tile[tx * 2 + 1][n]);
        *(__half2*)&dst[(size_t)(n0 + n) * K + k0 + tx * 2] = h;
    }
}

// ---------------------------------------------------------------------------
// Warp-MMA GEMM (1-term): C[M,N] = A@B, fp32 accum.
// 4-stage cp.async ring, lookahead 2, ONE __syncthreads per stage.
// A [M,K] fp16 K-major; B [N,K] fp16 K-major.
// Epilogue variants: Ck (QKV split) / Chi (fp16 out) / f32 C (+addsrc).
// mode 0 plain; 1 gather A rows via g_list; 2 contiguous slot rows.
// ---------------------------------------------------------------------------
__global__ void __launch_bounds__(256, 2)
mma_gemm(const __half* __restrict__ Ah,
         const __half* __restrict__ Bw, size_t bz,
         float* __restrict__ C, const float* __restrict__ addsrc,
         float* __restrict__ Ck, float* __restrict__ Cv,
         __half* __restrict__ Chi,
         int mode, int M, int N, int K) {
    extern __shared__ char smem[];
    int z = blockIdx.z;
    int Meff = M, off = 0;
    if (mode) { Meff = g_cnt[z]; off = g_off[z]; }
    int m0 = blockIdx.y * 128;
    if (m0 >= Meff) return;
    int n0 = blockIdx.x * 128;
    const __half* bw = Bw + bz * z;

    int tid = threadIdx.x, lane = tid & 31, wid = tid >> 5;
    uint32_t sb = smem_u32(smem);

    int lrow = tid >> 1;
    int lcolh = (tid & 1) * 16;
    int ar = m0 + lrow;
    long grow;
    if (mode == 1) { int rr = (ar < Meff) ? ar : (Meff - 1); grow = g_list[off + rr]; }
    else if (mode == 2) { int rr = (ar < Meff) ? ar : (Meff - 1); grow = off + rr; }
    else grow = ar;
    const __half* pA = Ah + (size_t)grow * K + lcolh;
    const __half* pB = bw + (size_t)(n0 + lrow) * K + lcolh;
    uint32_t dstrel = (uint32_t)(lrow * ROWB + lcolh * 2);

    float acc[4][4][4];
#pragma unroll
    for (int i = 0; i < 4; i++)
#pragma unroll
        for (int j = 0; j < 4; j++)
#pragma unroll
            for (int q = 0; q < 4; q++) acc[i][j][q] = 0.f;

    const int NS = K / 32;
    auto load_stage = [&](int s) {
        size_t ko = (size_t)s * 32;
        uint32_t d = sb + (s & 3) * (2 * TILEB) + dstrel;
        CP16(d, pA + ko); CP16(d + 16, pA + ko + 8);
        CP16(d + TILEB, pB + ko); CP16(d + TILEB + 16, pB + ko + 8);
        CP_COMMIT();
    };
    load_stage(0);
    if (NS > 1) load_stage(1);

    uint32_t a_rel = (uint32_t)(((wid & 1) * 64 + (lane & 15)) * ROWB + (lane >> 4) * 16);
    uint32_t b_rel = (uint32_t)(TILEB +
        ((wid >> 1) * 32 + (lane & 7) + ((lane >> 4) & 1) * 8) * ROWB +
        ((lane >> 3) & 1) * 16);

    for (int s = 0; s < NS; s++) {
        if (s + 2 < NS) { load_stage(s + 2); CP_WAIT(2); }
        else if (s + 1 < NS) { CP_WAIT(1); }
        else { CP_WAIT(0); }
        __syncthreads();   // single sync: ring depth 4 > lookahead 2 covers reuse
        uint32_t base = sb + (s & 3) * (2 * TILEB);
#pragma unroll
        for (int kh = 0; kh < 2; kh++) {
            uint32_t koffb = kh * 32;
            uint32_t ah[4][4];
            uint32_t aaddr = base + a_rel + koffb;
#pragma unroll
            for (int mi = 0; mi < 4; mi++)
                ldsm_x4(ah[mi], aaddr + mi * 16 * ROWB);
            uint32_t bh[4][2];
            uint32_t baddr = base + b_rel + koffb;
#pragma unroll
            for (int hf = 0; hf < 2; hf++) {
                uint32_t t4[4];
                ldsm_x4(t4, baddr + hf * 16 * ROWB);
                bh[2 * hf][0] = t4[0]; bh[2 * hf][1] = t4[1];
                bh[2 * hf + 1][0] = t4[2]; bh[2 * hf + 1][1] = t4[3];
            }
#pragma unroll
            for (int mi = 0; mi < 4; mi++)
#pragma unroll
                for (int ni = 0; ni < 4; ni++)
                    mma_fp16(acc[mi][ni], ah[mi], bh[ni]);
        }
    }

    int mW = m0 + (wid & 1) * 64;
    int nW = n0 + (wid >> 1) * 32;
#pragma unroll
    for (int mi = 0; mi < 4; mi++) {
#pragma unroll
        for (int hf = 0; hf < 2; hf++) {
            int r = mW + mi * 16 + hf * 8 + (lane >> 2);
            if (r >= Meff) continue;
            int crow = mode ? (off + r) : r;
#pragma unroll
            for (int ni = 0; ni < 4; ni++) {
                int c = nW + ni * 8 + (lane & 3) * 2;
                float v0 = acc[mi][ni][2 * hf + 0];
                float v1 = acc[mi][ni][2 * hf + 1];
                if (Ck) {
                    float2 v = {v0, v1};
                    if (c < QD)
                        *(float2*)(C + (size_t)crow * QD + c) = v;
                    else if (c < QD + KD)
                        *(float2*)(Ck + (size_t)crow * KD + (c - QD)) = v;
                    else
                        *(float2*)(Cv + (size_t)crow * KD + (c - QD - KD)) = v;
                } else if (Chi) {
                    *(__half2*)(Chi + (size_t)crow * N + c) = __floats2half2_rn(v0, v1);
                } else {
                    size_t co = (size_t)crow * N + c;
                    if (addsrc) { v0 += addsrc[co]; v1 += addsrc[co + 1]; }
                    float2 v = {v0, v1};
                    *(float2*)(C + co) = v;
                }
            }
        }
    }
}

// ---------------------------------------------------------------------------
// Dual-B GEMM: gate = A@Wg, up = A@Wu; he = silu(gate)*up -> fp16.
// 4-stage ring, single sync. CTA tile 128x64; gathered A rows.
// ---------------------------------------------------------------------------
__global__ void __launch_bounds__(256, 2)
mma_gateup(const __half* __restrict__ Ah,
           const __half* __restrict__ Wg_, const __half* __restrict__ Wu_,
           size_t bz, __half* __restrict__ He, int K) {
    extern __shared__ char smem[];
    int z = blockIdx.z;
    int Meff = g_cnt[z], off = g_off[z];
    int m0 = blockIdx.y * 128;
    if (m0 >= Meff) return;
    int n0 = blockIdx.x * 64;
    const __half* wg = Wg_ + bz * z;
    const __half* wu = Wu_ + bz * z;

    int tid = threadIdx.x, lane = tid & 31, wid = tid >> 5;
    int wm = wid & 3, wn = wid >> 2;
    uint32_t sb = smem_u32(smem);

    int lrow = tid >> 1;
    int lcolh = (tid & 1) * 16;
    int ar = m0 + lrow;
    int rr = (ar < Meff) ? ar : (Meff - 1);
    long grow = g_list[off + rr];
    const __half* pA = Ah + (size_t)grow * K + lcolh;
    uint32_t adst = (uint32_t)(lrow * ROWB + lcolh * 2);
    int brow = tid >> 2;
    int bch = (tid & 3) * 8;
    const __half* pG = wg + (size_t)(n0 + brow) * K + bch;
    const __half* pU = wu + (size_t)(n0 + brow) * K + bch;
    uint32_t bdst = (uint32_t)(brow * ROWB + bch * 2);

    float accG[2][4][4], accU[2][4][4];
#pragma unroll
    for (int i = 0; i < 2; i++)
#pragma unroll
        for (int j = 0; j < 4; j++)
#pragma unroll
            for (int q = 0; q < 4; q++) { accG[i][j][q] = 0.f; accU[i][j][q] = 0.f; }

    const int NS = K / 32;
    auto load_stage = [&](int s) {
        size_t ko = (size_t)s * 32;
        uint32_t d = sb + (s & 3) * DSTAGE;
        CP16(d + adst, pA + ko); CP16(d + adst + 16, pA + ko + 8);
        CP16(d + TILEB + bdst, pG + ko);
        CP16(d + TILEB + TILEBB + bdst, pU + ko);
        CP_COMMIT();
    };
    load_stage(0);
    if (NS > 1) load_stage(1);

    uint32_t a_rel = (uint32_t)((wm * 32 + (lane & 15)) * ROWB + (lane >> 4) * 16);
    uint32_t b_rel = (uint32_t)((wn * 32 + (lane & 7) + ((lane >> 4) & 1) * 8) * ROWB +
                                ((lane >> 3) & 1) * 16);

    for (int s = 0; s < NS; s++) {
        if (s + 2 < NS) { load_stage(s + 2); CP_WAIT(2); }
        else if (s + 1 < NS) { CP_WAIT(1); }
        else { CP_WAIT(0); }
        __syncthreads();
        uint32_t base = sb + (s & 3) * DSTAGE;
#pragma unroll
        for (int kh = 0; kh < 2; kh++) {
            uint32_t koffb = kh * 32;
            uint32_t ah[2][4];
            uint32_t aaddr = base + a_rel + koffb;
#pragma unroll
            for (int mi = 0; mi < 2; mi++)
                ldsm_x4(ah[mi], aaddr + mi * 16 * ROWB);
            uint32_t bg[4][2], bu[4][2];
#pragma unroll
            for (int hf = 0; hf < 2; hf++) {
                uint32_t t4[4];
                ldsm_x4(t4, base + TILEB + b_rel + koffb + hf * 16 * ROWB);
                bg[2 * hf][0] = t4[0]; bg[2 * hf][1] = t4[1];
                bg[2 * hf + 1][0] = t4[2]; bg[2 * hf + 1][1] = t4[3];
                ldsm_x4(t4, base + TILEB + TILEBB + b_rel + koffb + hf * 16 * ROWB);
                bu[2 * hf][0] = t4[0]; bu[2 * hf][1] = t4[1];
                bu[2 * hf + 1][0] = t4[2]; bu[2 * hf + 1][1] = t4[3];
            }
#pragma unroll
            for (int mi = 0; mi < 2; mi++)
#pragma unroll
                for (int ni = 0; ni < 4; ni++) {
                    mma_fp16(accG[mi][ni], ah[mi], bg[ni]);
                    mma_fp16(accU[mi][ni], ah[mi], bu[ni]);
                }
        }
    }

    int mW = m0 + wm * 32;
    int nW = n0 + wn * 32;
#pragma unroll
    for (int mi = 0; mi < 2; mi++) {
#pragma unroll
        for (int hf = 0; hf < 2; hf++) {
            int r = mW + mi * 16 + hf * 8 + (lane >> 2);
            if (r >= Meff) continue;
            int crow = off + r;
#pragma unroll
            for (int ni = 0; ni < 4; ni++) {
                int c = nW + ni * 8 + (lane & 3) * 2;
                float gv0 = accG[mi][ni][2 * hf + 0];
                float gv1 = accG[mi][ni][2 * hf + 1];
                float uv0 = accU[mi][ni][2 * hf + 0];
                float uv1 = accU[mi][ni][2 * hf + 1];
                float he0 = (gv0 / (1.f + __expf(-gv0))) * uv0;
                float he1 = (gv1 / (1.f + __expf(-gv1))) * uv1;
                *(__half2*)(He + (size_t)crow * Ff + c) = __floats2half2_rn(he0, he1);
            }
        }
    }
}

// ---------------------------------------------------------------------------
// RoPE: rotate q/k; emit q fp16 (pre-scaled 1/8 * log2e), k fp32 + fp16, v fp16.
// ---------------------------------------------------------------------------
__global__ void rope_kernel(const float* __restrict__ cosb,
                            const float* __restrict__ sinb,
                            const float* __restrict__ q,
                            const float* __restrict__ k,
                            float* __restrict__ outk,
                            const float* __restrict__ vin,
                            __half* __restrict__ qh,
                            __half* __restrict__ kh, __half* __restrict__ vh) {
    int t = blockIdx.x;
    int s = t % Ss;
    const float* cs = cosb + (size_t)s * HDd;
    const float* sn = sinb + (size_t)s * HDd;
    const float qsc = 0.125f * LOG2E;

    const float* qrow = q + (size_t)t * QD;
    for (int idx = threadIdx.x; idx < Hh * 32; idx += blockDim.x) {
        int hh = idx >> 5, d = idx & 31;
        float a = qrow[hh * HDd + d], b2 = qrow[hh * HDd + d + 32];
        float o1 = (a * cs[d] - b2 * sn[d]) * qsc;
        float o2 = (b2 * cs[d + 32] + a * sn[d + 32]) * qsc;
        size_t base = (size_t)t * QD + hh * HDd;
        qh[base + d] = __float2half_rn(o1);
        qh[base + d + 32] = __float2half_rn(o2);
    }
    const float* krow = k + (size_t)t * KD;
    for (int idx = threadIdx.x; idx < KVh * 32; idx += blockDim.x) {
        int hh = idx >> 5, d = idx & 31;
        float a = krow[hh * HDd + d], b2 = krow[hh * HDd + d + 32];
        float o1 = a * cs[d] - b2 * sn[d];
        float o2 = b2 * cs[d + 32] + a * sn[d + 32];
        size_t base = (size_t)t * KD + hh * HDd;
        outk[base + d] = o1;      outk[base + d + 32] = o2;
        kh[base + d] = __float2half_rn(o1);
        kh[base + d + 32] = __float2half_rn(o2);
    }
    for (int idx = threadIdx.x; idx < KD; idx += blockDim.x) {
        vh[(size_t)t * KD + idx] = __float2half_rn(vin[(size_t)t * KD + idx]);
    }
}

// ---------------------------------------------------------------------------
// FA2-style causal GQA attention on mma.sync (1-term Q, exp2 softmax).
// 3-deep KV ring, lookahead 1, single sync per tile.
// ---------------------------------------------------------------------------
__global__ void __launch_bounds__(256, 2)
attn_mma_kernel(const __half* __restrict__ qh,
                const __half* __restrict__ kh, const __half* __restrict__ vh,
                __half* __restrict__ ohi) {
    extern __shared__ char smem[];
    int b = blockIdx.z, h = blockIdx.y, qt = blockIdx.x;
    int kvh = h >> 2;
    int tid = threadIdx.x, lane = tid & 31, wid = tid >> 5;
    int qrow0 = qt * 128;
    uint32_t sb = smem_u32(smem);

    {
        const __half* qsh = qh + ((size_t)(b * Ss + qrow0)) * QD + h * HDd;
#pragma unroll
        for (int i = 0; i < 4; i++) {
            int c = tid + 256 * i;
            int row = c >> 3, u = c & 7;
            CP16(sb + row * AROW + u * 16, qsh + (size_t)row * QD + u * 8);
        }
        CP_COMMIT(); CP_WAIT(0);
    }
    __syncthreads();

    int wr = wid * 16;
    uint32_t qfh[4][4];
    {
        uint32_t qa = sb + (wr + (lane & 15)) * AROW + (lane >> 4) * 16;
#pragma unroll
        for (int kc = 0; kc < 4; kc++)
            ldsm_x4(qfh[kc], qa + kc * 32);
    }
    __syncthreads();

    float o[8][4];
#pragma unroll
    for (int i = 0; i < 8; i++)
#pragma unroll
        for (int j = 0; j < 4; j++) o[i][j] = 0.f;
    float m0 = -1e30f, m1 = -1e30f, l0 = 0.f, l1 = 0.f;

    const __half* kbase = kh + ((size_t)(b * Ss)) * KD + kvh * HDd;
    const __half* vbase = vh + ((size_t)(b * Ss)) * KD + kvh * HDd;

    int ntiles = (qt + 1) * 2;
    {
#pragma unroll
        for (int i = 0; i < 2; i++) {
            int c = tid + 256 * i;
            int row = c >> 3, u = c & 7;
            CP16(sb + row * AROW + u * 16, kbase + (size_t)row * KD + u * 8);
            CP16(sb + ATILE + row * AROW + u * 16, vbase + (size_t)row * KD + u * 8);
        }
        CP_COMMIT();
    }

    for (int t = 0; t < ntiles; t++) {
        int k0 = t * 64;
        if (t + 1 < ntiles) {
            uint32_t dbuf = sb + ((t + 1) % 3) * ASTAGE;
            const __half* kb = kbase + (size_t)(k0 + 64) * KD;
            const __half* vb = vbase + (size_t)(k0 + 64) * KD;
#pragma unroll
            for (int i = 0; i < 2; i++) {
                int c = tid + 256 * i;
                int row = c >> 3, u = c & 7;
                CP16(dbuf + row * AROW + u * 16, kb + (size_t)row * KD + u * 8);
                CP16(dbuf + ATILE + row * AROW + u * 16, vb + (size_t)row * KD + u * 8);
            }
            CP_COMMIT(); CP_WAIT(1);
        } else {
            CP_WAIT(0);
        }
        __syncthreads();   // single sync: ring depth 3 > lookahead 1 covers reuse
        uint32_t kb0 = sb + (t % 3) * ASTAGE;
        uint32_t vb0 = kb0 + ATILE;

        float s[8][4];
#pragma unroll
        for (int nc16 = 0; nc16 < 4; nc16++) {
            uint32_t bk[4][4];
            uint32_t baddr = kb0 + (nc16 * 16 + (lane & 7) + ((lane >> 4) & 1) * 8) * AROW
                           + ((lane >> 3) & 1) * 16;
#pragma unroll
            for (int kc = 0; kc < 4; kc++) ldsm_x4(bk[kc], baddr + kc * 32);
#pragma unroll
            for (int j = 0; j < 2; j++) {
                int nc = nc16 * 2 + j;
                s[nc][0] = s[nc][1] = s[nc][2] = s[nc][3] = 0.f;
#pragma unroll
                for (int kc = 0; kc < 4; kc++)
                    mma_fp16(s[nc], qfh[kc], &bk[kc][2 * j]);
            }
        }
        if (k0 + 63 > qrow0 + wr) {
            int row0 = qrow0 + wr + (lane >> 2);
            int colb = k0 + (lane & 3) * 2;
#pragma unroll
            for (int nc = 0; nc < 8; nc++) {
                int c0 = colb + nc * 8, c1 = c0 + 1;
                if (c0 > row0)     s[nc][0] = -1e9f;
                if (c1 > row0)     s[nc][1] = -1e9f;
                if (c0 > row0 + 8) s[nc][2] = -1e9f;
                if (c1 > row0 + 8) s[nc][3] = -1e9f;
            }
        }
        float mx0 = -1e30f, mx1 = -1e30f;
#pragma unroll
        for (int nc = 0; nc < 8; nc++) {
            mx0 = fmaxf(mx0, fmaxf(s[nc][0], s[nc][1]));
            mx1 = fmaxf(mx1, fmaxf(s[nc][2], s[nc][3]));
        }
        mx0 = fmaxf(mx0, __shfl_xor_sync(0xffffffffu, mx0, 1));
        mx0 = fmaxf(mx0, __shfl_xor_sync(0xffffffffu, mx0, 2));
        mx1 = fmaxf(mx1, __shfl_xor_sync(0xffffffffu, mx1, 1));
        mx1 = fmaxf(mx1, __shfl_xor_sync(0xffffffffu, mx1, 2));
        float mn0 = fmaxf(m0, mx0), mn1 = fmaxf(m1, mx1);
        float cr0 = exp2f(m0 - mn0), cr1 = exp2f(m1 - mn1);
        m0 = mn0; m1 = mn1;
        float sum0 = 0.f, sum1 = 0.f;
#pragma unroll
        for (int nc = 0; nc < 8; nc++) {
            s[nc][0] = exp2f(s[nc][0] - m0);
            s[nc][1] = exp2f(s[nc][1] - m0);
            s[nc][2] = exp2f(s[nc][2] - m1);
            s[nc][3] = exp2f(s[nc][3] - m1);
            sum0 += s[nc][0] + s[nc][1];
            sum1 += s[nc][2] + s[nc][3];
        }
        sum0 += __shfl_xor_sync(0xffffffffu, sum0, 1);
        sum0 += __shfl_xor_sync(0xffffffffu, sum0, 2);
        sum1 += __shfl_xor_sync(0xffffffffu, sum1, 1);
        sum1 += __shfl_xor_sync(0xffffffffu, sum1, 2);
        l0 = l0 * cr0 + sum0;
        l1 = l1 * cr1 + sum1;
#pragma unroll
        for (int nc = 0; nc < 8; nc++) {
            o[nc][0] *= cr0; o[nc][1] *= cr0;
            o[nc][2] *= cr1; o[nc][3] *= cr1;
        }
        uint32_t pa[4][4];
#pragma unroll
        for (int kc = 0; kc < 4; kc++) {
            pa[kc][0] = packh2(s[2 * kc][0],     s[2 * kc][1]);
            pa[kc][1] = packh2(s[2 * kc][2],     s[2 * kc][3]);
            pa[kc][2] = packh2(s[2 * kc + 1][0], s[2 * kc + 1][1]);
            pa[kc][3] = packh2(s[2 * kc + 1][2], s[2 * kc + 1][3]);
        }
#pragma unroll
        for (int kc = 0; kc < 4; kc++) {
            uint32_t baddr = vb0 + (kc * 16 + (lane & 7) + ((lane >> 3) & 1) * 8) * AROW
                           + ((lane >> 4) & 1) * 16;
#pragma unroll
            for (int n16 = 0; n16 < 4; n16++) {
                uint32_t t4[4];
                ldsm_x4_t(t4, baddr + n16 * 32);
                mma_fp16(o[n16 * 2],     pa[kc], &t4[0]);
                mma_fp16(o[n16 * 2 + 1], pa[kc], &t4[2]);
            }
        }
    }

    float inv0 = 1.f / l0, inv1 = 1.f / l1;
    int row0 = qrow0 + wr + (lane >> 2);
#pragma unroll
    for (int nc = 0; nc < 8; nc++) {
        int col = h * HDd + nc * 8 + (lane & 3) * 2;
        float v0 = o[nc][0] * inv0, v1 = o[nc][1] * inv0;
        float v2 = o[nc][2] * inv1, v3 = o[nc][3] * inv1;
        size_t o0 = (size_t)(b * Ss + row0) * QD + col;
        size_t o1 = (size_t)(b * Ss + row0 + 8) * QD + col;
        *(__half2*)(ohi + o0) = __floats2half2_rn(v0, v1);
        *(__half2*)(ohi + o1) = __floats2half2_rn(v2, v3);
    }
}

// ---------------------------------------------------------------------------
// Router + compacted slot assignment
// ---------------------------------------------------------------------------
__global__ void zero_cnt_kernel() {
    if (threadIdx.x < Ee) g_cnt[threadIdx.x] = 0;
}

__global__ void router_kernel(const float* __restrict__ y,
                              const float* __restrict__ rw) {
    int t = (blockIdx.x * blockDim.x + threadIdx.x) >> 5;
    int lane = threadIdx.x & 31;
    if (t >= NT) return;
    const float* yrow = y + (size_t)t * Dd;
    float logits[8] = {};
    for (int i = 0; i < 32; i++) {
        int d = i * 32 + lane;
        float yv = yrow[d];
#pragma unroll
        for (int e = 0; e < 8; e++) logits[e] += yv * rw[d * 8 + e];
    }
#pragma unroll
    for (int e = 0; e < 8; e++) {
#pragma unroll
        for (int o = 16; o > 0; o >>= 1)
            logits[e] += __shfl_xor_sync(0xffffffffu, logits[e], o);
    }
    if (lane == 0) {
        int i0 = 0; float v0 = logits[0];
#pragma unroll
        for (int e = 1; e < 8; e++) if (logits[e] > v0) { v0 = logits[e]; i0 = e; }
        int i1 = -1; float v1 = -1e30f;
#pragma unroll
        for (int e = 0; e < 8; e++)
            if (e != i0 && logits[e] > v1) { v1 = logits[e]; i1 = e; }
        float e1 = __expf(v1 - v0);
        g_texp[t * 2 + 0] = i0;
        g_texp[t * 2 + 1] = i1;
        g_gw[t * 2 + 0] = 1.f / (1.f + e1);
        g_gw[t * 2 + 1] = e1 / (1.f + e1);
        atomicAdd(&g_cnt[i0], 1);
        atomicAdd(&g_cnt[i1], 1);
    }
}

__global__ void offsets_kernel() {
    if (threadIdx.x == 0) {
        int a = 0;
        for (int e = 0; e < Ee; e++) { g_off[e] = a; a += g_cnt[e]; g_fill[e] = 0; }
    }
}

__global__ void scatter_kernel() {
    int t = blockIdx.x * blockDim.x + threadIdx.x;
    if (t >= NT) return;
#pragma unroll
    for (int j = 0; j < 2; j++) {
        int e = g_texp[t * 2 + j];
        int p = atomicAdd(&g_fill[e], 1);
        int slot = g_off[e] + p;
        g_list[slot] = t;
        g_slot[t * 2 + j] = slot;
    }
}

// ---------------------------------------------------------------------------
// out = h + w0 * down[slot0] + w1 * down[slot1]   (dn in fp16)
// ---------------------------------------------------------------------------
__global__ void combine_kernel(float* __restrict__ out) {
    int t = blockIdx.x;
    int d = (blockIdx.y * 256 + threadIdx.x) * 2;
    int s0 = g_slot[t * 2], s1 = g_slot[t * 2 + 1];
    float w0 = g_gw[t * 2], w1 = g_gw[t * 2 + 1];
    size_t o = (size_t)t * Dd + d;
    float2 hv = *(const float2*)(g_h + o);
    __half2 d0 = *(const __half2*)(g_dnh + (size_t)s0 * Dd + d);
    __half2 d1 = *(const __half2*)(g_dnh + (size_t)s1 * Dd + d);
    float2 f0 = __half22float2(d0);
    float2 f1 = __half22float2(d1);
    float2 r;
    r.x = hv.x + w0 * f0.x + w1 * f1.x;
    r.y = hv.y + w0 * f0.y + w1 * f1.y;
    *(float2*)(out + o) = r;
}

// ---------------------------------------------------------------------------
// Launch
// ---------------------------------------------------------------------------
extern "C" void kernel_launch(void* const* d_in, const int* in_sizes, int n_in,
                              void* d_out, int out_size) {
    const float* input  = (const float*)d_in[0];
    const float* cosb   = (const float*)d_in[1];
    const float* sinb   = (const float*)d_in[2];
    // d_in[3] = mask (causal, unused)
    const float* w_attn = (const float*)d_in[4];
    const float* w_moe  = (const float*)d_in[5];
    const float* Wq     = (const float*)d_in[6];
    const float* Wk     = (const float*)d_in[7];
    const float* Wv     = (const float*)d_in[8];
    const float* Wo     = (const float*)d_in[9];
    const float* rw     = (const float*)d_in[10];
    const float* Wg     = (const float*)d_in[11];
    const float* Wu     = (const float*)d_in[12];
    const float* Wd     = (const float*)d_in[13];

    cudaFuncSetAttribute(mma_gemm,        cudaFuncAttributeMaxDynamicSharedMemorySize, GS2);
    cudaFuncSetAttribute(mma_gateup,      cudaFuncAttributeMaxDynamicSharedMemorySize, GSD);
    cudaFuncSetAttribute(attn_mma_kernel, cudaFuncAttributeMaxDynamicSharedMemorySize, ASMEM);

    float *pq, *pk, *pvs, *pks, *ph, *py;
    cudaGetSymbolAddress((void**)&pq,  g_q);
    cudaGetSymbolAddress((void**)&pk,  g_k);
    cudaGetSymbolAddress((void**)&pvs, g_vscr);
    cudaGetSymbolAddress((void**)&pks, g_kscr);
    cudaGetSymbolAddress((void**)&ph,  g_h);
    cudaGetSymbolAddress((void**)&py,  g_y);

    __half *xhi, *ahi, *yhi, *hehi, *dnh;
    __half *qh2, *kh2, *vh2;
    __half *wqkv, *wo, *wg, *wu, *wd;
    cudaGetSymbolAddress((void**)&xhi, g_xhi);
    cudaGetSymbolAddress((void**)&ahi, g_ahi);
    cudaGetSymbolAddress((void**)&yhi, g_yhi);
    cudaGetSymbolAddress((void**)&hehi, g_hehi);
    cudaGetSymbolAddress((void**)&dnh, g_dnh);
    cudaGetSymbolAddress((void**)&qh2, g_qh2);
    cudaGetSymbolAddress((void**)&kh2, g_kh2);  cudaGetSymbolAddress((void**)&vh2, g_vh2);
    cudaGetSymbolAddress((void**)&wqkv, g_wqkv);
    cudaGetSymbolAddress((void**)&wo, g_wo);
    cudaGetSymbolAddress((void**)&wg, g_wg);
    cudaGetSymbolAddress((void**)&wu, g_wu);
    cudaGetSymbolAddress((void**)&wd, g_wd);

    float* out = (float*)d_out;
    size_t need = (size_t)NT * Dd + 2 * (size_t)NT * KD;
    bool full = ((size_t)out_size >= need);
    float* outk = full ? (out + (size_t)NT * Dd) : pks;
    float* outv = full ? (out + (size_t)NT * Dd + (size_t)NT * KD) : pvs;

    // weight transposes (fp16, [N,K]) — single merged launch
    merged_transpose_kernel<<<6784, dim3(32, 8)>>>(
        Wq, Wk, Wv, Wo, Wg, Wu, Wd, wqkv, wo, wg, wu, wd);

    // 1. x = rmsnorm(input) -> fp16
    rmsnorm_kernel<<<NT, 256>>>(input, w_attn, xhi, nullptr);
    // 2. fused QKV projection (epilogue routes q/k/v)
    mma_gemm<<<dim3(QKVN / 128, NT / 128, 1), 256, GS2>>>(
        xhi, wqkv, 0, pq, nullptr, pk, outv, nullptr, 0, NT, QKVN, Dd);
    // 3. RoPE -> fp16 q (scaled by log2e/8), fp32 k out, fp16 k/v
    rope_kernel<<<NT, 256>>>(cosb, sinb, pq, pk, outk, outv, qh2, kh2, vh2);
    // 4. attention (mma.sync, exp2 softmax) -> fp16 output
    attn_mma_kernel<<<dim3(Ss / 128, Hh, Bb), 256, ASMEM>>>(qh2, kh2, vh2, ahi);
    // 5. h = input + attn @ Wo
    mma_gemm<<<dim3(Dd / 128, NT / 128, 1), 256, GS2>>>(
        ahi, wo, 0, ph, input, nullptr, nullptr, nullptr, 0, NT, Dd, QD);
    // 6. y = rmsnorm(h) -> fp16 + f32
    rmsnorm_kernel<<<NT, 256>>>(ph, w_moe, yhi, py);
    // 7. router + compact slots
    zero_cnt_kernel<<<1, 32>>>();
    router_kernel<<<NT / 8, 256>>>(py, rw);
    offsets_kernel<<<1, 32>>>();
    scatter_kernel<<<NT / 256, 256>>>();
    // 8. fused gate+up GEMM with silu epilogue -> fp16 he
    mma_gateup<<<dim3(Ff / 64, NT / 128, Ee), 256, GSD>>>(
        yhi, wg, wu, (size_t)Ff * Dd, hehi, Dd);
    // 9. down projection (contiguous slot rows) -> fp16 dn
    mma_gemm<<<dim3(Dd / 128, NT / 128, Ee), 256, GS2>>>(
        hehi, wd, (size_t)Dd * Ff, nullptr, nullptr, nullptr, nullptr, dnh,
        2, NT, Dd, Ff);
    // 10. combine
    combine_kernel<<<dim3(NT, Dd / 512), 256>>>(out);
}